// round 9
// baseline (speedup 1.0000x reference)
#include <cuda_runtime.h>
#include <cuda_bf16.h>
#include <math.h>
#include <float.h>
#include <stdint.h>

#define NROW 16384
#define DIM  512
#define MARGIN 2.0f
#define EPSV 1e-6f

#if defined(__CUDA_ARCH_FEAT_SM103_ALL) || (defined(__CUDA_ARCH_SPECIFIC__) && (__CUDA_ARCH_SPECIFIC__ == 1030))
#define HAS_TCGEN05 1
#else
#define HAS_TCGEN05 0
#endif

// ---- device scratch (no dynamic allocation allowed) ----
__device__ __align__(16) float g_sq[NROW];
__device__ int   g_neg[NROW];
__device__ int   g_cand[NROW * 6];
__device__ float g_rowloss[NROW];
// e4m3 inputs PRE-SWIZZLED as 256 column-tiles of 32KB:
// tile t = rows t*64..t*64+63; 4 slabs of 8KB (128 K-bytes each);
// within slab: bo = r*128 + (k&127), stored at bo^((bo>>3)&0x70).
__device__ __align__(256) uint8_t  g_x8[NROW * DIM];
// linear bf16x2 copy (rerank + SIMT fallback)
__device__ __align__(16) uint32_t g_xb16[NROW * DIM / 2];

// SMEM layout
#define SMEM_TPTR   0
#define SMEM_FULL0  8            // 4 mbarriers (B ring complete_tx)
#define SMEM_DONE0  40           // 2 mbarriers (MMA commit)
#define SMEM_DFREE0 56           // 2 mbarriers (epilogue done with D+sq)
#define SMEM_SQF0   72           // 8 mbarriers (sq ring complete_tx)
#define SMEM_SQS    1024         // 8 slots x 256B
#define SMEM_B      3072         // 4 x 32768
#define SMEM_TOTAL  (3072 + 4 * 32768)

#define TMEM_A   0               // 128 cols: A 128x512 e4m3
#define TMEM_SCA 128             // 4 cols scale_A (ue8m0 = 127)
#define TMEM_SCB 132             // 2 cols scale_B
#define TMEM_D0  192             // 64 cols f32
#define TMEM_D1  256

#define NTILE 256
#define THREADS 160              // w0 = producer+MMA, w1-4 = epilogue

#if HAS_TCGEN05
__device__ __forceinline__ uint32_t elect_one() {
    uint32_t p;
    asm volatile("{\n\t.reg .pred p;\n\telect.sync _|p, 0xFFFFFFFF;\n\tselp.b32 %0, 1, 0, p;\n\t}" : "=r"(p));
    return p;
}
#define TCGEN05_ALLOC(dst, n) \
    asm volatile("tcgen05.alloc.cta_group::1.sync.aligned.shared::cta.b32 [%0], %1;" :: "r"(dst), "r"(n) : "memory")
#define TCGEN05_DEALLOC(t, n) \
    asm volatile("tcgen05.dealloc.cta_group::1.sync.aligned.b32 %0, %1;" :: "r"(t), "r"(n))
#define TCGEN05_RELINQ() \
    asm volatile("tcgen05.relinquish_alloc_permit.cta_group::1.sync.aligned;")
#define TCGEN05_WAIT_ST() asm volatile("tcgen05.wait::st.sync.aligned;" ::: "memory")
#define TCGEN05_WAIT_LD() asm volatile("tcgen05.wait::ld.sync.aligned;" ::: "memory")
#define TCGEN05_FENCE_BEFORE() asm volatile("tcgen05.fence::before_thread_sync;" ::: "memory")
#define TCGEN05_FENCE_AFTER()  asm volatile("tcgen05.fence::after_thread_sync;" ::: "memory")
#define MBARRIER_INIT(m, c) \
    asm volatile("mbarrier.init.shared.b64 [%0], %1;" :: "r"(m), "r"(c) : "memory")
#define MBARRIER_ARRIVE(m) \
    asm volatile("mbarrier.arrive.release.cta.shared.b64 _, [%0];" :: "r"(m) : "memory")
#define MBARRIER_EXPECT_TX(m, b) \
    asm volatile("mbarrier.arrive.expect_tx.shared.b64 _, [%0], %1;" :: "r"(m), "r"(b) : "memory")
#define TCGEN05_COMMIT(m) \
    asm volatile("tcgen05.commit.cta_group::1.mbarrier::arrive::one.shared::cluster.b64 [%0];" :: "r"(m) : "memory")

#define MBARRIER_WAIT_PARITY(mbar_smem_addr, phase_parity) do { \
    uint32_t _mbar = (uint32_t)(mbar_smem_addr); \
    uint32_t _parity = (uint32_t)(phase_parity); \
    uint32_t _done; \
    asm volatile("{\n\t.reg .pred p;\n\t" \
        "mbarrier.try_wait.parity.acquire.cta.shared::cta.b64 p, [%1], %2;\n\t" \
        "selp.b32 %0, 1, 0, p;\n\t}" : "=r"(_done) : "r"(_mbar), "r"(_parity) : "memory"); \
    if (!_done) { \
        asm volatile("{\n\t.reg .pred P1;\n\t" \
            "WAIT_LOOP_%=:\n\t" \
            "mbarrier.try_wait.parity.acquire.cta.shared::cta.b64 P1, [%0], %1, 0x989680;\n\t" \
            "@P1 bra.uni WAIT_DONE_%=;\n\t" \
            "bra.uni WAIT_LOOP_%=;\n\t" \
            "WAIT_DONE_%=:\n\t}" :: "r"(_mbar), "r"(_parity) : "memory"); \
    } \
} while (0)

#define TCGEN05_ST_X1(tmem_addr, r0) \
    asm volatile("tcgen05.st.sync.aligned.32x32b.x1.b32 [%0], {%1};" :: "r"(tmem_addr), "r"(r0) : "memory")

#define TCGEN05_ST_X32(tmem_addr, r) \
    asm volatile("tcgen05.st.sync.aligned.32x32b.x32.b32 [%0], " \
        "{%1, %2, %3, %4, %5, %6, %7, %8, %9, %10, %11, %12, %13, %14, %15, %16, " \
        "%17, %18, %19, %20, %21, %22, %23, %24, %25, %26, %27, %28, %29, %30, %31, %32};" \
        :: "r"(tmem_addr), \
           "r"((r)[0]),"r"((r)[1]),"r"((r)[2]),"r"((r)[3]),"r"((r)[4]),"r"((r)[5]),"r"((r)[6]),"r"((r)[7]), \
           "r"((r)[8]),"r"((r)[9]),"r"((r)[10]),"r"((r)[11]),"r"((r)[12]),"r"((r)[13]),"r"((r)[14]),"r"((r)[15]), \
           "r"((r)[16]),"r"((r)[17]),"r"((r)[18]),"r"((r)[19]),"r"((r)[20]),"r"((r)[21]),"r"((r)[22]),"r"((r)[23]), \
           "r"((r)[24]),"r"((r)[25]),"r"((r)[26]),"r"((r)[27]),"r"((r)[28]),"r"((r)[29]),"r"((r)[30]),"r"((r)[31]) \
        : "memory")

#define TCGEN05_LD_X32(r, tmem_addr) \
    asm volatile("tcgen05.ld.sync.aligned.32x32b.x32.b32 " \
        "{%0, %1, %2, %3, %4, %5, %6, %7, %8, %9, %10, %11, %12, %13, %14, %15, " \
        "%16, %17, %18, %19, %20, %21, %22, %23, %24, %25, %26, %27, %28, %29, %30, %31}, [%32];" \
        : "=r"((r)[0]),"=r"((r)[1]),"=r"((r)[2]),"=r"((r)[3]),"=r"((r)[4]),"=r"((r)[5]),"=r"((r)[6]),"=r"((r)[7]), \
          "=r"((r)[8]),"=r"((r)[9]),"=r"((r)[10]),"=r"((r)[11]),"=r"((r)[12]),"=r"((r)[13]),"=r"((r)[14]),"=r"((r)[15]), \
          "=r"((r)[16]),"=r"((r)[17]),"=r"((r)[18]),"=r"((r)[19]),"=r"((r)[20]),"=r"((r)[21]),"=r"((r)[22]),"=r"((r)[23]), \
          "=r"((r)[24]),"=r"((r)[25]),"=r"((r)[26]),"=r"((r)[27]),"=r"((r)[28]),"=r"((r)[29]),"=r"((r)[30]),"=r"((r)[31]) \
        : "r"(tmem_addr))

__device__ __forceinline__ void bulk_g2s(uint32_t dst, const void* src, uint32_t bytes, uint32_t mbar) {
    asm volatile("cp.async.bulk.shared::cta.global.mbarrier::complete_tx::bytes [%0], [%1], %2, [%3];"
                 :: "r"(dst), "l"(src), "r"(bytes), "r"(mbar) : "memory");
}

// TS-mode block-scaled MXFP8 MMA (verified encoding from test_mma_mxf8.cu)
__device__ __forceinline__ void mma_mxf8_ts(uint32_t d_tmem, uint32_t a_tmem,
                                            uint64_t b_desc, uint32_t idesc,
                                            uint32_t sca, uint32_t scb, bool acc) {
    uint32_t en = acc ? 1u : 0u;
    asm volatile("{\n\t.reg .pred p;\n\tsetp.ne.u32 p, %6, 0;\n\t"
        "tcgen05.mma.cta_group::1.kind::mxf8f6f4.block_scale.scale_vec::1X "
        "[%0], [%1], %2, %3, [%4], [%5], p;\n\t}"
        :: "r"(d_tmem), "r"(a_tmem), "l"(b_desc), "r"(idesc), "r"(sca), "r"(scb), "r"(en)
        : "memory");
}

// SW128 K-major SMEM descriptor (LBO=1, SBO=64)
__device__ __forceinline__ uint64_t make_desc(uint32_t addr) {
    return (uint64_t(2) << 61) | (uint64_t(1) << 46) | (uint64_t(64) << 32)
         | (uint64_t(1) << 16) | ((addr >> 4) & 0x3FFF);
}

// idesc: M=128 (1<<27), UE8M0 scales (1<<23), N=64 (8<<17), E4M3 x E4M3, SF ids = 0
#define MMA_IDESC8 ((1u << 27) | (1u << 23) | (8u << 17))
#endif  // HAS_TCGEN05

__device__ __forceinline__ uint32_t smem_u32(const void* p) {
    uint32_t a;
    asm("{ .reg .u64 t; cvta.to.shared.u64 t, %1; cvt.u32.u64 %0, t; }" : "=r"(a) : "l"(p));
    return a;
}

// ============================================================
// Kernel 0: fp32 -> {pre-swizzled e4m3 tiles, linear bf16x2} + row norms
// ============================================================
__global__ __launch_bounds__(128) void cvtsq_kernel(const float* __restrict__ X) {
    int row = blockIdx.x;
    int t = threadIdx.x;
    float4 v = *(const float4*)(X + (size_t)row * DIM + t * 4);
    // bf16x2 linear copy
    uint32_t blo, bhi;
    asm("cvt.rn.bf16x2.f32 %0, %1, %2;" : "=r"(blo) : "f"(v.y), "f"(v.x));
    asm("cvt.rn.bf16x2.f32 %0, %1, %2;" : "=r"(bhi) : "f"(v.w), "f"(v.z));
    *(uint2*)(g_xb16 + (size_t)row * 256 + t * 2) = make_uint2(blo, bhi);
    // e4m3 pre-swizzled tile image
    uint16_t h0, h1;
    asm("cvt.rn.satfinite.e4m3x2.f32 %0, %1, %2;" : "=h"(h0) : "f"(v.y), "f"(v.x));
    asm("cvt.rn.satfinite.e4m3x2.f32 %0, %1, %2;" : "=h"(h1) : "f"(v.w), "f"(v.z));
    uint32_t f8 = (uint32_t)h0 | ((uint32_t)h1 << 16);
    int tile = row >> 6, r = row & 63;
    int k = t * 4;
    uint32_t bo = (uint32_t)(r * 128 + (k & 127));
    uint32_t sw = bo ^ ((bo >> 3) & 0x70);
    *(uint32_t*)(g_x8 + (size_t)tile * 32768 + (size_t)(k >> 7) * 8192 + sw) = f8;
    // exact fp32 row norm
    float s = v.x * v.x + v.y * v.y + v.z * v.z + v.w * v.w;
#pragma unroll
    for (int o = 16; o > 0; o >>= 1) s += __shfl_down_sync(0xffffffffu, s, o);
    __shared__ float ws[4];
    if ((t & 31) == 0) ws[t >> 5] = s;
    __syncthreads();
    if (t == 0) g_sq[row] = ws[0] + ws[1] + ws[2] + ws[3];
}

// ============================================================
// Kernel 1: fully-async tcgen05 FP8 GEMM + min-screened top-6.
// 128 CTAs x 160 threads, async mbarrier protocol (no per-tile bar):
//   w0    = producer+MMA: 32KB bulk loads (4-deep B ring, 8-deep sq ring),
//           16 mxf8 dispatches/tile -> D[u&1], commit -> done[u&1].
//   w1-w4 = epilogue: wait done -> LDTM -> min-screen -> top-6 -> dfree.
// Scales all 1.0 (ue8m0=127). key = sq[j] - 2*dot8(i,j).
// Exact selection deferred to rerank_kernel (bf16-exact on 6 candidates).
// ============================================================
__global__ __launch_bounds__(THREADS, 1)
void mma_topk_kernel() {
    extern __shared__ char smem[];
    const uint32_t smem_base = smem_u32(smem);
    const int tid = threadIdx.x;
    const int rowBase = blockIdx.x * 128;

#if HAS_TCGEN05
    const char* x8 = (const char*)g_x8;
    const int wid = tid >> 5;
    const int lane = tid & 31;
    const bool is_mma = (wid == 0);
    const int smsp = wid & 3;
    const int row = smsp * 32 + lane;

    if (is_mma) {
        TCGEN05_ALLOC(smem_base + SMEM_TPTR, 512);
        TCGEN05_RELINQ();
    }
    if (tid == 0) {
#pragma unroll
        for (int s = 0; s < 4; ++s) MBARRIER_INIT(smem_base + SMEM_FULL0 + s * 8, 1);
        MBARRIER_INIT(smem_base + SMEM_DONE0, 1);
        MBARRIER_INIT(smem_base + SMEM_DONE0 + 8, 1);
        MBARRIER_INIT(smem_base + SMEM_DFREE0, 4);
        MBARRIER_INIT(smem_base + SMEM_DFREE0 + 8, 4);
#pragma unroll
        for (int s = 0; s < 8; ++s) MBARRIER_INIT(smem_base + SMEM_SQF0 + s * 8, 1);
    }
    __syncthreads();
    uint32_t tmem_base;
    asm volatile("ld.shared.b32 %0, [%1];" : "=r"(tmem_base) : "r"(smem_base + SMEM_TPTR));

    if (!is_mma) {
        // A (this warp's 32 rows x 512 e4m3) -> TMEM cols 0..127
        const int R = rowBase + row;
        const int tt = R >> 6, r = R & 63;
        const char* tbase = x8 + (size_t)tt * 32768;
        uint32_t wo = (uint32_t)smsp << 21;
#pragma unroll
        for (int grp = 0; grp < 4; ++grp) {       // 4 x 32 cols
            uint32_t rg[32];
#pragma unroll
            for (int u = 0; u < 8; ++u) {          // 8 x 16B granules
                int gg = grp * 8 + u;              // k = gg*16..gg*16+15
                uint32_t bo = (uint32_t)(r * 128 + ((gg * 16) & 127));
                uint32_t sw = bo ^ ((bo >> 3) & 0x70);
                uint4 v = *(const uint4*)(tbase + (size_t)(gg >> 3) * 8192 + sw);
                rg[u * 4 + 0] = v.x; rg[u * 4 + 1] = v.y;
                rg[u * 4 + 2] = v.z; rg[u * 4 + 3] = v.w;
            }
            TCGEN05_ST_X32(tmem_base + TMEM_A + grp * 32 + wo, rg);
        }
        // scales = 1.0 (ue8m0 127 in byte 0; SF ids are 0)
#pragma unroll
        for (int c = 0; c < 4; ++c)
            TCGEN05_ST_X1(tmem_base + TMEM_SCA + c + wo, 0x7Fu);
#pragma unroll
        for (int c = 0; c < 2; ++c)
            TCGEN05_ST_X1(tmem_base + TMEM_SCB + c + wo, 0x7Fu);
        TCGEN05_WAIT_ST();
        TCGEN05_FENCE_BEFORE();
    } else {
        if (elect_one()) {
#pragma unroll
            for (int pt = 0; pt < 3; ++pt) {
                uint32_t fb = smem_base + SMEM_FULL0 + pt * 8;
                MBARRIER_EXPECT_TX(fb, 32768);
                bulk_g2s(smem_base + SMEM_B + pt * 32768, x8 + (size_t)pt * 32768, 32768, fb);
                uint32_t qb = smem_base + SMEM_SQF0 + pt * 8;
                MBARRIER_EXPECT_TX(qb, 256);
                bulk_g2s(smem_base + SMEM_SQS + pt * 256, (const char*)g_sq + pt * 256, 256, qb);
            }
        }
    }
    __syncthreads();

    if (is_mma) {
        TCGEN05_FENCE_AFTER();
        for (int u = 0; u < NTILE; ++u) {
            const int b = u & 1;
            if (u >= 2) {
                MBARRIER_WAIT_PARITY(smem_base + SMEM_DFREE0 + b * 8, ((u - 2) >> 1) & 1);
                TCGEN05_FENCE_AFTER();
            }
            MBARRIER_WAIT_PARITY(smem_base + SMEM_FULL0 + (u & 3) * 8, (u >> 2) & 1);
            if (elect_one()) {
                uint64_t bdesc = make_desc(smem_base + SMEM_B + (u & 3) * 32768);
                uint32_t dtm = tmem_base + (b ? TMEM_D1 : TMEM_D0);
#pragma unroll
                for (int c = 0; c < 16; ++c) {     // 16 x K=32 e4m3 steps
                    uint64_t bd = bdesc + (uint64_t)((c >> 2) * 512 + (c & 3) * 2);
                    mma_mxf8_ts(dtm, tmem_base + TMEM_A + c * 8, bd, MMA_IDESC8,
                                tmem_base + TMEM_SCA, tmem_base + TMEM_SCB, c > 0);
                }
                TCGEN05_COMMIT(smem_base + SMEM_DONE0 + b * 8);
            }
            // recycle: B(u+3)->slot[(u+3)&3] (last read by MMA(u-1));
            //          sq(u+3)->slot[(u+3)&7] (last read by epi(u-5) <= dfree(u-2))
            if (u + 3 < NTILE) {
                if (u >= 1)
                    MBARRIER_WAIT_PARITY(smem_base + SMEM_DONE0 + ((u - 1) & 1) * 8,
                                         ((u - 1) >> 1) & 1);
                if (elect_one()) {
                    int s2 = (u + 3) & 3;
                    uint32_t fb = smem_base + SMEM_FULL0 + s2 * 8;
                    MBARRIER_EXPECT_TX(fb, 32768);
                    bulk_g2s(smem_base + SMEM_B + s2 * 32768,
                             x8 + (size_t)(u + 3) * 32768, 32768, fb);
                    int q2 = (u + 3) & 7;
                    uint32_t qb = smem_base + SMEM_SQF0 + q2 * 8;
                    MBARRIER_EXPECT_TX(qb, 256);
                    bulk_g2s(smem_base + SMEM_SQS + q2 * 256,
                             (const char*)g_sq + (size_t)(u + 3) * 256, 256, qb);
                }
            }
        }
    } else {
        float v0 = FLT_MAX, v1 = FLT_MAX, v2 = FLT_MAX,
              v3 = FLT_MAX, v4 = FLT_MAX, v5 = FLT_MAX;
        int   i0 = 0, i1 = 0, i2 = 0, i3 = 0, i4 = 0, i5 = 0;
        for (int u = 0; u < NTILE; ++u) {
            const int b = u & 1;
            MBARRIER_WAIT_PARITY(smem_base + SMEM_DONE0 + b * 8, (u >> 1) & 1);
            TCGEN05_FENCE_AFTER();
            MBARRIER_WAIT_PARITY(smem_base + SMEM_SQF0 + (u & 7) * 8, (u >> 3) & 1);
            const float* sqt = (const float*)(smem + SMEM_SQS + (u & 7) * 256);
            const int colBase = u * 64;
            const uint32_t dtm = tmem_base + (b ? TMEM_D1 : TMEM_D0);
            uint32_t dr[64];
            TCGEN05_LD_X32(dr, dtm);
            TCGEN05_LD_X32(dr + 32, dtm + 32);
            TCGEN05_WAIT_LD();
#pragma unroll
            for (int g = 0; g < 4; ++g) {
                float key[16];
#pragma unroll
                for (int c = 0; c < 16; ++c)
                    key[c] = fmaf(-2.f, __uint_as_float(dr[g * 16 + c]), sqt[g * 16 + c]);
                float t8[8];
#pragma unroll
                for (int c = 0; c < 8; ++c) t8[c] = fminf(key[c], key[c + 8]);
                float t4a = fminf(t8[0], t8[4]), t4b = fminf(t8[1], t8[5]);
                float t4c = fminf(t8[2], t8[6]), t4d = fminf(t8[3], t8[7]);
                float mn = fminf(fminf(t4a, t4b), fminf(t4c, t4d));
                if (mn < v5) {   // rare: branchless shift-insert, ascending cols
#pragma unroll
                    for (int c = 0; c < 16; ++c) {
                        float k = key[c];
                        int col = colBase + g * 16 + c;
                        if (k < v5) {
                            bool b0 = k < v0, b1 = k < v1, b2 = k < v2,
                                 b3 = k < v3, b4 = k < v4;
                            v5 = b4 ? v4 : k;                 i5 = b4 ? i4 : col;
                            v4 = b3 ? v3 : (b4 ? k : v4);     i4 = b3 ? i3 : (b4 ? col : i4);
                            v3 = b2 ? v2 : (b3 ? k : v3);     i3 = b2 ? i2 : (b3 ? col : i3);
                            v2 = b1 ? v1 : (b2 ? k : v2);     i2 = b1 ? i1 : (b2 ? col : i2);
                            v1 = b0 ? v0 : (b1 ? k : v1);     i1 = b0 ? i0 : (b1 ? col : i1);
                            v0 = b0 ? k : v0;                 i0 = b0 ? col : i0;
                        }
                    }
                }
            }
            TCGEN05_FENCE_BEFORE();
            if (lane == 0) MBARRIER_ARRIVE(smem_base + SMEM_DFREE0 + b * 8);
        }
        int* cp = g_cand + (size_t)(rowBase + row) * 6;
        cp[0] = i0; cp[1] = i1; cp[2] = i2; cp[3] = i3; cp[4] = i4; cp[5] = i5;
    }

    __syncthreads();
    if (is_mma) TCGEN05_DEALLOC(tmem_base, 512);

#else  // ---------------- SIMT fallback (non-'a' pass) ----------------
    float* As = (float*)(smem);
    float* Bs = (float*)(smem + 4096);
    float* mv = (float*)(smem + 12288);
    int*   mi = (int*)(smem + 36864);
    const int tx = tid & 15, ty = tid >> 4;
    const bool act = (tid < 128);

    for (int half = 0; half < 2; ++half) {
        const int rh = rowBase + half * 64;
        float tv[8][3]; int tii[8][3];
#pragma unroll
        for (int i = 0; i < 8; ++i)
#pragma unroll
            for (int q = 0; q < 3; ++q) { tv[i][q] = FLT_MAX; tii[i][q] = 0x7fffffff; }

        for (int jt = 0; jt < NROW / 128; ++jt) {
            const int colBase = jt * 128;
            float c[8][8];
#pragma unroll
            for (int i = 0; i < 8; ++i)
#pragma unroll
                for (int j = 0; j < 8; ++j) c[i][j] = 0.f;

            for (int kt = 0; kt < DIM; kt += 16) {
                __syncthreads();
                if (act) {
#pragma unroll
                    for (int l = 0; l < 4; ++l) {
                        int f = tid + l * 128;
                        int r = f >> 3, uu = f & 7;
                        uint32_t w = g_xb16[(size_t)(rh + r) * 256 + kt / 2 + uu];
                        __nv_bfloat162 b2 = *(__nv_bfloat162*)&w;
                        float2 f2 = __bfloat1622float2(b2);
                        As[(2 * uu + 0) * 64 + r] = f2.x;
                        As[(2 * uu + 1) * 64 + r] = f2.y;
                    }
#pragma unroll
                    for (int l = 0; l < 8; ++l) {
                        int f = tid + l * 128;
                        int r = f >> 3, uu = f & 7;
                        uint32_t w = g_xb16[(size_t)(colBase + r) * 256 + kt / 2 + uu];
                        __nv_bfloat162 b2 = *(__nv_bfloat162*)&w;
                        float2 f2 = __bfloat1622float2(b2);
                        Bs[(2 * uu + 0) * 128 + r] = f2.x;
                        Bs[(2 * uu + 1) * 128 + r] = f2.y;
                    }
                }
                __syncthreads();
                if (act) {
#pragma unroll
                    for (int kk = 0; kk < 16; ++kk) {
                        float a[8], b[8];
#pragma unroll
                        for (int i = 0; i < 8; ++i) a[i] = As[kk * 64 + ty * 8 + i];
#pragma unroll
                        for (int j = 0; j < 8; ++j) b[j] = Bs[kk * 128 + tx * 8 + j];
#pragma unroll
                        for (int i = 0; i < 8; ++i)
#pragma unroll
                            for (int j = 0; j < 8; ++j) c[i][j] += a[i] * b[j];
                    }
                }
            }
            if (act) {
#pragma unroll
                for (int j = 0; j < 8; ++j) {
                    int col = colBase + tx * 8 + j;
                    float sqc = g_sq[col];
#pragma unroll
                    for (int i = 0; i < 8; ++i) {
                        float d2 = fmaf(-2.f, c[i][j], sqc);
                        bool b2c = (d2 < tv[i][2]) || (d2 == tv[i][2] && col < tii[i][2]);
                        if (b2c) {
                            bool b1c = (d2 < tv[i][1]) || (d2 == tv[i][1] && col < tii[i][1]);
                            bool b0c = (d2 < tv[i][0]) || (d2 == tv[i][0] && col < tii[i][0]);
                            if (b0c) {
                                tv[i][2] = tv[i][1]; tii[i][2] = tii[i][1];
                                tv[i][1] = tv[i][0]; tii[i][1] = tii[i][0];
                                tv[i][0] = d2;       tii[i][0] = col;
                            } else if (b1c) {
                                tv[i][2] = tv[i][1]; tii[i][2] = tii[i][1];
                                tv[i][1] = d2;       tii[i][1] = col;
                            } else { tv[i][2] = d2; tii[i][2] = col; }
                        }
                    }
                }
            }
        }

        __syncthreads();
        if (act) {
#pragma unroll
            for (int i = 0; i < 8; ++i)
#pragma unroll
                for (int q = 0; q < 3; ++q) {
                    mv[(ty * 8 + i) * 48 + tx * 3 + q] = tv[i][q];
                    mi[(ty * 8 + i) * 48 + tx * 3 + q] = tii[i][q];
                }
        }
        __syncthreads();
        if (tid < 64) {
            float w0 = FLT_MAX, w1 = FLT_MAX, w2 = FLT_MAX;
            int   j0 = 0x7fffffff, j1 = 0x7fffffff, j2 = 0x7fffffff;
            for (int cnd = 0; cnd < 48; ++cnd) {
                float d = mv[tid * 48 + cnd];
                int   ix = mi[tid * 48 + cnd];
                bool b2c = (d < w2) || (d == w2 && ix < j2);
                if (b2c) {
                    bool b1c = (d < w1) || (d == w1 && ix < j1);
                    bool b0c = (d < w0) || (d == w0 && ix < j0);
                    if (b0c)      { w2 = w1; j2 = j1; w1 = w0; j1 = j0; w0 = d; j0 = ix; }
                    else if (b1c) { w2 = w1; j2 = j1; w1 = d; j1 = ix; }
                    else          { w2 = d;  j2 = ix; }
                }
            }
            int* cp = g_cand + (size_t)(rh + tid) * 6;
            cp[0] = j0; cp[1] = j1; cp[2] = j2; cp[3] = j2; cp[4] = j2; cp[5] = j2;
        }
        __syncthreads();
    }
#endif
}

// ============================================================
// Kernel 2: exact re-rank of the 6 candidates (bf16 x bf16 -> fp32
// dots, fp32 sq) and pick 3rd smallest with (val, idx) tie-break.
// One warp per row.
// ============================================================
__global__ __launch_bounds__(256) void rerank_kernel() {
    int warp = threadIdx.x >> 5;
    int lane = threadIdx.x & 31;
    int row = blockIdx.x * 8 + warp;

    const uint32_t* xr = g_xb16 + (size_t)row * 256;
    float xa[16];
#pragma unroll
    for (int j = 0; j < 8; ++j) {
        uint32_t w = xr[lane + 32 * j];
        float2 f2 = __bfloat1622float2(*(__nv_bfloat162*)&w);
        xa[2 * j] = f2.x; xa[2 * j + 1] = f2.y;
    }

    int idxs[6];
    float keys[6];
#pragma unroll
    for (int c = 0; c < 6; ++c) {
        int idx = g_cand[(size_t)row * 6 + c];
        idxs[c] = idx;
        const uint32_t* cr = g_xb16 + (size_t)idx * 256;
        float s = 0.f;
#pragma unroll
        for (int j = 0; j < 8; ++j) {
            uint32_t w = cr[lane + 32 * j];
            float2 f2 = __bfloat1622float2(*(__nv_bfloat162*)&w);
            s = fmaf(xa[2 * j], f2.x, s);
            s = fmaf(xa[2 * j + 1], f2.y, s);
        }
#pragma unroll
        for (int o = 16; o > 0; o >>= 1) s += __shfl_down_sync(0xffffffffu, s, o);
        keys[c] = s;   // lane 0 holds full dot
    }

    if (lane == 0) {
#pragma unroll
        for (int c = 0; c < 6; ++c)
            keys[c] = fmaf(-2.f, keys[c], g_sq[idxs[c]]);
        // 3 selection passes, lexicographic (key, idx)
        bool used[6] = {false, false, false, false, false, false};
        int pick = 0;
#pragma unroll
        for (int pass = 0; pass < 3; ++pass) {
            float bv = FLT_MAX; int bi = 0x7fffffff; int bc = 0;
#pragma unroll
            for (int c = 0; c < 6; ++c) {
                if (!used[c] &&
                    (keys[c] < bv || (keys[c] == bv && idxs[c] < bi))) {
                    bv = keys[c]; bi = idxs[c]; bc = c;
                }
            }
            used[bc] = true;
            pick = bi;
        }
        g_neg[row] = pick;
    }
}

// ============================================================
// Kernel 3: per-row triplet loss (one warp per row, fp32 exact)
// ============================================================
__global__ __launch_bounds__(256) void rowloss_kernel(const float* __restrict__ X,
                                                      const float* __restrict__ P) {
    int warp = threadIdx.x >> 5;
    int lane = threadIdx.x & 31;
    int row = blockIdx.x * 8 + warp;
    const float4* xr = (const float4*)(X + (size_t)row * DIM);
    const float4* pr = (const float4*)(P + (size_t)row * DIM);
    const float4* nr = (const float4*)(X + (size_t)g_neg[row] * DIM);
    float sap = 0.f, san = 0.f;
#pragma unroll
    for (int i = 0; i < 4; ++i) {
        float4 x = xr[lane + 32 * i];
        float4 p = pr[lane + 32 * i];
        float4 v = nr[lane + 32 * i];
        float d;
        d = x.x - p.x + EPSV; sap += d * d;
        d = x.y - p.y + EPSV; sap += d * d;
        d = x.z - p.z + EPSV; sap += d * d;
        d = x.w - p.w + EPSV; sap += d * d;
        d = x.x - v.x + EPSV; san += d * d;
        d = x.y - v.y + EPSV; san += d * d;
        d = x.z - v.z + EPSV; san += d * d;
        d = x.w - v.w + EPSV; san += d * d;
    }
#pragma unroll
    for (int o = 16; o > 0; o >>= 1) {
        sap += __shfl_down_sync(0xffffffffu, sap, o);
        san += __shfl_down_sync(0xffffffffu, san, o);
    }
    if (lane == 0)
        g_rowloss[row] = fmaxf(sqrtf(sap) - sqrtf(san) + MARGIN, 0.f);
}

// ============================================================
// Kernel 4: mean reduction -> d_out[0]
// ============================================================
__global__ __launch_bounds__(512) void reduce_kernel(float* __restrict__ out) {
    int t = threadIdx.x;
    float s = 0.f;
    for (int i = t; i < NROW; i += 512) s += g_rowloss[i];
#pragma unroll
    for (int o = 16; o > 0; o >>= 1) s += __shfl_down_sync(0xffffffffu, s, o);
    __shared__ float ws[16];
    if ((t & 31) == 0) ws[t >> 5] = s;
    __syncthreads();
    if (t == 0) {
        float tot = 0.f;
#pragma unroll
        for (int w = 0; w < 16; ++w) tot += ws[w];
        out[0] = tot / (float)NROW;
    }
}

extern "C" void kernel_launch(void* const* d_in, const int* in_sizes, int n_in,
                              void* d_out, int out_size) {
    const float* X = (const float*)d_in[0];   // inputs  [16384, 512] f32
    const float* P = (const float*)d_in[1];   // positive[16384, 512] f32
    float* out = (float*)d_out;

    cudaFuncSetAttribute(mma_topk_kernel,
                         cudaFuncAttributeMaxDynamicSharedMemorySize, SMEM_TOTAL);

    cvtsq_kernel<<<NROW, 128>>>(X);
    mma_topk_kernel<<<128, THREADS, SMEM_TOTAL>>>();
    rerank_kernel<<<NROW / 8, 256>>>();
    rowloss_kernel<<<NROW / 8, 256>>>(X, P);
    reduce_kernel<<<1, 512>>>(out);
}

// round 10
// speedup vs baseline: 1.1280x; 1.1280x over previous
#include <cuda_runtime.h>
#include <cuda_bf16.h>
#include <math.h>
#include <float.h>
#include <stdint.h>

#define NROW 16384
#define DIM  512
#define MARGIN 2.0f
#define EPSV 1e-6f

#if defined(__CUDA_ARCH_FEAT_SM103_ALL) || (defined(__CUDA_ARCH_SPECIFIC__) && (__CUDA_ARCH_SPECIFIC__ == 1030))
#define HAS_TCGEN05 1
#else
#define HAS_TCGEN05 0
#endif

// ---- device scratch ----
__device__ __align__(16) float g_sq[NROW];
__device__ int   g_neg[NROW];
__device__ float g_rowloss[NROW];
// bf16 PRE-SWIZZLED as 512 tiles of 32 rows x 512 K = 32KB each:
// tile t: 8 slabs of 4KB (64 K-elems each); bo = r*128 + (k&63)*2,
// stored at bo^((bo>>3)&0x70). Linear 32KB bulk copy == SW128 SMEM image.
__device__ __align__(256) uint32_t g_xb[NROW * DIM / 2];
// linear bf16x2 copy (A fill + SIMT fallback)
__device__ __align__(16) uint32_t g_xb16[NROW * DIM / 2];

// SMEM layout
#define SMEM_TPTR   0
#define SMEM_FULL0  8            // 3 mbarriers (own B ring complete_tx)
#define SMEM_DONE0  32           // 2 mbarriers (MMA commit, multicast to both)
#define SMEM_DFREE0 48           // 2 mbarriers (own epilogue done with D+sq)
#define SMEM_READY0 64           // 2 mbarriers (leader only: follower tile-ready)
#define SMEM_SQF0   80           // 8 mbarriers (sq ring complete_tx)
#define SMEM_SQS    1024         // 8 slots x 256B -> ends 3072
#define SMEM_A      3072         // 128 rows x 512 bf16 SW128 = 131072 -> ends 134144
#define SMEM_B      134144       // 3 x 32768 -> ends 232448
#define SMEM_TOTAL  232448       // == 227KB opt-in max

#define TMEM_D0 0                // 64 cols f32 (own 128 rows x 64 cols)
#define TMEM_D1 64

#define NTILE 256                // 64-column tiles
#define THREADS 160              // w0 = producer(+MMA on leader), w1-4 = epilogue

#if HAS_TCGEN05
__device__ __forceinline__ uint32_t elect_one() {
    uint32_t p;
    asm volatile("{\n\t.reg .pred p;\n\telect.sync _|p, 0xFFFFFFFF;\n\tselp.b32 %0, 1, 0, p;\n\t}" : "=r"(p));
    return p;
}
#define TCGEN05_ALLOC_CG2(dst, n) \
    asm volatile("tcgen05.alloc.cta_group::2.sync.aligned.shared::cta.b32 [%0], %1;" :: "r"(dst), "r"(n) : "memory")
#define TCGEN05_DEALLOC_CG2(t, n) \
    asm volatile("tcgen05.dealloc.cta_group::2.sync.aligned.b32 %0, %1;" :: "r"(t), "r"(n))
#define TCGEN05_RELINQ_CG2() \
    asm volatile("tcgen05.relinquish_alloc_permit.cta_group::2.sync.aligned;")
#define TCGEN05_WAIT_LD() asm volatile("tcgen05.wait::ld.sync.aligned;" ::: "memory")
#define TCGEN05_FENCE_BEFORE() asm volatile("tcgen05.fence::before_thread_sync;" ::: "memory")
#define TCGEN05_FENCE_AFTER()  asm volatile("tcgen05.fence::after_thread_sync;" ::: "memory")
#define FENCE_PROXY_ASYNC() asm volatile("fence.proxy.async;" ::: "memory")
#define MBARRIER_INIT(m, c) \
    asm volatile("mbarrier.init.shared.b64 [%0], %1;" :: "r"(m), "r"(c) : "memory")
#define MBARRIER_ARRIVE(m) \
    asm volatile("mbarrier.arrive.release.cta.shared.b64 _, [%0];" :: "r"(m) : "memory")
#define MBARRIER_EXPECT_TX(m, b) \
    asm volatile("mbarrier.arrive.expect_tx.shared.b64 _, [%0], %1;" :: "r"(m), "r"(b) : "memory")
// follower -> leader (cluster rank 0) arrive, cluster-scope release
#define MBARRIER_ARRIVE_LEADER(local_addr) \
    asm volatile("{\n\t.reg .b32 rA;\n\t.reg .b32 z;\n\tmov.b32 z, 0;\n\t" \
        "mapa.shared::cluster.u32 rA, %0, z;\n\t" \
        "mbarrier.arrive.release.cluster.shared::cluster.b64 _, [rA];\n\t}" \
        :: "r"((uint32_t)(local_addr)) : "memory")
#define TCGEN05_COMMIT_MC_CG2(m) \
    asm volatile("tcgen05.commit.cta_group::2.mbarrier::arrive::one.shared::cluster.multicast::cluster.b64 [%0], %1;" \
        :: "r"(m), "h"((uint16_t)3) : "memory")
#define CLUSTER_SYNC() do { \
    asm volatile("barrier.cluster.arrive.aligned;" ::: "memory"); \
    asm volatile("barrier.cluster.wait.aligned;" ::: "memory"); \
} while (0)

#define MBARRIER_WAIT_PARITY(mbar_smem_addr, phase_parity) do { \
    uint32_t _mbar = (uint32_t)(mbar_smem_addr); \
    uint32_t _parity = (uint32_t)(phase_parity); \
    uint32_t _done; \
    asm volatile("{\n\t.reg .pred p;\n\t" \
        "mbarrier.try_wait.parity.acquire.cta.shared::cta.b64 p, [%1], %2;\n\t" \
        "selp.b32 %0, 1, 0, p;\n\t}" : "=r"(_done) : "r"(_mbar), "r"(_parity) : "memory"); \
    if (!_done) { \
        asm volatile("{\n\t.reg .pred P1;\n\t" \
            "WAIT_LOOP_%=:\n\t" \
            "mbarrier.try_wait.parity.acquire.cta.shared::cta.b64 P1, [%0], %1, 0x989680;\n\t" \
            "@P1 bra.uni WAIT_DONE_%=;\n\t" \
            "bra.uni WAIT_LOOP_%=;\n\t" \
            "WAIT_DONE_%=:\n\t}" :: "r"(_mbar), "r"(_parity) : "memory"); \
    } \
} while (0)

// cluster-scope acquire (for leader waiting follower's cluster-release arrive)
#define MBARRIER_WAIT_PARITY_CL(mbar_smem_addr, phase_parity) do { \
    uint32_t _mbar = (uint32_t)(mbar_smem_addr); \
    uint32_t _parity = (uint32_t)(phase_parity); \
    uint32_t _done; \
    asm volatile("{\n\t.reg .pred p;\n\t" \
        "mbarrier.try_wait.parity.acquire.cluster.shared::cta.b64 p, [%1], %2;\n\t" \
        "selp.b32 %0, 1, 0, p;\n\t}" : "=r"(_done) : "r"(_mbar), "r"(_parity) : "memory"); \
    if (!_done) { \
        asm volatile("{\n\t.reg .pred P1;\n\t" \
            "WAIT_LOOP_%=:\n\t" \
            "mbarrier.try_wait.parity.acquire.cluster.shared::cta.b64 P1, [%0], %1, 0x989680;\n\t" \
            "@P1 bra.uni WAIT_DONE_%=;\n\t" \
            "bra.uni WAIT_LOOP_%=;\n\t" \
            "WAIT_DONE_%=:\n\t}" :: "r"(_mbar), "r"(_parity) : "memory"); \
    } \
} while (0)

#define TCGEN05_LD_X32(r, tmem_addr) \
    asm volatile("tcgen05.ld.sync.aligned.32x32b.x32.b32 " \
        "{%0, %1, %2, %3, %4, %5, %6, %7, %8, %9, %10, %11, %12, %13, %14, %15, " \
        "%16, %17, %18, %19, %20, %21, %22, %23, %24, %25, %26, %27, %28, %29, %30, %31}, [%32];" \
        : "=r"((r)[0]),"=r"((r)[1]),"=r"((r)[2]),"=r"((r)[3]),"=r"((r)[4]),"=r"((r)[5]),"=r"((r)[6]),"=r"((r)[7]), \
          "=r"((r)[8]),"=r"((r)[9]),"=r"((r)[10]),"=r"((r)[11]),"=r"((r)[12]),"=r"((r)[13]),"=r"((r)[14]),"=r"((r)[15]), \
          "=r"((r)[16]),"=r"((r)[17]),"=r"((r)[18]),"=r"((r)[19]),"=r"((r)[20]),"=r"((r)[21]),"=r"((r)[22]),"=r"((r)[23]), \
          "=r"((r)[24]),"=r"((r)[25]),"=r"((r)[26]),"=r"((r)[27]),"=r"((r)[28]),"=r"((r)[29]),"=r"((r)[30]),"=r"((r)[31]) \
        : "r"(tmem_addr))

__device__ __forceinline__ void bulk_g2s(uint32_t dst, const void* src, uint32_t bytes, uint32_t mbar) {
    asm volatile("cp.async.bulk.shared::cta.global.mbarrier::complete_tx::bytes [%0], [%1], %2, [%3];"
                 :: "r"(dst), "l"(src), "r"(bytes), "r"(mbar) : "memory");
}

// cg2 SS-mode bf16 MMA (verified pattern from test_2cta_mma_bf16.cu)
__device__ __forceinline__ void mma_f16_ss_cg2(uint32_t d_tmem, uint64_t a_desc,
                                               uint64_t b_desc, uint32_t idesc, bool acc) {
    uint32_t en = acc ? 1u : 0u;
    asm volatile("{\n\t.reg .pred p;\n\tsetp.ne.u32 p, %5, 0;\n\t"
        "tcgen05.mma.cta_group::2.kind::f16 [%0], %1, %2, %3, "
        "{%4, %4, %4, %4, %4, %4, %4, %4}, p;\n\t}"
        :: "r"(d_tmem), "l"(a_desc), "l"(b_desc), "r"(idesc), "r"(0u), "r"(en)
        : "memory");
}

// SW128 K-major SMEM descriptor (LBO=1, SBO=64)
__device__ __forceinline__ uint64_t make_desc(uint32_t addr) {
    return (uint64_t(2) << 61) | (uint64_t(1) << 46) | (uint64_t(64) << 32)
         | (uint64_t(1) << 16) | ((addr >> 4) & 0x3FFF);
}

// idesc: F32 accum, bf16 A/B, M=256 (16<<24), N=64 (8<<17)
#define MMA_IDESC ((16u << 24) | (8u << 17) | (1u << 10) | (1u << 7) | (1u << 4))
#endif  // HAS_TCGEN05

__device__ __forceinline__ uint32_t smem_u32(const void* p) {
    uint32_t a;
    asm("{ .reg .u64 t; cvta.to.shared.u64 t, %1; cvt.u32.u64 %0, t; }" : "=r"(a) : "l"(p));
    return a;
}

// ============================================================
// Kernel 0: fp32 -> {pre-swizzled 32-row bf16 tiles, linear bf16x2}
//           + exact fp32 row norms
// ============================================================
__global__ __launch_bounds__(128) void cvtsq_kernel(const float* __restrict__ X) {
    int row = blockIdx.x;
    int t = threadIdx.x;
    float4 v = *(const float4*)(X + (size_t)row * DIM + t * 4);
    uint32_t lo, hi;
    asm("cvt.rn.bf16x2.f32 %0, %1, %2;" : "=r"(lo) : "f"(v.y), "f"(v.x));
    asm("cvt.rn.bf16x2.f32 %0, %1, %2;" : "=r"(hi) : "f"(v.w), "f"(v.z));
    *(uint2*)(g_xb16 + (size_t)row * 256 + t * 2) = make_uint2(lo, hi);
    // pre-swizzled 32-row tile image
    int tile = row >> 5, r = row & 31;
    int k = t * 4;
    uint32_t bo = (uint32_t)(r * 128 + (k & 63) * 2);
    uint32_t sw = bo ^ ((bo >> 3) & 0x70);
    *(uint2*)((char*)g_xb + (size_t)tile * 32768 + (size_t)(k >> 6) * 4096 + sw)
        = make_uint2(lo, hi);
    float s = v.x * v.x + v.y * v.y + v.z * v.z + v.w * v.w;
#pragma unroll
    for (int o = 16; o > 0; o >>= 1) s += __shfl_down_sync(0xffffffffu, s, o);
    __shared__ float ws[4];
    if ((t & 31) == 0) ws[t >> 5] = s;
    __syncthreads();
    if (t == 0) g_sq[row] = ws[0] + ws[1] + ws[2] + ws[3];
}

// ============================================================
// Kernel 1: cta_group::2 bf16 SS GEMM + min-screened top-3.
// 128 CTAs as 64 clusters of 2. Pair computes M=256: each CTA
// holds its 128 A rows in SMEM (SW128); per 64-col tile, CTA rank r
// bulk-loads B columns [u*64 + r*32, +32) (32KB, 3-deep ring).
// Leader issues 32 cg2 MMAs -> each CTA's TMEM D half (128x64 f32),
// commit multicast -> both done[u&1]. Follower signals tile-ready
// (own full + own dfree) via cluster arrive on leader's ready[u&1].
// Epilogue identical to round 8 (exact jax tie semantics).
// ============================================================
__global__ __launch_bounds__(THREADS, 1) __cluster_dims__(2, 1, 1)
void mma_topk_kernel() {
    extern __shared__ char smem[];
    const uint32_t smem_base = smem_u32(smem);
    const int tid = threadIdx.x;
    const int rowBase = blockIdx.x * 128;     // own 128 rows (pair covers 256)

#if HAS_TCGEN05
    const char* xb = (const char*)g_xb;
    const int wid = tid >> 5;
    const int lane = tid & 31;
    const bool is_prod = (wid == 0);
    const int rank = blockIdx.x & 1;          // == cluster_ctarank for dims (2,1,1)
    const int smsp = wid & 3;
    const int row = smsp * 32 + lane;

    if (is_prod) {
        TCGEN05_ALLOC_CG2(smem_base + SMEM_TPTR, 128);
        TCGEN05_RELINQ_CG2();
    }
    if (tid == 0) {
#pragma unroll
        for (int s = 0; s < 3; ++s) MBARRIER_INIT(smem_base + SMEM_FULL0 + s * 8, 1);
        MBARRIER_INIT(smem_base + SMEM_DONE0, 1);
        MBARRIER_INIT(smem_base + SMEM_DONE0 + 8, 1);
        MBARRIER_INIT(smem_base + SMEM_DFREE0, 4);
        MBARRIER_INIT(smem_base + SMEM_DFREE0 + 8, 4);
        MBARRIER_INIT(smem_base + SMEM_READY0, 1);
        MBARRIER_INIT(smem_base + SMEM_READY0 + 8, 1);
#pragma unroll
        for (int s = 0; s < 8; ++s) MBARRIER_INIT(smem_base + SMEM_SQF0 + s * 8, 1);
    }
    __syncthreads();
    uint32_t tmem_base;
    asm volatile("ld.shared.b32 %0, [%1];" : "=r"(tmem_base) : "r"(smem_base + SMEM_TPTR));

    // ---- A fill: own 128 rows x 512 bf16 into SMEM_A (SW128 slabs of 16KB) ----
    for (int f = tid; f < 8192; f += THREADS) {     // 8192 x 16B granules
        int r = f >> 6, g = f & 63;                  // row, 16B-granule in row
        uint4 v = *(const uint4*)(g_xb16 + (size_t)(rowBase + r) * 256 + g * 4);
        uint32_t bo = (uint32_t)(r * 128 + (g & 7) * 16);
        uint32_t sw = bo ^ ((bo >> 3) & 0x70);
        *(uint4*)(smem + SMEM_A + (size_t)(g >> 3) * 16384 + sw) = v;
    }
    FENCE_PROXY_ASYNC();
    __syncthreads();
    CLUSTER_SYNC();     // mbarriers + A visible cluster-wide before any MMA / mc commit

    // ---- prologue: bulk B tiles 0,1 (own 32-col half) + sq 0,1 ----
    if (is_prod && elect_one()) {
#pragma unroll
        for (int pt = 0; pt < 2; ++pt) {
            uint32_t fb = smem_base + SMEM_FULL0 + pt * 8;
            MBARRIER_EXPECT_TX(fb, 32768);
            bulk_g2s(smem_base + SMEM_B + pt * 32768,
                     xb + (size_t)(2 * pt + rank) * 32768, 32768, fb);
            uint32_t qb = smem_base + SMEM_SQF0 + pt * 8;
            MBARRIER_EXPECT_TX(qb, 256);
            bulk_g2s(smem_base + SMEM_SQS + pt * 256, (const char*)g_sq + pt * 256, 256, qb);
        }
    }

    if (is_prod) {
        const uint64_t adesc0 = make_desc(smem_base + SMEM_A);
        for (int u = 0; u < NTILE; ++u) {
            const int b = u & 1;
            // D[b] + sq-slot WAR: own epilogue fully done with tile u-2
            if (u >= 2)
                MBARRIER_WAIT_PARITY(smem_base + SMEM_DFREE0 + b * 8, ((u - 2) >> 1) & 1);
            // own B half for tile u landed
            MBARRIER_WAIT_PARITY(smem_base + SMEM_FULL0 + (u % 3) * 8, (u / 3) & 1);

            if (rank == 0) {
                // follower ready for tile u (its B landed + its epi freed D)
                MBARRIER_WAIT_PARITY_CL(smem_base + SMEM_READY0 + b * 8, (u >> 1) & 1);
                TCGEN05_FENCE_AFTER();
                if (elect_one()) {
                    uint64_t bdesc = make_desc(smem_base + SMEM_B + (u % 3) * 32768);
                    uint32_t dtm = tmem_base + (b ? TMEM_D1 : TMEM_D0);
#pragma unroll
                    for (int c = 0; c < 32; ++c) {
                        uint64_t off = (uint64_t)((c >> 2) * 256 + (c & 3) * 2);
                        uint64_t aoff = (uint64_t)((c >> 2) * 1024 + (c & 3) * 2);
                        mma_f16_ss_cg2(dtm, adesc0 + aoff, bdesc + off, MMA_IDESC, c > 0);
                    }
                    TCGEN05_COMMIT_MC_CG2(smem_base + SMEM_DONE0 + b * 8);
                }
            } else {
                TCGEN05_FENCE_AFTER();
                if (elect_one())
                    MBARRIER_ARRIVE_LEADER(smem_base + SMEM_READY0 + b * 8);
            }

            // recycle: B(u+2) -> slot (u+2)%3 (last read by MMA(u-1));
            // sq(u+2) -> slot (u+2)&7 (last read by epi(u-6) <= dfree(u-2))
            if (u + 2 < NTILE) {
                if (u >= 1)
                    MBARRIER_WAIT_PARITY(smem_base + SMEM_DONE0 + ((u - 1) & 1) * 8,
                                         ((u - 1) >> 1) & 1);
                if (elect_one()) {
                    int s2 = (u + 2) % 3;
                    uint32_t fb = smem_base + SMEM_FULL0 + s2 * 8;
                    MBARRIER_EXPECT_TX(fb, 32768);
                    bulk_g2s(smem_base + SMEM_B + s2 * 32768,
                             xb + (size_t)(2 * (u + 2) + rank) * 32768, 32768, fb);
                    int q2 = (u + 2) & 7;
                    uint32_t qb = smem_base + SMEM_SQF0 + q2 * 8;
                    MBARRIER_EXPECT_TX(qb, 256);
                    bulk_g2s(smem_base + SMEM_SQS + q2 * 256,
                             (const char*)g_sq + (size_t)(u + 2) * 256, 256, qb);
                }
            }
        }
    } else {
        // ---- epilogue warps: per-thread (one row) top-3 over all tiles ----
        float v0 = FLT_MAX, v1 = FLT_MAX, v2 = FLT_MAX;
        int   i0 = 0, i1 = 0, i2 = 0;
        for (int u = 0; u < NTILE; ++u) {
            const int b = u & 1;
            MBARRIER_WAIT_PARITY(smem_base + SMEM_DONE0 + b * 8, (u >> 1) & 1);
            TCGEN05_FENCE_AFTER();
            MBARRIER_WAIT_PARITY(smem_base + SMEM_SQF0 + (u & 7) * 8, (u >> 3) & 1);
            const float* sqt = (const float*)(smem + SMEM_SQS + (u & 7) * 256);
            const int colBase = u * 64;
            const uint32_t dtm = tmem_base + (b ? TMEM_D1 : TMEM_D0);
            uint32_t dr[64];
            TCGEN05_LD_X32(dr, dtm);
            TCGEN05_LD_X32(dr + 32, dtm + 32);
            TCGEN05_WAIT_LD();
#pragma unroll
            for (int g = 0; g < 4; ++g) {
                float key[16];
#pragma unroll
                for (int c = 0; c < 16; ++c)
                    key[c] = fmaf(-2.f, __uint_as_float(dr[g * 16 + c]), sqt[g * 16 + c]);
                float t8[8];
#pragma unroll
                for (int c = 0; c < 8; ++c) t8[c] = fminf(key[c], key[c + 8]);
                float t4a = fminf(t8[0], t8[4]), t4b = fminf(t8[1], t8[5]);
                float t4c = fminf(t8[2], t8[6]), t4d = fminf(t8[3], t8[7]);
                float mn = fminf(fminf(t4a, t4b), fminf(t4c, t4d));
                if (mn < v2) {   // rare: exact ordered insert, ascending cols
#pragma unroll
                    for (int c = 0; c < 16; ++c) {
                        float k = key[c];
                        int col = colBase + g * 16 + c;
                        if (k < v2) {
                            if (k < v1) {
                                v2 = v1; i2 = i1;
                                if (k < v0) { v1 = v0; i1 = i0; v0 = k; i0 = col; }
                                else        { v1 = k; i1 = col; }
                            } else { v2 = k; i2 = col; }
                        }
                    }
                }
            }
            // fully done with D[b] and sq slot: release to producer
            TCGEN05_FENCE_BEFORE();
            if (lane == 0) MBARRIER_ARRIVE(smem_base + SMEM_DFREE0 + b * 8);
        }
        g_neg[rowBase + row] = i2;
    }

    __syncthreads();
    CLUSTER_SYNC();     // peer MMA must be done reading my SMEM before teardown
    if (is_prod) TCGEN05_DEALLOC_CG2(tmem_base, 128);
    CLUSTER_SYNC();

#else  // ---------------- SIMT fallback (non-'a' pass) ----------------
    float* As = (float*)(smem);
    float* Bs = (float*)(smem + 4096);
    float* mv = (float*)(smem + 12288);
    int*   mi = (int*)(smem + 36864);
    const int tx = tid & 15, ty = tid >> 4;
    const bool act = (tid < 128);

    for (int half = 0; half < 2; ++half) {
        const int rh = rowBase + half * 64;
        float tv[8][3]; int tii[8][3];
#pragma unroll
        for (int i = 0; i < 8; ++i)
#pragma unroll
            for (int q = 0; q < 3; ++q) { tv[i][q] = FLT_MAX; tii[i][q] = 0x7fffffff; }

        for (int jt = 0; jt < NROW / 128; ++jt) {
            const int colBase = jt * 128;
            float c[8][8];
#pragma unroll
            for (int i = 0; i < 8; ++i)
#pragma unroll
                for (int j = 0; j < 8; ++j) c[i][j] = 0.f;

            for (int kt = 0; kt < DIM; kt += 16) {
                __syncthreads();
                if (act) {
#pragma unroll
                    for (int l = 0; l < 4; ++l) {
                        int f = tid + l * 128;
                        int r = f >> 3, uu = f & 7;
                        uint32_t w = g_xb16[(size_t)(rh + r) * 256 + kt / 2 + uu];
                        __nv_bfloat162 b2 = *(__nv_bfloat162*)&w;
                        float2 f2 = __bfloat1622float2(b2);
                        As[(2 * uu + 0) * 64 + r] = f2.x;
                        As[(2 * uu + 1) * 64 + r] = f2.y;
                    }
#pragma unroll
                    for (int l = 0; l < 8; ++l) {
                        int f = tid + l * 128;
                        int r = f >> 3, uu = f & 7;
                        uint32_t w = g_xb16[(size_t)(colBase + r) * 256 + kt / 2 + uu];
                        __nv_bfloat162 b2 = *(__nv_bfloat162*)&w;
                        float2 f2 = __bfloat1622float2(b2);
                        Bs[(2 * uu + 0) * 128 + r] = f2.x;
                        Bs[(2 * uu + 1) * 128 + r] = f2.y;
                    }
                }
                __syncthreads();
                if (act) {
#pragma unroll
                    for (int kk = 0; kk < 16; ++kk) {
                        float a[8], b[8];
#pragma unroll
                        for (int i = 0; i < 8; ++i) a[i] = As[kk * 64 + ty * 8 + i];
#pragma unroll
                        for (int j = 0; j < 8; ++j) b[j] = Bs[kk * 128 + tx * 8 + j];
#pragma unroll
                        for (int i = 0; i < 8; ++i)
#pragma unroll
                            for (int j = 0; j < 8; ++j) c[i][j] += a[i] * b[j];
                    }
                }
            }
            if (act) {
#pragma unroll
                for (int j = 0; j < 8; ++j) {
                    int col = colBase + tx * 8 + j;
                    float sqc = g_sq[col];
#pragma unroll
                    for (int i = 0; i < 8; ++i) {
                        float d2 = fmaf(-2.f, c[i][j], sqc);
                        bool b2c = (d2 < tv[i][2]) || (d2 == tv[i][2] && col < tii[i][2]);
                        if (b2c) {
                            bool b1c = (d2 < tv[i][1]) || (d2 == tv[i][1] && col < tii[i][1]);
                            bool b0c = (d2 < tv[i][0]) || (d2 == tv[i][0] && col < tii[i][0]);
                            if (b0c) {
                                tv[i][2] = tv[i][1]; tii[i][2] = tii[i][1];
                                tv[i][1] = tv[i][0]; tii[i][1] = tii[i][0];
                                tv[i][0] = d2;       tii[i][0] = col;
                            } else if (b1c) {
                                tv[i][2] = tv[i][1]; tii[i][2] = tii[i][1];
                                tv[i][1] = d2;       tii[i][1] = col;
                            } else { tv[i][2] = d2; tii[i][2] = col; }
                        }
                    }
                }
            }
        }

        __syncthreads();
        if (act) {
#pragma unroll
            for (int i = 0; i < 8; ++i)
#pragma unroll
                for (int q = 0; q < 3; ++q) {
                    mv[(ty * 8 + i) * 48 + tx * 3 + q] = tv[i][q];
                    mi[(ty * 8 + i) * 48 + tx * 3 + q] = tii[i][q];
                }
        }
        __syncthreads();
        if (tid < 64) {
            float w0 = FLT_MAX, w1 = FLT_MAX, w2 = FLT_MAX;
            int   j0 = 0x7fffffff, j1 = 0x7fffffff, j2 = 0x7fffffff;
            for (int cnd = 0; cnd < 48; ++cnd) {
                float d = mv[tid * 48 + cnd];
                int   ix = mi[tid * 48 + cnd];
                bool b2c = (d < w2) || (d == w2 && ix < j2);
                if (b2c) {
                    bool b1c = (d < w1) || (d == w1 && ix < j1);
                    bool b0c = (d < w0) || (d == w0 && ix < j0);
                    if (b0c)      { w2 = w1; j2 = j1; w1 = w0; j1 = j0; w0 = d; j0 = ix; }
                    else if (b1c) { w2 = w1; j2 = j1; w1 = d; j1 = ix; }
                    else          { w2 = d;  j2 = ix; }
                }
            }
            g_neg[rh + tid] = j2;
        }
        __syncthreads();
    }
#endif
}

// ============================================================
// Kernel 2: per-row triplet loss (one warp per row, fp32 exact)
// ============================================================
__global__ __launch_bounds__(256) void rowloss_kernel(const float* __restrict__ X,
                                                      const float* __restrict__ P) {
    int warp = threadIdx.x >> 5;
    int lane = threadIdx.x & 31;
    int row = blockIdx.x * 8 + warp;
    const float4* xr = (const float4*)(X + (size_t)row * DIM);
    const float4* pr = (const float4*)(P + (size_t)row * DIM);
    const float4* nr = (const float4*)(X + (size_t)g_neg[row] * DIM);
    float sap = 0.f, san = 0.f;
#pragma unroll
    for (int i = 0; i < 4; ++i) {
        float4 x = xr[lane + 32 * i];
        float4 p = pr[lane + 32 * i];
        float4 v = nr[lane + 32 * i];
        float d;
        d = x.x - p.x + EPSV; sap += d * d;
        d = x.y - p.y + EPSV; sap += d * d;
        d = x.z - p.z + EPSV; sap += d * d;
        d = x.w - p.w + EPSV; sap += d * d;
        d = x.x - v.x + EPSV; san += d * d;
        d = x.y - v.y + EPSV; san += d * d;
        d = x.z - v.z + EPSV; san += d * d;
        d = x.w - v.w + EPSV; san += d * d;
    }
#pragma unroll
    for (int o = 16; o > 0; o >>= 1) {
        sap += __shfl_down_sync(0xffffffffu, sap, o);
        san += __shfl_down_sync(0xffffffffu, san, o);
    }
    if (lane == 0)
        g_rowloss[row] = fmaxf(sqrtf(sap) - sqrtf(san) + MARGIN, 0.f);
}

// ============================================================
// Kernel 3: mean reduction -> d_out[0]
// ============================================================
__global__ __launch_bounds__(512) void reduce_kernel(float* __restrict__ out) {
    int t = threadIdx.x;
    float s = 0.f;
    for (int i = t; i < NROW; i += 512) s += g_rowloss[i];
#pragma unroll
    for (int o = 16; o > 0; o >>= 1) s += __shfl_down_sync(0xffffffffu, s, o);
    __shared__ float ws[16];
    if ((t & 31) == 0) ws[t >> 5] = s;
    __syncthreads();
    if (t == 0) {
        float tot = 0.f;
#pragma unroll
        for (int w = 0; w < 16; ++w) tot += ws[w];
        out[0] = tot / (float)NROW;
    }
}

extern "C" void kernel_launch(void* const* d_in, const int* in_sizes, int n_in,
                              void* d_out, int out_size) {
    const float* X = (const float*)d_in[0];   // inputs  [16384, 512] f32
    const float* P = (const float*)d_in[1];   // positive[16384, 512] f32
    float* out = (float*)d_out;

    cudaFuncSetAttribute(mma_topk_kernel,
                         cudaFuncAttributeMaxDynamicSharedMemorySize, SMEM_TOTAL);

    cvtsq_kernel<<<NROW, 128>>>(X);
    mma_topk_kernel<<<128, THREADS, SMEM_TOTAL>>>();
    rowloss_kernel<<<NROW / 8, 256>>>(X, P);
    reduce_kernel<<<1, 512>>>(out);
}

// round 11
// speedup vs baseline: 1.2707x; 1.1266x over previous
#include <cuda_runtime.h>
#include <cuda_bf16.h>
#include <math.h>
#include <float.h>
#include <stdint.h>

#define NROW 16384
#define DIM  512
#define MARGIN 2.0f
#define EPSV 1e-6f

#if defined(__CUDA_ARCH_FEAT_SM103_ALL) || (defined(__CUDA_ARCH_SPECIFIC__) && (__CUDA_ARCH_SPECIFIC__ == 1030))
#define HAS_TCGEN05 1
#else
#define HAS_TCGEN05 0
#endif

// ---- device scratch (no dynamic allocation allowed) ----
__device__ __align__(16) float g_sq[NROW];
__device__ int   g_neg[NROW];
__device__ float g_rowloss[NROW];
// bf16 inputs PRE-SWIZZLED as 256 column-tiles of 64KB each:
// tile t (rows t*64..t*64+63), 8 slabs of 8KB (64 elems of K each),
// within slab: byte bo = r*128 + (k&63)*2, stored at bo^((bo>>3)&0x70).
// A linear 64KB bulk copy reproduces the SW128 SMEM image exactly.
__device__ __align__(256) uint32_t g_xb[NROW * DIM / 2];

// SMEM layout
#define SMEM_TPTR   0
#define SMEM_FULL0  8            // 3 mbarriers (B ring complete_tx)
#define SMEM_DONEA0 32           // 2 mbarriers (MMA set0 commit)
#define SMEM_DONEB0 48           // 2 mbarriers (MMA set0+set1 commit)
#define SMEM_DFREE0 64           // 2 mbarriers (epilogue done with D+sq)
#define SMEM_SQF0   80           // 8 mbarriers (sq ring complete_tx)
#define SMEM_SQS    1024         // 8 slots x 512B -> ends 5120
#define SMEM_B      8192         // 3 x 65536
#define SMEM_TOTAL  (8192 + 3 * 65536)

#define TMEM_A  0                // 256 cols: A 128x512 bf16
#define TMEM_D0 256              // 128 cols f32 (two 64-col halves)
#define TMEM_D1 384

#define NT2 128                  // 128 super-tiles of 128 columns
#define THREADS 160              // w0 = producer+MMA, w1-4 = epilogue

#if HAS_TCGEN05
__device__ __forceinline__ uint32_t elect_one() {
    uint32_t p;
    asm volatile("{\n\t.reg .pred p;\n\telect.sync _|p, 0xFFFFFFFF;\n\tselp.b32 %0, 1, 0, p;\n\t}" : "=r"(p));
    return p;
}
#define TCGEN05_ALLOC(dst, n) \
    asm volatile("tcgen05.alloc.cta_group::1.sync.aligned.shared::cta.b32 [%0], %1;" :: "r"(dst), "r"(n) : "memory")
#define TCGEN05_DEALLOC(t, n) \
    asm volatile("tcgen05.dealloc.cta_group::1.sync.aligned.b32 %0, %1;" :: "r"(t), "r"(n))
#define TCGEN05_RELINQ() \
    asm volatile("tcgen05.relinquish_alloc_permit.cta_group::1.sync.aligned;")
#define TCGEN05_WAIT_ST() asm volatile("tcgen05.wait::st.sync.aligned;" ::: "memory")
#define TCGEN05_WAIT_LD() asm volatile("tcgen05.wait::ld.sync.aligned;" ::: "memory")
#define TCGEN05_FENCE_BEFORE() asm volatile("tcgen05.fence::before_thread_sync;" ::: "memory")
#define TCGEN05_FENCE_AFTER()  asm volatile("tcgen05.fence::after_thread_sync;" ::: "memory")
#define MBARRIER_INIT(m, c) \
    asm volatile("mbarrier.init.shared.b64 [%0], %1;" :: "r"(m), "r"(c) : "memory")
#define MBARRIER_ARRIVE(m) \
    asm volatile("mbarrier.arrive.release.cta.shared.b64 _, [%0];" :: "r"(m) : "memory")
#define MBARRIER_EXPECT_TX(m, b) \
    asm volatile("mbarrier.arrive.expect_tx.shared.b64 _, [%0], %1;" :: "r"(m), "r"(b) : "memory")
#define TCGEN05_COMMIT(m) \
    asm volatile("tcgen05.commit.cta_group::1.mbarrier::arrive::one.shared::cluster.b64 [%0];" :: "r"(m) : "memory")

#define MBARRIER_WAIT_PARITY(mbar_smem_addr, phase_parity) do { \
    uint32_t _mbar = (uint32_t)(mbar_smem_addr); \
    uint32_t _parity = (uint32_t)(phase_parity); \
    uint32_t _done; \
    asm volatile("{\n\t.reg .pred p;\n\t" \
        "mbarrier.try_wait.parity.acquire.cta.shared::cta.b64 p, [%1], %2;\n\t" \
        "selp.b32 %0, 1, 0, p;\n\t}" : "=r"(_done) : "r"(_mbar), "r"(_parity) : "memory"); \
    if (!_done) { \
        asm volatile("{\n\t.reg .pred P1;\n\t" \
            "WAIT_LOOP_%=:\n\t" \
            "mbarrier.try_wait.parity.acquire.cta.shared::cta.b64 P1, [%0], %1, 0x989680;\n\t" \
            "@P1 bra.uni WAIT_DONE_%=;\n\t" \
            "bra.uni WAIT_LOOP_%=;\n\t" \
            "WAIT_DONE_%=:\n\t}" :: "r"(_mbar), "r"(_parity) : "memory"); \
    } \
} while (0)

#define TCGEN05_ST_X32(tmem_addr, r) \
    asm volatile("tcgen05.st.sync.aligned.32x32b.x32.b32 [%0], " \
        "{%1, %2, %3, %4, %5, %6, %7, %8, %9, %10, %11, %12, %13, %14, %15, %16, " \
        "%17, %18, %19, %20, %21, %22, %23, %24, %25, %26, %27, %28, %29, %30, %31, %32};" \
        :: "r"(tmem_addr), \
           "r"((r)[0]),"r"((r)[1]),"r"((r)[2]),"r"((r)[3]),"r"((r)[4]),"r"((r)[5]),"r"((r)[6]),"r"((r)[7]), \
           "r"((r)[8]),"r"((r)[9]),"r"((r)[10]),"r"((r)[11]),"r"((r)[12]),"r"((r)[13]),"r"((r)[14]),"r"((r)[15]), \
           "r"((r)[16]),"r"((r)[17]),"r"((r)[18]),"r"((r)[19]),"r"((r)[20]),"r"((r)[21]),"r"((r)[22]),"r"((r)[23]), \
           "r"((r)[24]),"r"((r)[25]),"r"((r)[26]),"r"((r)[27]),"r"((r)[28]),"r"((r)[29]),"r"((r)[30]),"r"((r)[31]) \
        : "memory")

#define TCGEN05_LD_X32(r, tmem_addr) \
    asm volatile("tcgen05.ld.sync.aligned.32x32b.x32.b32 " \
        "{%0, %1, %2, %3, %4, %5, %6, %7, %8, %9, %10, %11, %12, %13, %14, %15, " \
        "%16, %17, %18, %19, %20, %21, %22, %23, %24, %25, %26, %27, %28, %29, %30, %31}, [%32];" \
        : "=r"((r)[0]),"=r"((r)[1]),"=r"((r)[2]),"=r"((r)[3]),"=r"((r)[4]),"=r"((r)[5]),"=r"((r)[6]),"=r"((r)[7]), \
          "=r"((r)[8]),"=r"((r)[9]),"=r"((r)[10]),"=r"((r)[11]),"=r"((r)[12]),"=r"((r)[13]),"=r"((r)[14]),"=r"((r)[15]), \
          "=r"((r)[16]),"=r"((r)[17]),"=r"((r)[18]),"=r"((r)[19]),"=r"((r)[20]),"=r"((r)[21]),"=r"((r)[22]),"=r"((r)[23]), \
          "=r"((r)[24]),"=r"((r)[25]),"=r"((r)[26]),"=r"((r)[27]),"=r"((r)[28]),"=r"((r)[29]),"=r"((r)[30]),"=r"((r)[31]) \
        : "r"(tmem_addr))

__device__ __forceinline__ void bulk_g2s(uint32_t dst, const void* src, uint32_t bytes, uint32_t mbar) {
    asm volatile("cp.async.bulk.shared::cta.global.mbarrier::complete_tx::bytes [%0], [%1], %2, [%3];"
                 :: "r"(dst), "l"(src), "r"(bytes), "r"(mbar) : "memory");
}

// TS-mode bf16 MMA: A in TMEM, B via SMEM descriptor
__device__ __forceinline__ void mma_f16_ts(uint32_t d_tmem, uint32_t a_tmem,
                                           uint64_t b_desc, uint32_t idesc, bool acc) {
    uint32_t en = acc ? 1u : 0u;
    uint32_t z = 0u;
    asm volatile("{\n\t.reg .pred p;\n\tsetp.ne.u32 p, %5, 0;\n\t"
        "tcgen05.mma.cta_group::1.kind::f16 [%0], [%1], %2, %3, {%4, %4, %4, %4}, p;\n\t}"
        :: "r"(d_tmem), "r"(a_tmem), "l"(b_desc), "r"(idesc), "r"(z), "r"(en)
        : "memory");
}

// SW128 K-major SMEM descriptor (LBO=1, SBO=64)
__device__ __forceinline__ uint64_t make_desc(uint32_t addr) {
    return (uint64_t(2) << 61) | (uint64_t(1) << 46) | (uint64_t(64) << 32)
         | (uint64_t(1) << 16) | ((addr >> 4) & 0x3FFF);
}

// idesc: F32 accum, bf16 A/B, M=128 (8<<24), N=64 (8<<17)
#define MMA_IDESC ((8u << 24) | (8u << 17) | (1u << 10) | (1u << 7) | (1u << 4))
#endif  // HAS_TCGEN05

__device__ __forceinline__ uint32_t smem_u32(const void* p) {
    uint32_t a;
    asm("{ .reg .u64 t; cvta.to.shared.u64 t, %1; cvt.u32.u64 %0, t; }" : "=r"(a) : "l"(p));
    return a;
}

// ============================================================
// Kernel 0: fp32 -> pre-swizzled bf16 tiles + exact row norms
// ============================================================
__global__ __launch_bounds__(128) void cvtsq_kernel(const float* __restrict__ X) {
    int row = blockIdx.x;
    int t = threadIdx.x;
    float4 v = *(const float4*)(X + (size_t)row * DIM + t * 4);
    uint32_t lo, hi;
    asm("cvt.rn.bf16x2.f32 %0, %1, %2;" : "=r"(lo) : "f"(v.y), "f"(v.x));
    asm("cvt.rn.bf16x2.f32 %0, %1, %2;" : "=r"(hi) : "f"(v.w), "f"(v.z));
    int tile = row >> 6, r = row & 63;
    int k = t * 4;
    uint32_t bo = (uint32_t)(r * 128 + (k & 63) * 2);
    uint32_t sw = bo ^ ((bo >> 3) & 0x70);
    *(uint2*)((char*)g_xb + (size_t)tile * 65536 + (size_t)(k >> 6) * 8192 + sw)
        = make_uint2(lo, hi);
    float s = v.x * v.x + v.y * v.y + v.z * v.z + v.w * v.w;
#pragma unroll
    for (int o = 16; o > 0; o >>= 1) s += __shfl_down_sync(0xffffffffu, s, o);
    __shared__ float ws[4];
    if ((t & 31) == 0) ws[t >> 5] = s;
    __syncthreads();
    if (t == 0) g_sq[row] = ws[0] + ws[1] + ws[2] + ws[3];
}

// ============================================================
// Kernel 1: async tcgen05 bf16 GEMM, 128-col super-tiles.
// 128 CTAs x 160 threads. Per super-tile u (cols u*128..+128):
//   w0: wait dfree(u-2); [full(2u) -> 32 MMAs -> D[u&1] lo, commit doneA];
//       [full(2u+1) -> 32 MMAs -> D[u&1] hi, commit doneB];
//       recycle slot (2u+2)%3 after doneB(u-1), slot (2u+3)%3 after doneA(u).
//   w1-4: wait doneB(u) -> LDTM 128 cols -> min-screen top-3 -> dfree.
// Tensor pipe in-order => doneA/doneB cover exactly the right WARs.
// ============================================================
__global__ __launch_bounds__(THREADS, 1)
void mma_topk_kernel() {
    extern __shared__ char smem[];
    const uint32_t smem_base = smem_u32(smem);
    const int tid = threadIdx.x;
    const int rowBase = blockIdx.x * 128;
    const char* xb = (const char*)g_xb;

#if HAS_TCGEN05
    const int wid = tid >> 5;
    const int lane = tid & 31;
    const bool is_mma = (wid == 0);
    const int smsp = wid & 3;
    const int row = smsp * 32 + lane;

    if (is_mma) {
        TCGEN05_ALLOC(smem_base + SMEM_TPTR, 512);
        TCGEN05_RELINQ();
    }
    if (tid == 0) {
#pragma unroll
        for (int s = 0; s < 3; ++s) MBARRIER_INIT(smem_base + SMEM_FULL0 + s * 8, 1);
        MBARRIER_INIT(smem_base + SMEM_DONEA0, 1);
        MBARRIER_INIT(smem_base + SMEM_DONEA0 + 8, 1);
        MBARRIER_INIT(smem_base + SMEM_DONEB0, 1);
        MBARRIER_INIT(smem_base + SMEM_DONEB0 + 8, 1);
        MBARRIER_INIT(smem_base + SMEM_DFREE0, 4);
        MBARRIER_INIT(smem_base + SMEM_DFREE0 + 8, 4);
#pragma unroll
        for (int s = 0; s < 8; ++s) MBARRIER_INIT(smem_base + SMEM_SQF0 + s * 8, 1);
    }
    __syncthreads();
    uint32_t tmem_base;
    asm volatile("ld.shared.b32 %0, [%1];" : "=r"(tmem_base) : "r"(smem_base + SMEM_TPTR));

    // ---- prologue ----
    if (!is_mma) {
        // A (this warp's 32 rows x 512 bf16) -> TMEM, de-swizzled 16B granules
        const int R = rowBase + row;
        const int tt = R >> 6, r = R & 63;
        const char* tbase = xb + (size_t)tt * 65536;
        uint32_t wo = (uint32_t)smsp << 21;
#pragma unroll
        for (int c8 = 0; c8 < 8; ++c8) {
            uint32_t rg[32];
#pragma unroll
            for (int u = 0; u < 8; ++u) {
                int g = c8 * 8 + u;
                uint32_t bo = (uint32_t)(r * 128 + (g & 7) * 16);
                uint32_t sw = bo ^ ((bo >> 3) & 0x70);
                uint4 v = *(const uint4*)(tbase + (size_t)(g >> 3) * 8192 + sw);
                rg[u * 4 + 0] = v.x; rg[u * 4 + 1] = v.y;
                rg[u * 4 + 2] = v.z; rg[u * 4 + 3] = v.w;
            }
            TCGEN05_ST_X32(tmem_base + TMEM_A + c8 * 32 + wo, rg);
        }
        TCGEN05_WAIT_ST();
        TCGEN05_FENCE_BEFORE();
    } else {
        if (elect_one()) {
            // B tiles 0,1 -> slots 0,1; sq super-tile 0 -> slot 0
#pragma unroll
            for (int pt = 0; pt < 2; ++pt) {
                uint32_t fb = smem_base + SMEM_FULL0 + pt * 8;
                MBARRIER_EXPECT_TX(fb, 65536);
                bulk_g2s(smem_base + SMEM_B + pt * 65536, xb + (size_t)pt * 65536, 65536, fb);
            }
            uint32_t qb = smem_base + SMEM_SQF0;
            MBARRIER_EXPECT_TX(qb, 512);
            bulk_g2s(smem_base + SMEM_SQS, (const char*)g_sq, 512, qb);
        }
    }
    __syncthreads();   // A in TMEM visible to MMA warp

    if (is_mma) {
        TCGEN05_FENCE_AFTER();
        for (int u = 0; u < NT2; ++u) {
            const int b = u & 1;
            const int t0 = 2 * u, t1 = 2 * u + 1;
            if (u >= 2) {
                MBARRIER_WAIT_PARITY(smem_base + SMEM_DFREE0 + b * 8, ((u - 2) >> 1) & 1);
                TCGEN05_FENCE_AFTER();
            }
            // set 0: B tile t0 -> D[b] cols 0..63
            MBARRIER_WAIT_PARITY(smem_base + SMEM_FULL0 + (t0 % 3) * 8, (t0 / 3) & 1);
            if (elect_one()) {
                uint64_t bdesc = make_desc(smem_base + SMEM_B + (t0 % 3) * 65536);
                uint32_t dtm = tmem_base + (b ? TMEM_D1 : TMEM_D0);
#pragma unroll
                for (int c = 0; c < 32; ++c) {
                    uint64_t bd = bdesc + (uint64_t)((c >> 2) * 512 + (c & 3) * 2);
                    mma_f16_ts(dtm, tmem_base + TMEM_A + c * 8, bd, MMA_IDESC, c > 0);
                }
                TCGEN05_COMMIT(smem_base + SMEM_DONEA0 + b * 8);
            }
            // set 1: B tile t1 -> D[b] cols 64..127
            MBARRIER_WAIT_PARITY(smem_base + SMEM_FULL0 + (t1 % 3) * 8, (t1 / 3) & 1);
            if (elect_one()) {
                uint64_t bdesc = make_desc(smem_base + SMEM_B + (t1 % 3) * 65536);
                uint32_t dtm = tmem_base + (b ? TMEM_D1 : TMEM_D0) + 64;
#pragma unroll
                for (int c = 0; c < 32; ++c) {
                    uint64_t bd = bdesc + (uint64_t)((c >> 2) * 512 + (c & 3) * 2);
                    mma_f16_ts(dtm, tmem_base + TMEM_A + c * 8, bd, MMA_IDESC, c > 0);
                }
                TCGEN05_COMMIT(smem_base + SMEM_DONEB0 + b * 8);
            }
            // recycle loads for super-tile u+1 (tiles t0+2, t1+2)
            if (u + 1 < NT2) {
                // slot (t0+2)%3 was last read by MMA set1(u-1) (tile t0-1)
                if (u >= 1)
                    MBARRIER_WAIT_PARITY(smem_base + SMEM_DONEB0 + ((u - 1) & 1) * 8,
                                         ((u - 1) >> 1) & 1);
                if (elect_one()) {
                    int s2 = (t0 + 2) % 3;
                    uint32_t fb = smem_base + SMEM_FULL0 + s2 * 8;
                    MBARRIER_EXPECT_TX(fb, 65536);
                    bulk_g2s(smem_base + SMEM_B + s2 * 65536,
                             xb + (size_t)(t0 + 2) * 65536, 65536, fb);
                    int q2 = (u + 1) & 7;   // sq slot; epi(u-7) done via dfree(u-2)
                    uint32_t qb = smem_base + SMEM_SQF0 + q2 * 8;
                    MBARRIER_EXPECT_TX(qb, 512);
                    bulk_g2s(smem_base + SMEM_SQS + q2 * 512,
                             (const char*)g_sq + (size_t)(u + 1) * 512, 512, qb);
                }
                // slot (t1+2)%3 == (t0)%3, last read by MMA set0(u) -> doneA(u)
                MBARRIER_WAIT_PARITY(smem_base + SMEM_DONEA0 + b * 8, (u >> 1) & 1);
                if (elect_one()) {
                    int s3 = (t1 + 2) % 3;
                    uint32_t fb = smem_base + SMEM_FULL0 + s3 * 8;
                    MBARRIER_EXPECT_TX(fb, 65536);
                    bulk_g2s(smem_base + SMEM_B + s3 * 65536,
                             xb + (size_t)(t1 + 2) * 65536, 65536, fb);
                }
            }
        }
    } else {
        // epilogue warps: per-thread (one row) top-3 over all super-tiles
        float v0 = FLT_MAX, v1 = FLT_MAX, v2 = FLT_MAX;
        int   i0 = 0, i1 = 0, i2 = 0;
        for (int u = 0; u < NT2; ++u) {
            const int b = u & 1;
            MBARRIER_WAIT_PARITY(smem_base + SMEM_DONEB0 + b * 8, (u >> 1) & 1);
            TCGEN05_FENCE_AFTER();
            MBARRIER_WAIT_PARITY(smem_base + SMEM_SQF0 + (u & 7) * 8, (u >> 3) & 1);
            const float* sqt = (const float*)(smem + SMEM_SQS + (u & 7) * 512);
            const uint32_t dtm = tmem_base + (b ? TMEM_D1 : TMEM_D0);
#pragma unroll
            for (int h = 0; h < 2; ++h) {
                uint32_t dr[64];
                TCGEN05_LD_X32(dr, dtm + h * 64);
                TCGEN05_LD_X32(dr + 32, dtm + h * 64 + 32);
                TCGEN05_WAIT_LD();
                const int colBase = u * 128 + h * 64;
                const float* sqh = sqt + h * 64;
#pragma unroll
                for (int g = 0; g < 4; ++g) {
                    float key[16];
#pragma unroll
                    for (int c = 0; c < 16; ++c)
                        key[c] = fmaf(-2.f, __uint_as_float(dr[g * 16 + c]), sqh[g * 16 + c]);
                    float t8[8];
#pragma unroll
                    for (int c = 0; c < 8; ++c) t8[c] = fminf(key[c], key[c + 8]);
                    float t4a = fminf(t8[0], t8[4]), t4b = fminf(t8[1], t8[5]);
                    float t4c = fminf(t8[2], t8[6]), t4d = fminf(t8[3], t8[7]);
                    float mn = fminf(fminf(t4a, t4b), fminf(t4c, t4d));
                    if (mn < v2) {   // rare: exact ordered insert, ascending cols
#pragma unroll
                        for (int c = 0; c < 16; ++c) {
                            float k = key[c];
                            int col = colBase + g * 16 + c;
                            if (k < v2) {
                                if (k < v1) {
                                    v2 = v1; i2 = i1;
                                    if (k < v0) { v1 = v0; i1 = i0; v0 = k; i0 = col; }
                                    else        { v1 = k; i1 = col; }
                                } else { v2 = k; i2 = col; }
                            }
                        }
                    }
                }
            }
            TCGEN05_FENCE_BEFORE();
            if (lane == 0) MBARRIER_ARRIVE(smem_base + SMEM_DFREE0 + b * 8);
        }
        g_neg[rowBase + row] = i2;
    }

    __syncthreads();
    if (is_mma) TCGEN05_DEALLOC(tmem_base, 512);

#else  // ---------------- SIMT fallback (non-'a' pass) ----------------
    // Reads the pre-swizzled g_xb layout via per-4B de-swizzle.
    float* As = (float*)(smem);
    float* Bs = (float*)(smem + 4096);
    float* mv = (float*)(smem + 12288);
    int*   mi = (int*)(smem + 36864);
    const int tx = tid & 15, ty = tid >> 4;
    const bool act = (tid < 128);

    for (int half = 0; half < 2; ++half) {
        const int rh = rowBase + half * 64;
        float tv[8][3]; int tii[8][3];
#pragma unroll
        for (int i = 0; i < 8; ++i)
#pragma unroll
            for (int q = 0; q < 3; ++q) { tv[i][q] = FLT_MAX; tii[i][q] = 0x7fffffff; }

        for (int jt = 0; jt < NROW / 128; ++jt) {
            const int colBase = jt * 128;
            float c[8][8];
#pragma unroll
            for (int i = 0; i < 8; ++i)
#pragma unroll
                for (int j = 0; j < 8; ++j) c[i][j] = 0.f;

            for (int kt = 0; kt < DIM; kt += 16) {
                __syncthreads();
                if (act) {
#pragma unroll
                    for (int l = 0; l < 4; ++l) {
                        int f = tid + l * 128;
                        int r = f >> 3, uu = f & 7;
                        int R = rh + r, kk = kt + 2 * uu;
                        uint32_t bo = (uint32_t)((R & 63) * 128 + (kk & 63) * 2);
                        uint32_t sw = bo ^ ((bo >> 3) & 0x70);
                        uint32_t w = *(const uint32_t*)(xb + (size_t)(R >> 6) * 65536
                                                        + (size_t)(kk >> 6) * 8192 + sw);
                        __nv_bfloat162 b2 = *(__nv_bfloat162*)&w;
                        float2 f2 = __bfloat1622float2(b2);
                        As[(2 * uu + 0) * 64 + r] = f2.x;
                        As[(2 * uu + 1) * 64 + r] = f2.y;
                    }
#pragma unroll
                    for (int l = 0; l < 8; ++l) {
                        int f = tid + l * 128;
                        int r = f >> 3, uu = f & 7;
                        int R = colBase + r, kk = kt + 2 * uu;
                        uint32_t bo = (uint32_t)((R & 63) * 128 + (kk & 63) * 2);
                        uint32_t sw = bo ^ ((bo >> 3) & 0x70);
                        uint32_t w = *(const uint32_t*)(xb + (size_t)(R >> 6) * 65536
                                                        + (size_t)(kk >> 6) * 8192 + sw);
                        __nv_bfloat162 b2 = *(__nv_bfloat162*)&w;
                        float2 f2 = __bfloat1622float2(b2);
                        Bs[(2 * uu + 0) * 128 + r] = f2.x;
                        Bs[(2 * uu + 1) * 128 + r] = f2.y;
                    }
                }
                __syncthreads();
                if (act) {
#pragma unroll
                    for (int kk = 0; kk < 16; ++kk) {
                        float a[8], b[8];
#pragma unroll
                        for (int i = 0; i < 8; ++i) a[i] = As[kk * 64 + ty * 8 + i];
#pragma unroll
                        for (int j = 0; j < 8; ++j) b[j] = Bs[kk * 128 + tx * 8 + j];
#pragma unroll
                        for (int i = 0; i < 8; ++i)
#pragma unroll
                            for (int j = 0; j < 8; ++j) c[i][j] += a[i] * b[j];
                    }
                }
            }
            if (act) {
#pragma unroll
                for (int j = 0; j < 8; ++j) {
                    int col = colBase + tx * 8 + j;
                    float sqc = g_sq[col];
#pragma unroll
                    for (int i = 0; i < 8; ++i) {
                        float d2 = fmaf(-2.f, c[i][j], sqc);
                        bool b2c = (d2 < tv[i][2]) || (d2 == tv[i][2] && col < tii[i][2]);
                        if (b2c) {
                            bool b1c = (d2 < tv[i][1]) || (d2 == tv[i][1] && col < tii[i][1]);
                            bool b0c = (d2 < tv[i][0]) || (d2 == tv[i][0] && col < tii[i][0]);
                            if (b0c) {
                                tv[i][2] = tv[i][1]; tii[i][2] = tii[i][1];
                                tv[i][1] = tv[i][0]; tii[i][1] = tii[i][0];
                                tv[i][0] = d2;       tii[i][0] = col;
                            } else if (b1c) {
                                tv[i][2] = tv[i][1]; tii[i][2] = tii[i][1];
                                tv[i][1] = d2;       tii[i][1] = col;
                            } else { tv[i][2] = d2; tii[i][2] = col; }
                        }
                    }
                }
            }
        }

        __syncthreads();
        if (act) {
#pragma unroll
            for (int i = 0; i < 8; ++i)
#pragma unroll
                for (int q = 0; q < 3; ++q) {
                    mv[(ty * 8 + i) * 48 + tx * 3 + q] = tv[i][q];
                    mi[(ty * 8 + i) * 48 + tx * 3 + q] = tii[i][q];
                }
        }
        __syncthreads();
        if (tid < 64) {
            float w0 = FLT_MAX, w1 = FLT_MAX, w2 = FLT_MAX;
            int   j0 = 0x7fffffff, j1 = 0x7fffffff, j2 = 0x7fffffff;
            for (int cnd = 0; cnd < 48; ++cnd) {
                float d = mv[tid * 48 + cnd];
                int   ix = mi[tid * 48 + cnd];
                bool b2c = (d < w2) || (d == w2 && ix < j2);
                if (b2c) {
                    bool b1c = (d < w1) || (d == w1 && ix < j1);
                    bool b0c = (d < w0) || (d == w0 && ix < j0);
                    if (b0c)      { w2 = w1; j2 = j1; w1 = w0; j1 = j0; w0 = d; j0 = ix; }
                    else if (b1c) { w2 = w1; j2 = j1; w1 = d; j1 = ix; }
                    else          { w2 = d;  j2 = ix; }
                }
            }
            g_neg[rh + tid] = j2;
        }
        __syncthreads();
    }
#endif
}

// ============================================================
// Kernel 2: per-row triplet loss (one warp per row, fp32 exact)
// ============================================================
__global__ __launch_bounds__(256) void rowloss_kernel(const float* __restrict__ X,
                                                      const float* __restrict__ P) {
    int warp = threadIdx.x >> 5;
    int lane = threadIdx.x & 31;
    int row = blockIdx.x * 8 + warp;
    const float4* xr = (const float4*)(X + (size_t)row * DIM);
    const float4* pr = (const float4*)(P + (size_t)row * DIM);
    const float4* nr = (const float4*)(X + (size_t)g_neg[row] * DIM);
    float sap = 0.f, san = 0.f;
#pragma unroll
    for (int i = 0; i < 4; ++i) {
        float4 x = xr[lane + 32 * i];
        float4 p = pr[lane + 32 * i];
        float4 v = nr[lane + 32 * i];
        float d;
        d = x.x - p.x + EPSV; sap += d * d;
        d = x.y - p.y + EPSV; sap += d * d;
        d = x.z - p.z + EPSV; sap += d * d;
        d = x.w - p.w + EPSV; sap += d * d;
        d = x.x - v.x + EPSV; san += d * d;
        d = x.y - v.y + EPSV; san += d * d;
        d = x.z - v.z + EPSV; san += d * d;
        d = x.w - v.w + EPSV; san += d * d;
    }
#pragma unroll
    for (int o = 16; o > 0; o >>= 1) {
        sap += __shfl_down_sync(0xffffffffu, sap, o);
        san += __shfl_down_sync(0xffffffffu, san, o);
    }
    if (lane == 0)
        g_rowloss[row] = fmaxf(sqrtf(sap) - sqrtf(san) + MARGIN, 0.f);
}

// ============================================================
// Kernel 3: mean reduction -> d_out[0]
// ============================================================
__global__ __launch_bounds__(512) void reduce_kernel(float* __restrict__ out) {
    int t = threadIdx.x;
    float s = 0.f;
    for (int i = t; i < NROW; i += 512) s += g_rowloss[i];
#pragma unroll
    for (int o = 16; o > 0; o >>= 1) s += __shfl_down_sync(0xffffffffu, s, o);
    __shared__ float ws[16];
    if ((t & 31) == 0) ws[t >> 5] = s;
    __syncthreads();
    if (t == 0) {
        float tot = 0.f;
#pragma unroll
        for (int w = 0; w < 16; ++w) tot += ws[w];
        out[0] = tot / (float)NROW;
    }
}

extern "C" void kernel_launch(void* const* d_in, const int* in_sizes, int n_in,
                              void* d_out, int out_size) {
    const float* X = (const float*)d_in[0];   // inputs  [16384, 512] f32
    const float* P = (const float*)d_in[1];   // positive[16384, 512] f32
    float* out = (float*)d_out;

    cudaFuncSetAttribute(mma_topk_kernel,
                         cudaFuncAttributeMaxDynamicSharedMemorySize, SMEM_TOTAL);

    cvtsq_kernel<<<NROW, 128>>>(X);
    mma_topk_kernel<<<128, THREADS, SMEM_TOTAL>>>();
    rowloss_kernel<<<NROW / 8, 256>>>(X, P);
    reduce_kernel<<<1, 512>>>(out);
}

// round 12
// speedup vs baseline: 1.4270x; 1.1230x over previous
#include <cuda_runtime.h>
#include <cuda_bf16.h>
#include <math.h>
#include <float.h>
#include <stdint.h>

#define NROW 16384
#define DIM  512
#define MARGIN 2.0f
#define EPSV 1e-6f

#if defined(__CUDA_ARCH_FEAT_SM103_ALL) || (defined(__CUDA_ARCH_SPECIFIC__) && (__CUDA_ARCH_SPECIFIC__ == 1030))
#define HAS_TCGEN05 1
#else
#define HAS_TCGEN05 0
#endif

// ---- device scratch ----
__device__ __align__(16) float g_sq[NROW];
__device__ int   g_neg[NROW];
__device__ float g_rowloss[NROW];
// bf16 PRE-SWIZZLED as 512 tiles of 32 rows x 512 K = 32KB each (SW128 image)
__device__ __align__(256) uint32_t g_xb[NROW * DIM / 2];
// linear bf16x2 copy (A fill + SIMT fallback)
__device__ __align__(16) uint32_t g_xb16[NROW * DIM / 2];

// SMEM layout
#define SMEM_TPTR   0
#define SMEM_FULL0  8            // 3 mbarriers (own B ring complete_tx)
#define SMEM_DONE0  32           // 4 mbarriers (MMA commit, multicast to both)
#define SMEM_DFREE0 64           // 4 mbarriers (own epilogue done with D slot)
#define SMEM_READY0 96           // 4 mbarriers (leader: follower tile-ready)
#define SMEM_SQF0   128          // 8 mbarriers (sq ring complete_tx)
#define SMEM_SQS    1024         // 8 slots x 256B -> ends 3072
#define SMEM_A      3072         // 128 rows x 512 bf16 SW128 -> ends 134144
#define SMEM_B      134144       // 3 x 32768 -> ends 232448
#define SMEM_TOTAL  232448       // 227KB

#define TMEM_D 0                 // 4 x 64 cols f32 (own 128 rows)

#define NTILE 256
#define THREADS 160              // w0 = producer(+MMA on leader), w1-4 = epilogue

#if HAS_TCGEN05
__device__ __forceinline__ uint32_t elect_one() {
    uint32_t p;
    asm volatile("{\n\t.reg .pred p;\n\telect.sync _|p, 0xFFFFFFFF;\n\tselp.b32 %0, 1, 0, p;\n\t}" : "=r"(p));
    return p;
}
#define TCGEN05_ALLOC_CG2(dst, n) \
    asm volatile("tcgen05.alloc.cta_group::2.sync.aligned.shared::cta.b32 [%0], %1;" :: "r"(dst), "r"(n) : "memory")
#define TCGEN05_DEALLOC_CG2(t, n) \
    asm volatile("tcgen05.dealloc.cta_group::2.sync.aligned.b32 %0, %1;" :: "r"(t), "r"(n))
#define TCGEN05_RELINQ_CG2() \
    asm volatile("tcgen05.relinquish_alloc_permit.cta_group::2.sync.aligned;")
#define TCGEN05_WAIT_LD() asm volatile("tcgen05.wait::ld.sync.aligned;" ::: "memory")
#define TCGEN05_FENCE_BEFORE() asm volatile("tcgen05.fence::before_thread_sync;" ::: "memory")
#define TCGEN05_FENCE_AFTER()  asm volatile("tcgen05.fence::after_thread_sync;" ::: "memory")
#define FENCE_PROXY_ASYNC() asm volatile("fence.proxy.async;" ::: "memory")
#define MBARRIER_INIT(m, c) \
    asm volatile("mbarrier.init.shared.b64 [%0], %1;" :: "r"(m), "r"(c) : "memory")
#define MBARRIER_ARRIVE(m) \
    asm volatile("mbarrier.arrive.release.cta.shared.b64 _, [%0];" :: "r"(m) : "memory")
#define MBARRIER_EXPECT_TX(m, b) \
    asm volatile("mbarrier.arrive.expect_tx.shared.b64 _, [%0], %1;" :: "r"(m), "r"(b) : "memory")
#define MBARRIER_ARRIVE_LEADER(local_addr) \
    asm volatile("{\n\t.reg .b32 rA;\n\t.reg .b32 z;\n\tmov.b32 z, 0;\n\t" \
        "mapa.shared::cluster.u32 rA, %0, z;\n\t" \
        "mbarrier.arrive.release.cluster.shared::cluster.b64 _, [rA];\n\t}" \
        :: "r"((uint32_t)(local_addr)) : "memory")
#define TCGEN05_COMMIT_MC_CG2(m) \
    asm volatile("tcgen05.commit.cta_group::2.mbarrier::arrive::one.shared::cluster.multicast::cluster.b64 [%0], %1;" \
        :: "r"(m), "h"((uint16_t)3) : "memory")
#define CLUSTER_SYNC() do { \
    asm volatile("barrier.cluster.arrive.aligned;" ::: "memory"); \
    asm volatile("barrier.cluster.wait.aligned;" ::: "memory"); \
} while (0)

#define MBARRIER_WAIT_PARITY(mbar_smem_addr, phase_parity) do { \
    uint32_t _mbar = (uint32_t)(mbar_smem_addr); \
    uint32_t _parity = (uint32_t)(phase_parity); \
    uint32_t _done; \
    asm volatile("{\n\t.reg .pred p;\n\t" \
        "mbarrier.try_wait.parity.acquire.cta.shared::cta.b64 p, [%1], %2;\n\t" \
        "selp.b32 %0, 1, 0, p;\n\t}" : "=r"(_done) : "r"(_mbar), "r"(_parity) : "memory"); \
    if (!_done) { \
        asm volatile("{\n\t.reg .pred P1;\n\t" \
            "WAIT_LOOP_%=:\n\t" \
            "mbarrier.try_wait.parity.acquire.cta.shared::cta.b64 P1, [%0], %1, 0x989680;\n\t" \
            "@P1 bra.uni WAIT_DONE_%=;\n\t" \
            "bra.uni WAIT_LOOP_%=;\n\t" \
            "WAIT_DONE_%=:\n\t}" :: "r"(_mbar), "r"(_parity) : "memory"); \
    } \
} while (0)

#define MBARRIER_WAIT_PARITY_CL(mbar_smem_addr, phase_parity) do { \
    uint32_t _mbar = (uint32_t)(mbar_smem_addr); \
    uint32_t _parity = (uint32_t)(phase_parity); \
    uint32_t _done; \
    asm volatile("{\n\t.reg .pred p;\n\t" \
        "mbarrier.try_wait.parity.acquire.cluster.shared::cta.b64 p, [%1], %2;\n\t" \
        "selp.b32 %0, 1, 0, p;\n\t}" : "=r"(_done) : "r"(_mbar), "r"(_parity) : "memory"); \
    if (!_done) { \
        asm volatile("{\n\t.reg .pred P1;\n\t" \
            "WAIT_LOOP_%=:\n\t" \
            "mbarrier.try_wait.parity.acquire.cluster.shared::cta.b64 P1, [%0], %1, 0x989680;\n\t" \
            "@P1 bra.uni WAIT_DONE_%=;\n\t" \
            "bra.uni WAIT_LOOP_%=;\n\t" \
            "WAIT_DONE_%=:\n\t}" :: "r"(_mbar), "r"(_parity) : "memory"); \
    } \
} while (0)

#define TCGEN05_LD_X32(r, tmem_addr) \
    asm volatile("tcgen05.ld.sync.aligned.32x32b.x32.b32 " \
        "{%0, %1, %2, %3, %4, %5, %6, %7, %8, %9, %10, %11, %12, %13, %14, %15, " \
        "%16, %17, %18, %19, %20, %21, %22, %23, %24, %25, %26, %27, %28, %29, %30, %31}, [%32];" \
        : "=r"((r)[0]),"=r"((r)[1]),"=r"((r)[2]),"=r"((r)[3]),"=r"((r)[4]),"=r"((r)[5]),"=r"((r)[6]),"=r"((r)[7]), \
          "=r"((r)[8]),"=r"((r)[9]),"=r"((r)[10]),"=r"((r)[11]),"=r"((r)[12]),"=r"((r)[13]),"=r"((r)[14]),"=r"((r)[15]), \
          "=r"((r)[16]),"=r"((r)[17]),"=r"((r)[18]),"=r"((r)[19]),"=r"((r)[20]),"=r"((r)[21]),"=r"((r)[22]),"=r"((r)[23]), \
          "=r"((r)[24]),"=r"((r)[25]),"=r"((r)[26]),"=r"((r)[27]),"=r"((r)[28]),"=r"((r)[29]),"=r"((r)[30]),"=r"((r)[31]) \
        : "r"(tmem_addr))

__device__ __forceinline__ void bulk_g2s(uint32_t dst, const void* src, uint32_t bytes, uint32_t mbar) {
    asm volatile("cp.async.bulk.shared::cta.global.mbarrier::complete_tx::bytes [%0], [%1], %2, [%3];"
                 :: "r"(dst), "l"(src), "r"(bytes), "r"(mbar) : "memory");
}

// cg2 SS-mode bf16 MMA
__device__ __forceinline__ void mma_f16_ss_cg2(uint32_t d_tmem, uint64_t a_desc,
                                               uint64_t b_desc, uint32_t idesc, bool acc) {
    uint32_t en = acc ? 1u : 0u;
    asm volatile("{\n\t.reg .pred p;\n\tsetp.ne.u32 p, %5, 0;\n\t"
        "tcgen05.mma.cta_group::2.kind::f16 [%0], %1, %2, %3, "
        "{%4, %4, %4, %4, %4, %4, %4, %4}, p;\n\t}"
        :: "r"(d_tmem), "l"(a_desc), "l"(b_desc), "r"(idesc), "r"(0u), "r"(en)
        : "memory");
}

__device__ __forceinline__ uint64_t make_desc(uint32_t addr) {
    return (uint64_t(2) << 61) | (uint64_t(1) << 46) | (uint64_t(64) << 32)
         | (uint64_t(1) << 16) | ((addr >> 4) & 0x3FFF);
}

// idesc: F32 accum, bf16 A/B, M=256 (16<<24), N=64 (8<<17)
#define MMA_IDESC ((16u << 24) | (8u << 17) | (1u << 10) | (1u << 7) | (1u << 4))
#endif  // HAS_TCGEN05

__device__ __forceinline__ uint32_t smem_u32(const void* p) {
    uint32_t a;
    asm("{ .reg .u64 t; cvta.to.shared.u64 t, %1; cvt.u32.u64 %0, t; }" : "=r"(a) : "l"(p));
    return a;
}

// ============================================================
// Kernel 0: fp32 -> {pre-swizzled 32-row bf16 tiles, linear bf16x2}
//           + exact fp32 row norms
// ============================================================
__global__ __launch_bounds__(128) void cvtsq_kernel(const float* __restrict__ X) {
    int row = blockIdx.x;
    int t = threadIdx.x;
    float4 v = *(const float4*)(X + (size_t)row * DIM + t * 4);
    uint32_t lo, hi;
    asm("cvt.rn.bf16x2.f32 %0, %1, %2;" : "=r"(lo) : "f"(v.y), "f"(v.x));
    asm("cvt.rn.bf16x2.f32 %0, %1, %2;" : "=r"(hi) : "f"(v.w), "f"(v.z));
    *(uint2*)(g_xb16 + (size_t)row * 256 + t * 2) = make_uint2(lo, hi);
    int tile = row >> 5, r = row & 31;
    int k = t * 4;
    uint32_t bo = (uint32_t)(r * 128 + (k & 63) * 2);
    uint32_t sw = bo ^ ((bo >> 3) & 0x70);
    *(uint2*)((char*)g_xb + (size_t)tile * 32768 + (size_t)(k >> 6) * 4096 + sw)
        = make_uint2(lo, hi);
    float s = v.x * v.x + v.y * v.y + v.z * v.z + v.w * v.w;
#pragma unroll
    for (int o = 16; o > 0; o >>= 1) s += __shfl_down_sync(0xffffffffu, s, o);
    __shared__ float ws[4];
    if ((t & 31) == 0) ws[t >> 5] = s;
    __syncthreads();
    if (t == 0) g_sq[row] = ws[0] + ws[1] + ws[2] + ws[3];
}

// ============================================================
// Kernel 1: cg2 bf16 SS GEMM, 4-deep TMEM D ring, decoupled handshake.
// 64 clusters x 2 CTAs x 160 threads. Per 64-col tile u:
//   both producers: wait own full(u%3) [B half landed], own dfree(u-4);
//   follower: arrive leader ready[u&3] (slack 0; leader consumes at u);
//   leader: wait ready[u&3], issue 32 cg2 MMAs -> D slot u&3 (both CTAs),
//           commit multicast -> done[u&3] on both.
//   both: recycle B(u+2) -> slot (u+2)%3 after done(u-1); sq(u+2).
//   epilogue (w1-4, both CTAs): wait done[u&3] -> LDTM own 128x64 ->
//           min-screen top-3 -> arrive dfree[u&3].
// 4-deep D lets the cluster handshake hide under ~4 tiles of MMA.
// ============================================================
__global__ __launch_bounds__(THREADS, 1) __cluster_dims__(2, 1, 1)
void mma_topk_kernel() {
    extern __shared__ char smem[];
    const uint32_t smem_base = smem_u32(smem);
    const int tid = threadIdx.x;
    const int rowBase = blockIdx.x * 128;

#if HAS_TCGEN05
    const char* xb = (const char*)g_xb;
    const int wid = tid >> 5;
    const int lane = tid & 31;
    const bool is_prod = (wid == 0);
    const int rank = blockIdx.x & 1;
    const int smsp = wid & 3;
    const int row = smsp * 32 + lane;

    if (is_prod) {
        TCGEN05_ALLOC_CG2(smem_base + SMEM_TPTR, 256);
        TCGEN05_RELINQ_CG2();
    }
    if (tid == 0) {
#pragma unroll
        for (int s = 0; s < 3; ++s) MBARRIER_INIT(smem_base + SMEM_FULL0 + s * 8, 1);
#pragma unroll
        for (int s = 0; s < 4; ++s) {
            MBARRIER_INIT(smem_base + SMEM_DONE0 + s * 8, 1);
            MBARRIER_INIT(smem_base + SMEM_DFREE0 + s * 8, 4);
            MBARRIER_INIT(smem_base + SMEM_READY0 + s * 8, 1);
        }
#pragma unroll
        for (int s = 0; s < 8; ++s) MBARRIER_INIT(smem_base + SMEM_SQF0 + s * 8, 1);
    }
    __syncthreads();
    uint32_t tmem_base;
    asm volatile("ld.shared.b32 %0, [%1];" : "=r"(tmem_base) : "r"(smem_base + SMEM_TPTR));

    // ---- A fill: own 128 rows x 512 bf16 into SMEM_A (SW128, 8 slabs x 16KB) ----
    for (int f = tid; f < 8192; f += THREADS) {
        int r = f >> 6, g = f & 63;
        uint4 v = *(const uint4*)(g_xb16 + (size_t)(rowBase + r) * 256 + g * 4);
        uint32_t bo = (uint32_t)(r * 128 + (g & 7) * 16);
        uint32_t sw = bo ^ ((bo >> 3) & 0x70);
        *(uint4*)(smem + SMEM_A + (size_t)(g >> 3) * 16384 + sw) = v;
    }
    FENCE_PROXY_ASYNC();
    __syncthreads();
    CLUSTER_SYNC();   // mbarriers + A visible cluster-wide

    // ---- prologue: bulk B tiles 0,1 (own half) + sq 0,1 ----
    if (is_prod && elect_one()) {
#pragma unroll
        for (int pt = 0; pt < 2; ++pt) {
            uint32_t fb = smem_base + SMEM_FULL0 + pt * 8;
            MBARRIER_EXPECT_TX(fb, 32768);
            bulk_g2s(smem_base + SMEM_B + pt * 32768,
                     xb + (size_t)(2 * pt + rank) * 32768, 32768, fb);
            uint32_t qb = smem_base + SMEM_SQF0 + pt * 8;
            MBARRIER_EXPECT_TX(qb, 256);
            bulk_g2s(smem_base + SMEM_SQS + pt * 256, (const char*)g_sq + pt * 256, 256, qb);
        }
    }

    if (is_prod) {
        const uint64_t adesc0 = make_desc(smem_base + SMEM_A);
        for (int u = 0; u < NTILE; ++u) {
            const int ds = u & 3;
            // own B half landed
            MBARRIER_WAIT_PARITY(smem_base + SMEM_FULL0 + (u % 3) * 8, (u / 3) & 1);
            // D slot WAR: own epilogue done with tile u-4
            if (u >= 4)
                MBARRIER_WAIT_PARITY(smem_base + SMEM_DFREE0 + ds * 8, ((u - 4) >> 2) & 1);

            if (rank == 1) {
                // signal leader: this CTA ready for tile u
                TCGEN05_FENCE_AFTER();
                if (elect_one())
                    MBARRIER_ARRIVE_LEADER(smem_base + SMEM_READY0 + ds * 8);
            } else {
                MBARRIER_WAIT_PARITY_CL(smem_base + SMEM_READY0 + ds * 8, (u >> 2) & 1);
                TCGEN05_FENCE_AFTER();
                if (elect_one()) {
                    uint64_t bdesc = make_desc(smem_base + SMEM_B + (u % 3) * 32768);
                    uint32_t dtm = tmem_base + TMEM_D + ds * 64;
#pragma unroll
                    for (int c = 0; c < 32; ++c) {
                        uint64_t boff = (uint64_t)((c >> 2) * 256 + (c & 3) * 2);
                        uint64_t aoff = (uint64_t)((c >> 2) * 1024 + (c & 3) * 2);
                        mma_f16_ss_cg2(dtm, adesc0 + aoff, bdesc + boff, MMA_IDESC, c > 0);
                    }
                    TCGEN05_COMMIT_MC_CG2(smem_base + SMEM_DONE0 + ds * 8);
                }
            }

            // recycle: B(u+2) -> slot (u+2)%3 (last read by MMA(u-1) -> done(u-1))
            if (u + 2 < NTILE) {
                if (u >= 1)
                    MBARRIER_WAIT_PARITY(smem_base + SMEM_DONE0 + ((u - 1) & 3) * 8,
                                         ((u - 1) >> 2) & 1);
                if (elect_one()) {
                    int s2 = (u + 2) % 3;
                    uint32_t fb = smem_base + SMEM_FULL0 + s2 * 8;
                    MBARRIER_EXPECT_TX(fb, 32768);
                    bulk_g2s(smem_base + SMEM_B + s2 * 32768,
                             xb + (size_t)(2 * (u + 2) + rank) * 32768, 32768, fb);
                    int q2 = (u + 2) & 7;
                    uint32_t qb = smem_base + SMEM_SQF0 + q2 * 8;
                    MBARRIER_EXPECT_TX(qb, 256);
                    bulk_g2s(smem_base + SMEM_SQS + q2 * 256,
                             (const char*)g_sq + (size_t)(u + 2) * 256, 256, qb);
                }
            }
        }
    } else {
        // ---- epilogue warps: per-thread (one row) top-3 over all tiles ----
        float v0 = FLT_MAX, v1 = FLT_MAX, v2 = FLT_MAX;
        int   i0 = 0, i1 = 0, i2 = 0;
        for (int u = 0; u < NTILE; ++u) {
            const int ds = u & 3;
            MBARRIER_WAIT_PARITY(smem_base + SMEM_DONE0 + ds * 8, (u >> 2) & 1);
            TCGEN05_FENCE_AFTER();
            MBARRIER_WAIT_PARITY(smem_base + SMEM_SQF0 + (u & 7) * 8, (u >> 3) & 1);
            const float* sqt = (const float*)(smem + SMEM_SQS + (u & 7) * 256);
            const int colBase = u * 64;
            const uint32_t dtm = tmem_base + TMEM_D + ds * 64;
            uint32_t dr[64];
            TCGEN05_LD_X32(dr, dtm);
            TCGEN05_LD_X32(dr + 32, dtm + 32);
            TCGEN05_WAIT_LD();
#pragma unroll
            for (int g = 0; g < 4; ++g) {
                float key[16];
#pragma unroll
                for (int c = 0; c < 16; ++c)
                    key[c] = fmaf(-2.f, __uint_as_float(dr[g * 16 + c]), sqt[g * 16 + c]);
                float t8[8];
#pragma unroll
                for (int c = 0; c < 8; ++c) t8[c] = fminf(key[c], key[c + 8]);
                float t4a = fminf(t8[0], t8[4]), t4b = fminf(t8[1], t8[5]);
                float t4c = fminf(t8[2], t8[6]), t4d = fminf(t8[3], t8[7]);
                float mn = fminf(fminf(t4a, t4b), fminf(t4c, t4d));
                if (mn < v2) {   // rare: exact ordered insert, ascending cols
#pragma unroll
                    for (int c = 0; c < 16; ++c) {
                        float k = key[c];
                        int col = colBase + g * 16 + c;
                        if (k < v2) {
                            if (k < v1) {
                                v2 = v1; i2 = i1;
                                if (k < v0) { v1 = v0; i1 = i0; v0 = k; i0 = col; }
                                else        { v1 = k; i1 = col; }
                            } else { v2 = k; i2 = col; }
                        }
                    }
                }
            }
            TCGEN05_FENCE_BEFORE();
            if (lane == 0) MBARRIER_ARRIVE(smem_base + SMEM_DFREE0 + ds * 8);
        }
        g_neg[rowBase + row] = i2;
    }

    __syncthreads();
    CLUSTER_SYNC();   // peer MMA done reading my SMEM before teardown
    if (is_prod) TCGEN05_DEALLOC_CG2(tmem_base, 256);
    CLUSTER_SYNC();

#else  // ---------------- SIMT fallback (non-'a' pass) ----------------
    float* As = (float*)(smem);
    float* Bs = (float*)(smem + 4096);
    float* mv = (float*)(smem + 12288);
    int*   mi = (int*)(smem + 36864);
    const int tx = tid & 15, ty = tid >> 4;
    const bool act = (tid < 128);

    for (int half = 0; half < 2; ++half) {
        const int rh = rowBase + half * 64;
        float tv[8][3]; int tii[8][3];
#pragma unroll
        for (int i = 0; i < 8; ++i)
#pragma unroll
            for (int q = 0; q < 3; ++q) { tv[i][q] = FLT_MAX; tii[i][q] = 0x7fffffff; }

        for (int jt = 0; jt < NROW / 128; ++jt) {
            const int colBase = jt * 128;
            float c[8][8];
#pragma unroll
            for (int i = 0; i < 8; ++i)
#pragma unroll
                for (int j = 0; j < 8; ++j) c[i][j] = 0.f;

            for (int kt = 0; kt < DIM; kt += 16) {
                __syncthreads();
                if (act) {
#pragma unroll
                    for (int l = 0; l < 4; ++l) {
                        int f = tid + l * 128;
                        int r = f >> 3, uu = f & 7;
                        uint32_t w = g_xb16[(size_t)(rh + r) * 256 + kt / 2 + uu];
                        __nv_bfloat162 b2 = *(__nv_bfloat162*)&w;
                        float2 f2 = __bfloat1622float2(b2);
                        As[(2 * uu + 0) * 64 + r] = f2.x;
                        As[(2 * uu + 1) * 64 + r] = f2.y;
                    }
#pragma unroll
                    for (int l = 0; l < 8; ++l) {
                        int f = tid + l * 128;
                        int r = f >> 3, uu = f & 7;
                        uint32_t w = g_xb16[(size_t)(colBase + r) * 256 + kt / 2 + uu];
                        __nv_bfloat162 b2 = *(__nv_bfloat162*)&w;
                        float2 f2 = __bfloat1622float2(b2);
                        Bs[(2 * uu + 0) * 128 + r] = f2.x;
                        Bs[(2 * uu + 1) * 128 + r] = f2.y;
                    }
                }
                __syncthreads();
                if (act) {
#pragma unroll
                    for (int kk = 0; kk < 16; ++kk) {
                        float a[8], b[8];
#pragma unroll
                        for (int i = 0; i < 8; ++i) a[i] = As[kk * 64 + ty * 8 + i];
#pragma unroll
                        for (int j = 0; j < 8; ++j) b[j] = Bs[kk * 128 + tx * 8 + j];
#pragma unroll
                        for (int i = 0; i < 8; ++i)
#pragma unroll
                            for (int j = 0; j < 8; ++j) c[i][j] += a[i] * b[j];
                    }
                }
            }
            if (act) {
#pragma unroll
                for (int j = 0; j < 8; ++j) {
                    int col = colBase + tx * 8 + j;
                    float sqc = g_sq[col];
#pragma unroll
                    for (int i = 0; i < 8; ++i) {
                        float d2 = fmaf(-2.f, c[i][j], sqc);
                        bool b2c = (d2 < tv[i][2]) || (d2 == tv[i][2] && col < tii[i][2]);
                        if (b2c) {
                            bool b1c = (d2 < tv[i][1]) || (d2 == tv[i][1] && col < tii[i][1]);
                            bool b0c = (d2 < tv[i][0]) || (d2 == tv[i][0] && col < tii[i][0]);
                            if (b0c) {
                                tv[i][2] = tv[i][1]; tii[i][2] = tii[i][1];
                                tv[i][1] = tv[i][0]; tii[i][1] = tii[i][0];
                                tv[i][0] = d2;       tii[i][0] = col;
                            } else if (b1c) {
                                tv[i][2] = tv[i][1]; tii[i][2] = tii[i][1];
                                tv[i][1] = d2;       tii[i][1] = col;
                            } else { tv[i][2] = d2; tii[i][2] = col; }
                        }
                    }
                }
            }
        }

        __syncthreads();
        if (act) {
#pragma unroll
            for (int i = 0; i < 8; ++i)
#pragma unroll
                for (int q = 0; q < 3; ++q) {
                    mv[(ty * 8 + i) * 48 + tx * 3 + q] = tv[i][q];
                    mi[(ty * 8 + i) * 48 + tx * 3 + q] = tii[i][q];
                }
        }
        __syncthreads();
        if (tid < 64) {
            float w0 = FLT_MAX, w1 = FLT_MAX, w2 = FLT_MAX;
            int   j0 = 0x7fffffff, j1 = 0x7fffffff, j2 = 0x7fffffff;
            for (int cnd = 0; cnd < 48; ++cnd) {
                float d = mv[tid * 48 + cnd];
                int   ix = mi[tid * 48 + cnd];
                bool b2c = (d < w2) || (d == w2 && ix < j2);
                if (b2c) {
                    bool b1c = (d < w1) || (d == w1 && ix < j1);
                    bool b0c = (d < w0) || (d == w0 && ix < j0);
                    if (b0c)      { w2 = w1; j2 = j1; w1 = w0; j1 = j0; w0 = d; j0 = ix; }
                    else if (b1c) { w2 = w1; j2 = j1; w1 = d; j1 = ix; }
                    else          { w2 = d;  j2 = ix; }
                }
            }
            g_neg[rh + tid] = j2;
        }
        __syncthreads();
    }
#endif
}

// ============================================================
// Kernel 2: per-row triplet loss (one warp per row, fp32 exact)
// ============================================================
__global__ __launch_bounds__(256) void rowloss_kernel(const float* __restrict__ X,
                                                      const float* __restrict__ P) {
    int warp = threadIdx.x >> 5;
    int lane = threadIdx.x & 31;
    int row = blockIdx.x * 8 + warp;
    const float4* xr = (const float4*)(X + (size_t)row * DIM);
    const float4* pr = (const float4*)(P + (size_t)row * DIM);
    const float4* nr = (const float4*)(X + (size_t)g_neg[row] * DIM);
    float sap = 0.f, san = 0.f;
#pragma unroll
    for (int i = 0; i < 4; ++i) {
        float4 x = xr[lane + 32 * i];
        float4 p = pr[lane + 32 * i];
        float4 v = nr[lane + 32 * i];
        float d;
        d = x.x - p.x + EPSV; sap += d * d;
        d = x.y - p.y + EPSV; sap += d * d;
        d = x.z - p.z + EPSV; sap += d * d;
        d = x.w - p.w + EPSV; sap += d * d;
        d = x.x - v.x + EPSV; san += d * d;
        d = x.y - v.y + EPSV; san += d * d;
        d = x.z - v.z + EPSV; san += d * d;
        d = x.w - v.w + EPSV; san += d * d;
    }
#pragma unroll
    for (int o = 16; o > 0; o >>= 1) {
        sap += __shfl_down_sync(0xffffffffu, sap, o);
        san += __shfl_down_sync(0xffffffffu, san, o);
    }
    if (lane == 0)
        g_rowloss[row] = fmaxf(sqrtf(sap) - sqrtf(san) + MARGIN, 0.f);
}

// ============================================================
// Kernel 3: mean reduction -> d_out[0]
// ============================================================
__global__ __launch_bounds__(512) void reduce_kernel(float* __restrict__ out) {
    int t = threadIdx.x;
    float s = 0.f;
    for (int i = t; i < NROW; i += 512) s += g_rowloss[i];
#pragma unroll
    for (int o = 16; o > 0; o >>= 1) s += __shfl_down_sync(0xffffffffu, s, o);
    __shared__ float ws[16];
    if ((t & 31) == 0) ws[t >> 5] = s;
    __syncthreads();
    if (t == 0) {
        float tot = 0.f;
#pragma unroll
        for (int w = 0; w < 16; ++w) tot += ws[w];
        out[0] = tot / (float)NROW;
    }
}

extern "C" void kernel_launch(void* const* d_in, const int* in_sizes, int n_in,
                              void* d_out, int out_size) {
    const float* X = (const float*)d_in[0];   // inputs  [16384, 512] f32
    const float* P = (const float*)d_in[1];   // positive[16384, 512] f32
    float* out = (float*)d_out;

    cudaFuncSetAttribute(mma_topk_kernel,
                         cudaFuncAttributeMaxDynamicSharedMemorySize, SMEM_TOTAL);

    cvtsq_kernel<<<NROW, 128>>>(X);
    mma_topk_kernel<<<128, THREADS, SMEM_TOTAL>>>();
    rowloss_kernel<<<NROW / 8, 256>>>(X, P);
    reduce_kernel<<<1, 512>>>(out);
}

// round 13
// speedup vs baseline: 1.4680x; 1.0287x over previous
#include <cuda_runtime.h>
#include <cuda_bf16.h>
#include <math.h>
#include <float.h>
#include <stdint.h>

#define NROW 16384
#define DIM  512
#define MARGIN 2.0f
#define EPSV 1e-6f

#if defined(__CUDA_ARCH_FEAT_SM103_ALL) || (defined(__CUDA_ARCH_SPECIFIC__) && (__CUDA_ARCH_SPECIFIC__ == 1030))
#define HAS_TCGEN05 1
#else
#define HAS_TCGEN05 0
#endif

// ---- device scratch ----
__device__ __align__(16) float g_sq[NROW];
__device__ int   g_neg[NROW];
__device__ float g_rowloss[NROW];
// bf16 PRE-SWIZZLED as 512 tiles of 32 rows x 512 K = 32KB each (SW128 image)
__device__ __align__(256) uint32_t g_xb[NROW * DIM / 2];
// linear bf16x2 copy (A fill + SIMT fallback)
__device__ __align__(16) uint32_t g_xb16[NROW * DIM / 2];

// SMEM layout (no A tile needed: A lives in TMEM)
#define SMEM_TPTR   0
#define SMEM_FULL0  8            // 3 mbarriers (own B ring complete_tx)
#define SMEM_DONE0  32           // 4 mbarriers (MMA commit, multicast to both)
#define SMEM_DFREE0 64           // 4 mbarriers (own epilogue done with D slot)
#define SMEM_READY0 96           // 4 mbarriers (leader: follower tile-ready)
#define SMEM_SQF0   128          // 8 mbarriers (sq ring complete_tx)
#define SMEM_SQS    1024         // 8 slots x 256B -> ends 3072
#define SMEM_B      3072         // 3 x 32768 -> ends 101376
#define SMEM_TOTAL  101376

#define TMEM_A 0                 // 256 cols: own 128 rows x 512 bf16
#define TMEM_D 256               // 4 x 64 cols f32

#define NTILE 256
#define THREADS 160              // w0 = producer(+MMA on leader), w1-4 = epilogue

#if HAS_TCGEN05
__device__ __forceinline__ uint32_t elect_one() {
    uint32_t p;
    asm volatile("{\n\t.reg .pred p;\n\telect.sync _|p, 0xFFFFFFFF;\n\tselp.b32 %0, 1, 0, p;\n\t}" : "=r"(p));
    return p;
}
#define TCGEN05_ALLOC_CG2(dst, n) \
    asm volatile("tcgen05.alloc.cta_group::2.sync.aligned.shared::cta.b32 [%0], %1;" :: "r"(dst), "r"(n) : "memory")
#define TCGEN05_DEALLOC_CG2(t, n) \
    asm volatile("tcgen05.dealloc.cta_group::2.sync.aligned.b32 %0, %1;" :: "r"(t), "r"(n))
#define TCGEN05_RELINQ_CG2() \
    asm volatile("tcgen05.relinquish_alloc_permit.cta_group::2.sync.aligned;")
#define TCGEN05_WAIT_ST() asm volatile("tcgen05.wait::st.sync.aligned;" ::: "memory")
#define TCGEN05_WAIT_LD() asm volatile("tcgen05.wait::ld.sync.aligned;" ::: "memory")
#define TCGEN05_FENCE_BEFORE() asm volatile("tcgen05.fence::before_thread_sync;" ::: "memory")
#define TCGEN05_FENCE_AFTER()  asm volatile("tcgen05.fence::after_thread_sync;" ::: "memory")
#define FENCE_PROXY_ASYNC() asm volatile("fence.proxy.async;" ::: "memory")
#define MBARRIER_INIT(m, c) \
    asm volatile("mbarrier.init.shared.b64 [%0], %1;" :: "r"(m), "r"(c) : "memory")
#define MBARRIER_ARRIVE(m) \
    asm volatile("mbarrier.arrive.release.cta.shared.b64 _, [%0];" :: "r"(m) : "memory")
#define MBARRIER_EXPECT_TX(m, b) \
    asm volatile("mbarrier.arrive.expect_tx.shared.b64 _, [%0], %1;" :: "r"(m), "r"(b) : "memory")
#define MBARRIER_ARRIVE_LEADER(local_addr) \
    asm volatile("{\n\t.reg .b32 rA;\n\t.reg .b32 z;\n\tmov.b32 z, 0;\n\t" \
        "mapa.shared::cluster.u32 rA, %0, z;\n\t" \
        "mbarrier.arrive.release.cluster.shared::cluster.b64 _, [rA];\n\t}" \
        :: "r"((uint32_t)(local_addr)) : "memory")
#define TCGEN05_COMMIT_MC_CG2(m) \
    asm volatile("tcgen05.commit.cta_group::2.mbarrier::arrive::one.shared::cluster.multicast::cluster.b64 [%0], %1;" \
        :: "r"(m), "h"((uint16_t)3) : "memory")
#define CLUSTER_SYNC() do { \
    asm volatile("barrier.cluster.arrive.aligned;" ::: "memory"); \
    asm volatile("barrier.cluster.wait.aligned;" ::: "memory"); \
} while (0)

#define MBARRIER_WAIT_PARITY(mbar_smem_addr, phase_parity) do { \
    uint32_t _mbar = (uint32_t)(mbar_smem_addr); \
    uint32_t _parity = (uint32_t)(phase_parity); \
    uint32_t _done; \
    asm volatile("{\n\t.reg .pred p;\n\t" \
        "mbarrier.try_wait.parity.acquire.cta.shared::cta.b64 p, [%1], %2;\n\t" \
        "selp.b32 %0, 1, 0, p;\n\t}" : "=r"(_done) : "r"(_mbar), "r"(_parity) : "memory"); \
    if (!_done) { \
        asm volatile("{\n\t.reg .pred P1;\n\t" \
            "WAIT_LOOP_%=:\n\t" \
            "mbarrier.try_wait.parity.acquire.cta.shared::cta.b64 P1, [%0], %1, 0x989680;\n\t" \
            "@P1 bra.uni WAIT_DONE_%=;\n\t" \
            "bra.uni WAIT_LOOP_%=;\n\t" \
            "WAIT_DONE_%=:\n\t}" :: "r"(_mbar), "r"(_parity) : "memory"); \
    } \
} while (0)

#define MBARRIER_WAIT_PARITY_CL(mbar_smem_addr, phase_parity) do { \
    uint32_t _mbar = (uint32_t)(mbar_smem_addr); \
    uint32_t _parity = (uint32_t)(phase_parity); \
    uint32_t _done; \
    asm volatile("{\n\t.reg .pred p;\n\t" \
        "mbarrier.try_wait.parity.acquire.cluster.shared::cta.b64 p, [%1], %2;\n\t" \
        "selp.b32 %0, 1, 0, p;\n\t}" : "=r"(_done) : "r"(_mbar), "r"(_parity) : "memory"); \
    if (!_done) { \
        asm volatile("{\n\t.reg .pred P1;\n\t" \
            "WAIT_LOOP_%=:\n\t" \
            "mbarrier.try_wait.parity.acquire.cluster.shared::cta.b64 P1, [%0], %1, 0x989680;\n\t" \
            "@P1 bra.uni WAIT_DONE_%=;\n\t" \
            "bra.uni WAIT_LOOP_%=;\n\t" \
            "WAIT_DONE_%=:\n\t}" :: "r"(_mbar), "r"(_parity) : "memory"); \
    } \
} while (0)

#define TCGEN05_ST_X32(tmem_addr, r) \
    asm volatile("tcgen05.st.sync.aligned.32x32b.x32.b32 [%0], " \
        "{%1, %2, %3, %4, %5, %6, %7, %8, %9, %10, %11, %12, %13, %14, %15, %16, " \
        "%17, %18, %19, %20, %21, %22, %23, %24, %25, %26, %27, %28, %29, %30, %31, %32};" \
        :: "r"(tmem_addr), \
           "r"((r)[0]),"r"((r)[1]),"r"((r)[2]),"r"((r)[3]),"r"((r)[4]),"r"((r)[5]),"r"((r)[6]),"r"((r)[7]), \
           "r"((r)[8]),"r"((r)[9]),"r"((r)[10]),"r"((r)[11]),"r"((r)[12]),"r"((r)[13]),"r"((r)[14]),"r"((r)[15]), \
           "r"((r)[16]),"r"((r)[17]),"r"((r)[18]),"r"((r)[19]),"r"((r)[20]),"r"((r)[21]),"r"((r)[22]),"r"((r)[23]), \
           "r"((r)[24]),"r"((r)[25]),"r"((r)[26]),"r"((r)[27]),"r"((r)[28]),"r"((r)[29]),"r"((r)[30]),"r"((r)[31]) \
        : "memory")

#define TCGEN05_LD_X32(r, tmem_addr) \
    asm volatile("tcgen05.ld.sync.aligned.32x32b.x32.b32 " \
        "{%0, %1, %2, %3, %4, %5, %6, %7, %8, %9, %10, %11, %12, %13, %14, %15, " \
        "%16, %17, %18, %19, %20, %21, %22, %23, %24, %25, %26, %27, %28, %29, %30, %31}, [%32];" \
        : "=r"((r)[0]),"=r"((r)[1]),"=r"((r)[2]),"=r"((r)[3]),"=r"((r)[4]),"=r"((r)[5]),"=r"((r)[6]),"=r"((r)[7]), \
          "=r"((r)[8]),"=r"((r)[9]),"=r"((r)[10]),"=r"((r)[11]),"=r"((r)[12]),"=r"((r)[13]),"=r"((r)[14]),"=r"((r)[15]), \
          "=r"((r)[16]),"=r"((r)[17]),"=r"((r)[18]),"=r"((r)[19]),"=r"((r)[20]),"=r"((r)[21]),"=r"((r)[22]),"=r"((r)[23]), \
          "=r"((r)[24]),"=r"((r)[25]),"=r"((r)[26]),"=r"((r)[27]),"=r"((r)[28]),"=r"((r)[29]),"=r"((r)[30]),"=r"((r)[31]) \
        : "r"(tmem_addr))

__device__ __forceinline__ void bulk_g2s(uint32_t dst, const void* src, uint32_t bytes, uint32_t mbar) {
    asm volatile("cp.async.bulk.shared::cta.global.mbarrier::complete_tx::bytes [%0], [%1], %2, [%3];"
                 :: "r"(dst), "l"(src), "r"(bytes), "r"(mbar) : "memory");
}

// cg2 TS-mode bf16 MMA: A in (each CTA's own) TMEM, B via SMEM descriptor
__device__ __forceinline__ void mma_f16_ts_cg2(uint32_t d_tmem, uint32_t a_tmem,
                                               uint64_t b_desc, uint32_t idesc, bool acc) {
    uint32_t en = acc ? 1u : 0u;
    asm volatile("{\n\t.reg .pred p;\n\tsetp.ne.u32 p, %5, 0;\n\t"
        "tcgen05.mma.cta_group::2.kind::f16 [%0], [%1], %2, %3, "
        "{%4, %4, %4, %4, %4, %4, %4, %4}, p;\n\t}"
        :: "r"(d_tmem), "r"(a_tmem), "l"(b_desc), "r"(idesc), "r"(0u), "r"(en)
        : "memory");
}

__device__ __forceinline__ uint64_t make_desc(uint32_t addr) {
    return (uint64_t(2) << 61) | (uint64_t(1) << 46) | (uint64_t(64) << 32)
         | (uint64_t(1) << 16) | ((addr >> 4) & 0x3FFF);
}

// idesc: F32 accum, bf16 A/B, M=256 (16<<24), N=64 (8<<17)
#define MMA_IDESC ((16u << 24) | (8u << 17) | (1u << 10) | (1u << 7) | (1u << 4))
#endif  // HAS_TCGEN05

__device__ __forceinline__ uint32_t smem_u32(const void* p) {
    uint32_t a;
    asm("{ .reg .u64 t; cvta.to.shared.u64 t, %1; cvt.u32.u64 %0, t; }" : "=r"(a) : "l"(p));
    return a;
}

// ============================================================
// Kernel 0: fp32 -> {pre-swizzled 32-row bf16 tiles, linear bf16x2}
//           + exact fp32 row norms
// ============================================================
__global__ __launch_bounds__(128) void cvtsq_kernel(const float* __restrict__ X) {
    int row = blockIdx.x;
    int t = threadIdx.x;
    float4 v = *(const float4*)(X + (size_t)row * DIM + t * 4);
    uint32_t lo, hi;
    asm("cvt.rn.bf16x2.f32 %0, %1, %2;" : "=r"(lo) : "f"(v.y), "f"(v.x));
    asm("cvt.rn.bf16x2.f32 %0, %1, %2;" : "=r"(hi) : "f"(v.w), "f"(v.z));
    *(uint2*)(g_xb16 + (size_t)row * 256 + t * 2) = make_uint2(lo, hi);
    int tile = row >> 5, r = row & 31;
    int k = t * 4;
    uint32_t bo = (uint32_t)(r * 128 + (k & 63) * 2);
    uint32_t sw = bo ^ ((bo >> 3) & 0x70);
    *(uint2*)((char*)g_xb + (size_t)tile * 32768 + (size_t)(k >> 6) * 4096 + sw)
        = make_uint2(lo, hi);
    float s = v.x * v.x + v.y * v.y + v.z * v.z + v.w * v.w;
#pragma unroll
    for (int o = 16; o > 0; o >>= 1) s += __shfl_down_sync(0xffffffffu, s, o);
    __shared__ float ws[4];
    if ((t & 31) == 0) ws[t >> 5] = s;
    __syncthreads();
    if (t == 0) g_sq[row] = ws[0] + ws[1] + ws[2] + ws[3];
}

// ============================================================
// Kernel 1: cg2 TS-mode bf16 GEMM, 4-deep TMEM D ring.
// 64 clusters x 2 CTAs x 160 threads. Each CTA: its 128 A rows in
// its OWN TMEM (cols 0..255); per 64-col tile u, CTA rank r bulk-
// loads B rows [u*64 + r*32, +32) (32KB, 3-deep SMEM ring).
// Leader issues 32 cg2 TS MMAs (A from both TMEMs, B from both
// SMEMs) -> D slot u&3 in both CTAs' TMEM; commit multicast.
// Epilogue + handshake identical to round-12 champion.
// ============================================================
__global__ __launch_bounds__(THREADS, 1) __cluster_dims__(2, 1, 1)
void mma_topk_kernel() {
    extern __shared__ char smem[];
    const uint32_t smem_base = smem_u32(smem);
    const int tid = threadIdx.x;
    const int rowBase = blockIdx.x * 128;

#if HAS_TCGEN05
    const char* xb = (const char*)g_xb;
    const int wid = tid >> 5;
    const int lane = tid & 31;
    const bool is_prod = (wid == 0);
    const int rank = blockIdx.x & 1;
    const int smsp = wid & 3;
    const int row = smsp * 32 + lane;

    if (is_prod) {
        TCGEN05_ALLOC_CG2(smem_base + SMEM_TPTR, 512);
        TCGEN05_RELINQ_CG2();
    }
    if (tid == 0) {
#pragma unroll
        for (int s = 0; s < 3; ++s) MBARRIER_INIT(smem_base + SMEM_FULL0 + s * 8, 1);
#pragma unroll
        for (int s = 0; s < 4; ++s) {
            MBARRIER_INIT(smem_base + SMEM_DONE0 + s * 8, 1);
            MBARRIER_INIT(smem_base + SMEM_DFREE0 + s * 8, 4);
            MBARRIER_INIT(smem_base + SMEM_READY0 + s * 8, 1);
        }
#pragma unroll
        for (int s = 0; s < 8; ++s) MBARRIER_INIT(smem_base + SMEM_SQF0 + s * 8, 1);
    }
    __syncthreads();
    uint32_t tmem_base;
    asm volatile("ld.shared.b32 %0, [%1];" : "=r"(tmem_base) : "r"(smem_base + SMEM_TPTR));

    // ---- A fill: epilogue warps store own 128 rows x 512 bf16 to own TMEM ----
    if (!is_prod) {
        const uint4* arow = (const uint4*)g_xb16 + (size_t)(rowBase + row) * (DIM / 8);
        uint32_t wo = (uint32_t)smsp << 21;
#pragma unroll
        for (int c8 = 0; c8 < 8; ++c8) {
            uint32_t rg[32];
#pragma unroll
            for (int u = 0; u < 8; ++u) {
                uint4 v = arow[c8 * 8 + u];
                rg[u * 4 + 0] = v.x; rg[u * 4 + 1] = v.y;
                rg[u * 4 + 2] = v.z; rg[u * 4 + 3] = v.w;
            }
            TCGEN05_ST_X32(tmem_base + TMEM_A + c8 * 32 + wo, rg);
        }
        TCGEN05_WAIT_ST();
        TCGEN05_FENCE_BEFORE();
    } else {
        // prologue: bulk B tiles 0,1 (own 32-row half) + sq 0,1
        if (elect_one()) {
#pragma unroll
            for (int pt = 0; pt < 2; ++pt) {
                uint32_t fb = smem_base + SMEM_FULL0 + pt * 8;
                MBARRIER_EXPECT_TX(fb, 32768);
                bulk_g2s(smem_base + SMEM_B + pt * 32768,
                         xb + (size_t)(2 * pt + rank) * 32768, 32768, fb);
                uint32_t qb = smem_base + SMEM_SQF0 + pt * 8;
                MBARRIER_EXPECT_TX(qb, 256);
                bulk_g2s(smem_base + SMEM_SQS + pt * 256, (const char*)g_sq + pt * 256, 256, qb);
            }
        }
    }
    __syncthreads();
    CLUSTER_SYNC();   // both CTAs' A in TMEM + mbarriers visible before any cg2 MMA

    if (is_prod) {
        for (int u = 0; u < NTILE; ++u) {
            const int ds = u & 3;
            // own B half landed
            MBARRIER_WAIT_PARITY(smem_base + SMEM_FULL0 + (u % 3) * 8, (u / 3) & 1);
            // D slot WAR: own epilogue done with tile u-4
            if (u >= 4)
                MBARRIER_WAIT_PARITY(smem_base + SMEM_DFREE0 + ds * 8, ((u - 4) >> 2) & 1);

            if (rank == 1) {
                TCGEN05_FENCE_AFTER();
                if (elect_one())
                    MBARRIER_ARRIVE_LEADER(smem_base + SMEM_READY0 + ds * 8);
            } else {
                MBARRIER_WAIT_PARITY_CL(smem_base + SMEM_READY0 + ds * 8, (u >> 2) & 1);
                TCGEN05_FENCE_AFTER();
                if (elect_one()) {
                    uint64_t bdesc = make_desc(smem_base + SMEM_B + (u % 3) * 32768);
                    uint32_t dtm = tmem_base + TMEM_D + ds * 64;
#pragma unroll
                    for (int c = 0; c < 32; ++c) {
                        uint64_t boff = (uint64_t)((c >> 2) * 256 + (c & 3) * 2);
                        mma_f16_ts_cg2(dtm, tmem_base + TMEM_A + c * 8,
                                       bdesc + boff, MMA_IDESC, c > 0);
                    }
                    TCGEN05_COMMIT_MC_CG2(smem_base + SMEM_DONE0 + ds * 8);
                }
            }

            // recycle: B(u+2) -> slot (u+2)%3 (last read by MMA(u-1) -> done(u-1))
            if (u + 2 < NTILE) {
                if (u >= 1)
                    MBARRIER_WAIT_PARITY(smem_base + SMEM_DONE0 + ((u - 1) & 3) * 8,
                                         ((u - 1) >> 2) & 1);
                if (elect_one()) {
                    int s2 = (u + 2) % 3;
                    uint32_t fb = smem_base + SMEM_FULL0 + s2 * 8;
                    MBARRIER_EXPECT_TX(fb, 32768);
                    bulk_g2s(smem_base + SMEM_B + s2 * 32768,
                             xb + (size_t)(2 * (u + 2) + rank) * 32768, 32768, fb);
                    int q2 = (u + 2) & 7;
                    uint32_t qb = smem_base + SMEM_SQF0 + q2 * 8;
                    MBARRIER_EXPECT_TX(qb, 256);
                    bulk_g2s(smem_base + SMEM_SQS + q2 * 256,
                             (const char*)g_sq + (size_t)(u + 2) * 256, 256, qb);
                }
            }
        }
    } else {
        // ---- epilogue warps: per-thread (one row) top-3 over all tiles ----
        float v0 = FLT_MAX, v1 = FLT_MAX, v2 = FLT_MAX;
        int   i0 = 0, i1 = 0, i2 = 0;
        for (int u = 0; u < NTILE; ++u) {
            const int ds = u & 3;
            MBARRIER_WAIT_PARITY(smem_base + SMEM_DONE0 + ds * 8, (u >> 2) & 1);
            TCGEN05_FENCE_AFTER();
            MBARRIER_WAIT_PARITY(smem_base + SMEM_SQF0 + (u & 7) * 8, (u >> 3) & 1);
            const float* sqt = (const float*)(smem + SMEM_SQS + (u & 7) * 256);
            const int colBase = u * 64;
            const uint32_t dtm = tmem_base + TMEM_D + ds * 64;
            uint32_t dr[64];
            TCGEN05_LD_X32(dr, dtm);
            TCGEN05_LD_X32(dr + 32, dtm + 32);
            TCGEN05_WAIT_LD();
#pragma unroll
            for (int g = 0; g < 4; ++g) {
                float key[16];
#pragma unroll
                for (int c = 0; c < 16; ++c)
                    key[c] = fmaf(-2.f, __uint_as_float(dr[g * 16 + c]), sqt[g * 16 + c]);
                float t8[8];
#pragma unroll
                for (int c = 0; c < 8; ++c) t8[c] = fminf(key[c], key[c + 8]);
                float t4a = fminf(t8[0], t8[4]), t4b = fminf(t8[1], t8[5]);
                float t4c = fminf(t8[2], t8[6]), t4d = fminf(t8[3], t8[7]);
                float mn = fminf(fminf(t4a, t4b), fminf(t4c, t4d));
                if (mn < v2) {   // rare: exact ordered insert, ascending cols
#pragma unroll
                    for (int c = 0; c < 16; ++c) {
                        float k = key[c];
                        int col = colBase + g * 16 + c;
                        if (k < v2) {
                            if (k < v1) {
                                v2 = v1; i2 = i1;
                                if (k < v0) { v1 = v0; i1 = i0; v0 = k; i0 = col; }
                                else        { v1 = k; i1 = col; }
                            } else { v2 = k; i2 = col; }
                        }
                    }
                }
            }
            TCGEN05_FENCE_BEFORE();
            if (lane == 0) MBARRIER_ARRIVE(smem_base + SMEM_DFREE0 + ds * 8);
        }
        g_neg[rowBase + row] = i2;
    }

    __syncthreads();
    CLUSTER_SYNC();   // peer MMA done reading my SMEM/TMEM before teardown
    if (is_prod) TCGEN05_DEALLOC_CG2(tmem_base, 512);
    CLUSTER_SYNC();

#else  // ---------------- SIMT fallback (non-'a' pass) ----------------
    float* As = (float*)(smem);
    float* Bs = (float*)(smem + 4096);
    float* mv = (float*)(smem + 12288);
    int*   mi = (int*)(smem + 36864);
    const int tx = tid & 15, ty = tid >> 4;
    const bool act = (tid < 128);

    for (int half = 0; half < 2; ++half) {
        const int rh = rowBase + half * 64;
        float tv[8][3]; int tii[8][3];
#pragma unroll
        for (int i = 0; i < 8; ++i)
#pragma unroll
            for (int q = 0; q < 3; ++q) { tv[i][q] = FLT_MAX; tii[i][q] = 0x7fffffff; }

        for (int jt = 0; jt < NROW / 128; ++jt) {
            const int colBase = jt * 128;
            float c[8][8];
#pragma unroll
            for (int i = 0; i < 8; ++i)
#pragma unroll
                for (int j = 0; j < 8; ++j) c[i][j] = 0.f;

            for (int kt = 0; kt < DIM; kt += 16) {
                __syncthreads();
                if (act) {
#pragma unroll
                    for (int l = 0; l < 4; ++l) {
                        int f = tid + l * 128;
                        int r = f >> 3, uu = f & 7;
                        uint32_t w = g_xb16[(size_t)(rh + r) * 256 + kt / 2 + uu];
                        __nv_bfloat162 b2 = *(__nv_bfloat162*)&w;
                        float2 f2 = __bfloat1622float2(b2);
                        As[(2 * uu + 0) * 64 + r] = f2.x;
                        As[(2 * uu + 1) * 64 + r] = f2.y;
                    }
#pragma unroll
                    for (int l = 0; l < 8; ++l) {
                        int f = tid + l * 128;
                        int r = f >> 3, uu = f & 7;
                        uint32_t w = g_xb16[(size_t)(colBase + r) * 256 + kt / 2 + uu];
                        __nv_bfloat162 b2 = *(__nv_bfloat162*)&w;
                        float2 f2 = __bfloat1622float2(b2);
                        Bs[(2 * uu + 0) * 128 + r] = f2.x;
                        Bs[(2 * uu + 1) * 128 + r] = f2.y;
                    }
                }
                __syncthreads();
                if (act) {
#pragma unroll
                    for (int kk = 0; kk < 16; ++kk) {
                        float a[8], b[8];
#pragma unroll
                        for (int i = 0; i < 8; ++i) a[i] = As[kk * 64 + ty * 8 + i];
#pragma unroll
                        for (int j = 0; j < 8; ++j) b[j] = Bs[kk * 128 + tx * 8 + j];
#pragma unroll
                        for (int i = 0; i < 8; ++i)
#pragma unroll
                            for (int j = 0; j < 8; ++j) c[i][j] += a[i] * b[j];
                    }
                }
            }
            if (act) {
#pragma unroll
                for (int j = 0; j < 8; ++j) {
                    int col = colBase + tx * 8 + j;
                    float sqc = g_sq[col];
#pragma unroll
                    for (int i = 0; i < 8; ++i) {
                        float d2 = fmaf(-2.f, c[i][j], sqc);
                        bool b2c = (d2 < tv[i][2]) || (d2 == tv[i][2] && col < tii[i][2]);
                        if (b2c) {
                            bool b1c = (d2 < tv[i][1]) || (d2 == tv[i][1] && col < tii[i][1]);
                            bool b0c = (d2 < tv[i][0]) || (d2 == tv[i][0] && col < tii[i][0]);
                            if (b0c) {
                                tv[i][2] = tv[i][1]; tii[i][2] = tii[i][1];
                                tv[i][1] = tv[i][0]; tii[i][1] = tii[i][0];
                                tv[i][0] = d2;       tii[i][0] = col;
                            } else if (b1c) {
                                tv[i][2] = tv[i][1]; tii[i][2] = tii[i][1];
                                tv[i][1] = d2;       tii[i][1] = col;
                            } else { tv[i][2] = d2; tii[i][2] = col; }
                        }
                    }
                }
            }
        }

        __syncthreads();
        if (act) {
#pragma unroll
            for (int i = 0; i < 8; ++i)
#pragma unroll
                for (int q = 0; q < 3; ++q) {
                    mv[(ty * 8 + i) * 48 + tx * 3 + q] = tv[i][q];
                    mi[(ty * 8 + i) * 48 + tx * 3 + q] = tii[i][q];
                }
        }
        __syncthreads();
        if (tid < 64) {
            float w0 = FLT_MAX, w1 = FLT_MAX, w2 = FLT_MAX;
            int   j0 = 0x7fffffff, j1 = 0x7fffffff, j2 = 0x7fffffff;
            for (int cnd = 0; cnd < 48; ++cnd) {
                float d = mv[tid * 48 + cnd];
                int   ix = mi[tid * 48 + cnd];
                bool b2c = (d < w2) || (d == w2 && ix < j2);
                if (b2c) {
                    bool b1c = (d < w1) || (d == w1 && ix < j1);
                    bool b0c = (d < w0) || (d == w0 && ix < j0);
                    if (b0c)      { w2 = w1; j2 = j1; w1 = w0; j1 = j0; w0 = d; j0 = ix; }
                    else if (b1c) { w2 = w1; j2 = j1; w1 = d; j1 = ix; }
                    else          { w2 = d;  j2 = ix; }
                }
            }
            g_neg[rh + tid] = j2;
        }
        __syncthreads();
    }
#endif
}

// ============================================================
// Kernel 2: per-row triplet loss (one warp per row, fp32 exact)
// ============================================================
__global__ __launch_bounds__(256) void rowloss_kernel(const float* __restrict__ X,
                                                      const float* __restrict__ P) {
    int warp = threadIdx.x >> 5;
    int lane = threadIdx.x & 31;
    int row = blockIdx.x * 8 + warp;
    const float4* xr = (const float4*)(X + (size_t)row * DIM);
    const float4* pr = (const float4*)(P + (size_t)row * DIM);
    const float4* nr = (const float4*)(X + (size_t)g_neg[row] * DIM);
    float sap = 0.f, san = 0.f;
#pragma unroll
    for (int i = 0; i < 4; ++i) {
        float4 x = xr[lane + 32 * i];
        float4 p = pr[lane + 32 * i];
        float4 v = nr[lane + 32 * i];
        float d;
        d = x.x - p.x + EPSV; sap += d * d;
        d = x.y - p.y + EPSV; sap += d * d;
        d = x.z - p.z + EPSV; sap += d * d;
        d = x.w - p.w + EPSV; sap += d * d;
        d = x.x - v.x + EPSV; san += d * d;
        d = x.y - v.y + EPSV; san += d * d;
        d = x.z - v.z + EPSV; san += d * d;
        d = x.w - v.w + EPSV; san += d * d;
    }
#pragma unroll
    for (int o = 16; o > 0; o >>= 1) {
        sap += __shfl_down_sync(0xffffffffu, sap, o);
        san += __shfl_down_sync(0xffffffffu, san, o);
    }
    if (lane == 0)
        g_rowloss[row] = fmaxf(sqrtf(sap) - sqrtf(san) + MARGIN, 0.f);
}

// ============================================================
// Kernel 3: mean reduction -> d_out[0]
// ============================================================
__global__ __launch_bounds__(512) void reduce_kernel(float* __restrict__ out) {
    int t = threadIdx.x;
    float s = 0.f;
    for (int i = t; i < NROW; i += 512) s += g_rowloss[i];
#pragma unroll
    for (int o = 16; o > 0; o >>= 1) s += __shfl_down_sync(0xffffffffu, s, o);
    __shared__ float ws[16];
    if ((t & 31) == 0) ws[t >> 5] = s;
    __syncthreads();
    if (t == 0) {
        float tot = 0.f;
#pragma unroll
        for (int w = 0; w < 16; ++w) tot += ws[w];
        out[0] = tot / (float)NROW;
    }
}

extern "C" void kernel_launch(void* const* d_in, const int* in_sizes, int n_in,
                              void* d_out, int out_size) {
    const float* X = (const float*)d_in[0];   // inputs  [16384, 512] f32
    const float* P = (const float*)d_in[1];   // positive[16384, 512] f32
    float* out = (float*)d_out;

    cudaFuncSetAttribute(mma_topk_kernel,
                         cudaFuncAttributeMaxDynamicSharedMemorySize, SMEM_TOTAL);

    cvtsq_kernel<<<NROW, 128>>>(X);
    mma_topk_kernel<<<128, THREADS, SMEM_TOTAL>>>();
    rowloss_kernel<<<NROW / 8, 256>>>(X, P);
    reduce_kernel<<<1, 512>>>(out);
}

// round 14
// speedup vs baseline: 1.5178x; 1.0339x over previous
#include <cuda_runtime.h>
#include <cuda_bf16.h>
#include <math.h>
#include <float.h>
#include <stdint.h>

#define NROW 16384
#define DIM  512
#define MARGIN 2.0f
#define EPSV 1e-6f

#if defined(__CUDA_ARCH_FEAT_SM103_ALL) || (defined(__CUDA_ARCH_SPECIFIC__) && (__CUDA_ARCH_SPECIFIC__ == 1030))
#define HAS_TCGEN05 1
#else
#define HAS_TCGEN05 0
#endif

// ---- device scratch ----
__device__ __align__(16) float g_sq[NROW];
__device__ int   g_neg[NROW];
__device__ float g_rowloss[NROW];
// bf16 PRE-SWIZZLED as 512 tiles of 32 rows x 512 K = 32KB each (SW128 image)
__device__ __align__(256) uint32_t g_xb[NROW * DIM / 2];
// linear bf16x2 copy (A fill + SIMT fallback)
__device__ __align__(16) uint32_t g_xb16[NROW * DIM / 2];

// SMEM layout (A in TMEM; whole sq resident; 4-deep B ring)
#define SMEM_TPTR   0
#define SMEM_FULL0  8            // 4 mbarriers (own B ring complete_tx)
#define SMEM_DONE0  40           // 4 mbarriers (MMA commit, multicast to both)
#define SMEM_DFREE0 72           // 4 mbarriers (own epilogue done with D slot)
#define SMEM_READY0 104          // 4 mbarriers (leader: follower tile-ready)
#define SMEM_SQFULL 136          // 1 mbarrier  (whole-sq load complete)
#define SMEM_SQ     1024         // 16384 floats = 65536 B -> ends 66560
#define SMEM_B      66560        // 4 x 32768 -> ends 197632
#define SMEM_TOTAL  197632

#define TMEM_A 0                 // 256 cols: own 128 rows x 512 bf16
#define TMEM_D 256               // 4 x 64 cols f32

#define NTILE 256
#define THREADS 160              // w0 = producer(+MMA on leader), w1-4 = epilogue

#if HAS_TCGEN05
__device__ __forceinline__ uint32_t elect_one() {
    uint32_t p;
    asm volatile("{\n\t.reg .pred p;\n\telect.sync _|p, 0xFFFFFFFF;\n\tselp.b32 %0, 1, 0, p;\n\t}" : "=r"(p));
    return p;
}
#define TCGEN05_ALLOC_CG2(dst, n) \
    asm volatile("tcgen05.alloc.cta_group::2.sync.aligned.shared::cta.b32 [%0], %1;" :: "r"(dst), "r"(n) : "memory")
#define TCGEN05_DEALLOC_CG2(t, n) \
    asm volatile("tcgen05.dealloc.cta_group::2.sync.aligned.b32 %0, %1;" :: "r"(t), "r"(n))
#define TCGEN05_RELINQ_CG2() \
    asm volatile("tcgen05.relinquish_alloc_permit.cta_group::2.sync.aligned;")
#define TCGEN05_WAIT_ST() asm volatile("tcgen05.wait::st.sync.aligned;" ::: "memory")
#define TCGEN05_WAIT_LD() asm volatile("tcgen05.wait::ld.sync.aligned;" ::: "memory")
#define TCGEN05_FENCE_BEFORE() asm volatile("tcgen05.fence::before_thread_sync;" ::: "memory")
#define TCGEN05_FENCE_AFTER()  asm volatile("tcgen05.fence::after_thread_sync;" ::: "memory")
#define FENCE_PROXY_ASYNC() asm volatile("fence.proxy.async;" ::: "memory")
#define MBARRIER_INIT(m, c) \
    asm volatile("mbarrier.init.shared.b64 [%0], %1;" :: "r"(m), "r"(c) : "memory")
#define MBARRIER_ARRIVE(m) \
    asm volatile("mbarrier.arrive.release.cta.shared.b64 _, [%0];" :: "r"(m) : "memory")
#define MBARRIER_EXPECT_TX(m, b) \
    asm volatile("mbarrier.arrive.expect_tx.shared.b64 _, [%0], %1;" :: "r"(m), "r"(b) : "memory")
#define MBARRIER_ARRIVE_LEADER(local_addr) \
    asm volatile("{\n\t.reg .b32 rA;\n\t.reg .b32 z;\n\tmov.b32 z, 0;\n\t" \
        "mapa.shared::cluster.u32 rA, %0, z;\n\t" \
        "mbarrier.arrive.release.cluster.shared::cluster.b64 _, [rA];\n\t}" \
        :: "r"((uint32_t)(local_addr)) : "memory")
#define TCGEN05_COMMIT_MC_CG2(m) \
    asm volatile("tcgen05.commit.cta_group::2.mbarrier::arrive::one.shared::cluster.multicast::cluster.b64 [%0], %1;" \
        :: "r"(m), "h"((uint16_t)3) : "memory")
#define CLUSTER_SYNC() do { \
    asm volatile("barrier.cluster.arrive.aligned;" ::: "memory"); \
    asm volatile("barrier.cluster.wait.aligned;" ::: "memory"); \
} while (0)

#define MBARRIER_WAIT_PARITY(mbar_smem_addr, phase_parity) do { \
    uint32_t _mbar = (uint32_t)(mbar_smem_addr); \
    uint32_t _parity = (uint32_t)(phase_parity); \
    uint32_t _done; \
    asm volatile("{\n\t.reg .pred p;\n\t" \
        "mbarrier.try_wait.parity.acquire.cta.shared::cta.b64 p, [%1], %2;\n\t" \
        "selp.b32 %0, 1, 0, p;\n\t}" : "=r"(_done) : "r"(_mbar), "r"(_parity) : "memory"); \
    if (!_done) { \
        asm volatile("{\n\t.reg .pred P1;\n\t" \
            "WAIT_LOOP_%=:\n\t" \
            "mbarrier.try_wait.parity.acquire.cta.shared::cta.b64 P1, [%0], %1, 0x989680;\n\t" \
            "@P1 bra.uni WAIT_DONE_%=;\n\t" \
            "bra.uni WAIT_LOOP_%=;\n\t" \
            "WAIT_DONE_%=:\n\t}" :: "r"(_mbar), "r"(_parity) : "memory"); \
    } \
} while (0)

#define MBARRIER_WAIT_PARITY_CL(mbar_smem_addr, phase_parity) do { \
    uint32_t _mbar = (uint32_t)(mbar_smem_addr); \
    uint32_t _parity = (uint32_t)(phase_parity); \
    uint32_t _done; \
    asm volatile("{\n\t.reg .pred p;\n\t" \
        "mbarrier.try_wait.parity.acquire.cluster.shared::cta.b64 p, [%1], %2;\n\t" \
        "selp.b32 %0, 1, 0, p;\n\t}" : "=r"(_done) : "r"(_mbar), "r"(_parity) : "memory"); \
    if (!_done) { \
        asm volatile("{\n\t.reg .pred P1;\n\t" \
            "WAIT_LOOP_%=:\n\t" \
            "mbarrier.try_wait.parity.acquire.cluster.shared::cta.b64 P1, [%0], %1, 0x989680;\n\t" \
            "@P1 bra.uni WAIT_DONE_%=;\n\t" \
            "bra.uni WAIT_LOOP_%=;\n\t" \
            "WAIT_DONE_%=:\n\t}" :: "r"(_mbar), "r"(_parity) : "memory"); \
    } \
} while (0)

#define TCGEN05_ST_X32(tmem_addr, r) \
    asm volatile("tcgen05.st.sync.aligned.32x32b.x32.b32 [%0], " \
        "{%1, %2, %3, %4, %5, %6, %7, %8, %9, %10, %11, %12, %13, %14, %15, %16, " \
        "%17, %18, %19, %20, %21, %22, %23, %24, %25, %26, %27, %28, %29, %30, %31, %32};" \
        :: "r"(tmem_addr), \
           "r"((r)[0]),"r"((r)[1]),"r"((r)[2]),"r"((r)[3]),"r"((r)[4]),"r"((r)[5]),"r"((r)[6]),"r"((r)[7]), \
           "r"((r)[8]),"r"((r)[9]),"r"((r)[10]),"r"((r)[11]),"r"((r)[12]),"r"((r)[13]),"r"((r)[14]),"r"((r)[15]), \
           "r"((r)[16]),"r"((r)[17]),"r"((r)[18]),"r"((r)[19]),"r"((r)[20]),"r"((r)[21]),"r"((r)[22]),"r"((r)[23]), \
           "r"((r)[24]),"r"((r)[25]),"r"((r)[26]),"r"((r)[27]),"r"((r)[28]),"r"((r)[29]),"r"((r)[30]),"r"((r)[31]) \
        : "memory")

#define TCGEN05_LD_X32(r, tmem_addr) \
    asm volatile("tcgen05.ld.sync.aligned.32x32b.x32.b32 " \
        "{%0, %1, %2, %3, %4, %5, %6, %7, %8, %9, %10, %11, %12, %13, %14, %15, " \
        "%16, %17, %18, %19, %20, %21, %22, %23, %24, %25, %26, %27, %28, %29, %30, %31}, [%32];" \
        : "=r"((r)[0]),"=r"((r)[1]),"=r"((r)[2]),"=r"((r)[3]),"=r"((r)[4]),"=r"((r)[5]),"=r"((r)[6]),"=r"((r)[7]), \
          "=r"((r)[8]),"=r"((r)[9]),"=r"((r)[10]),"=r"((r)[11]),"=r"((r)[12]),"=r"((r)[13]),"=r"((r)[14]),"=r"((r)[15]), \
          "=r"((r)[16]),"=r"((r)[17]),"=r"((r)[18]),"=r"((r)[19]),"=r"((r)[20]),"=r"((r)[21]),"=r"((r)[22]),"=r"((r)[23]), \
          "=r"((r)[24]),"=r"((r)[25]),"=r"((r)[26]),"=r"((r)[27]),"=r"((r)[28]),"=r"((r)[29]),"=r"((r)[30]),"=r"((r)[31]) \
        : "r"(tmem_addr))

__device__ __forceinline__ void bulk_g2s(uint32_t dst, const void* src, uint32_t bytes, uint32_t mbar) {
    asm volatile("cp.async.bulk.shared::cta.global.mbarrier::complete_tx::bytes [%0], [%1], %2, [%3];"
                 :: "r"(dst), "l"(src), "r"(bytes), "r"(mbar) : "memory");
}

// cg2 TS-mode bf16 MMA: A in (each CTA's own) TMEM, B via SMEM descriptor
__device__ __forceinline__ void mma_f16_ts_cg2(uint32_t d_tmem, uint32_t a_tmem,
                                               uint64_t b_desc, uint32_t idesc, bool acc) {
    uint32_t en = acc ? 1u : 0u;
    asm volatile("{\n\t.reg .pred p;\n\tsetp.ne.u32 p, %5, 0;\n\t"
        "tcgen05.mma.cta_group::2.kind::f16 [%0], [%1], %2, %3, "
        "{%4, %4, %4, %4, %4, %4, %4, %4}, p;\n\t}"
        :: "r"(d_tmem), "r"(a_tmem), "l"(b_desc), "r"(idesc), "r"(0u), "r"(en)
        : "memory");
}

__device__ __forceinline__ uint64_t make_desc(uint32_t addr) {
    return (uint64_t(2) << 61) | (uint64_t(1) << 46) | (uint64_t(64) << 32)
         | (uint64_t(1) << 16) | ((addr >> 4) & 0x3FFF);
}

// idesc: F32 accum, bf16 A/B, M=256 (16<<24), N=64 (8<<17)
#define MMA_IDESC ((16u << 24) | (8u << 17) | (1u << 10) | (1u << 7) | (1u << 4))
#endif  // HAS_TCGEN05

__device__ __forceinline__ uint32_t smem_u32(const void* p) {
    uint32_t a;
    asm("{ .reg .u64 t; cvta.to.shared.u64 t, %1; cvt.u32.u64 %0, t; }" : "=r"(a) : "l"(p));
    return a;
}

// ============================================================
// Kernel 0: fp32 -> {pre-swizzled 32-row bf16 tiles, linear bf16x2}
//           + exact fp32 row norms
// ============================================================
__global__ __launch_bounds__(128) void cvtsq_kernel(const float* __restrict__ X) {
    int row = blockIdx.x;
    int t = threadIdx.x;
    float4 v = *(const float4*)(X + (size_t)row * DIM + t * 4);
    uint32_t lo, hi;
    asm("cvt.rn.bf16x2.f32 %0, %1, %2;" : "=r"(lo) : "f"(v.y), "f"(v.x));
    asm("cvt.rn.bf16x2.f32 %0, %1, %2;" : "=r"(hi) : "f"(v.w), "f"(v.z));
    *(uint2*)(g_xb16 + (size_t)row * 256 + t * 2) = make_uint2(lo, hi);
    int tile = row >> 5, r = row & 31;
    int k = t * 4;
    uint32_t bo = (uint32_t)(r * 128 + (k & 63) * 2);
    uint32_t sw = bo ^ ((bo >> 3) & 0x70);
    *(uint2*)((char*)g_xb + (size_t)tile * 32768 + (size_t)(k >> 6) * 4096 + sw)
        = make_uint2(lo, hi);
    float s = v.x * v.x + v.y * v.y + v.z * v.z + v.w * v.w;
#pragma unroll
    for (int o = 16; o > 0; o >>= 1) s += __shfl_down_sync(0xffffffffu, s, o);
    __shared__ float ws[4];
    if ((t & 31) == 0) ws[t >> 5] = s;
    __syncthreads();
    if (t == 0) g_sq[row] = ws[0] + ws[1] + ws[2] + ws[3];
}

// ============================================================
// Kernel 1: cg2 TS-mode bf16 GEMM, 4-deep TMEM D ring, 4-deep B ring,
// whole sq resident in SMEM. 64 clusters x 2 CTAs x 160 threads.
// Each CTA: 128 A rows in OWN TMEM; per 64-col tile u, rank r bulk-
// loads B rows [u*64 + r*32, +32) into slot u&3 (prefetch depth 3).
// Leader issues 32 cg2 TS MMAs -> D slot u&3; commit multicast.
// Epilogue: wait done -> LDTM -> min-screen top-3 -> arrive dfree.
// ============================================================
__global__ __launch_bounds__(THREADS, 1) __cluster_dims__(2, 1, 1)
void mma_topk_kernel() {
    extern __shared__ char smem[];
    const uint32_t smem_base = smem_u32(smem);
    const int tid = threadIdx.x;
    const int rowBase = blockIdx.x * 128;

#if HAS_TCGEN05
    const char* xb = (const char*)g_xb;
    const int wid = tid >> 5;
    const int lane = tid & 31;
    const bool is_prod = (wid == 0);
    const int rank = blockIdx.x & 1;
    const int smsp = wid & 3;
    const int row = smsp * 32 + lane;

    if (is_prod) {
        TCGEN05_ALLOC_CG2(smem_base + SMEM_TPTR, 512);
        TCGEN05_RELINQ_CG2();
    }
    if (tid == 0) {
#pragma unroll
        for (int s = 0; s < 4; ++s) {
            MBARRIER_INIT(smem_base + SMEM_FULL0 + s * 8, 1);
            MBARRIER_INIT(smem_base + SMEM_DONE0 + s * 8, 1);
            MBARRIER_INIT(smem_base + SMEM_DFREE0 + s * 8, 4);
            MBARRIER_INIT(smem_base + SMEM_READY0 + s * 8, 1);
        }
        MBARRIER_INIT(smem_base + SMEM_SQFULL, 1);
    }
    __syncthreads();
    uint32_t tmem_base;
    asm volatile("ld.shared.b32 %0, [%1];" : "=r"(tmem_base) : "r"(smem_base + SMEM_TPTR));

    // ---- A fill: epilogue warps store own 128 rows x 512 bf16 to own TMEM ----
    if (!is_prod) {
        const uint4* arow = (const uint4*)g_xb16 + (size_t)(rowBase + row) * (DIM / 8);
        uint32_t wo = (uint32_t)smsp << 21;
#pragma unroll
        for (int c8 = 0; c8 < 8; ++c8) {
            uint32_t rg[32];
#pragma unroll
            for (int u = 0; u < 8; ++u) {
                uint4 v = arow[c8 * 8 + u];
                rg[u * 4 + 0] = v.x; rg[u * 4 + 1] = v.y;
                rg[u * 4 + 2] = v.z; rg[u * 4 + 3] = v.w;
            }
            TCGEN05_ST_X32(tmem_base + TMEM_A + c8 * 32 + wo, rg);
        }
        TCGEN05_WAIT_ST();
        TCGEN05_FENCE_BEFORE();
    } else {
        // prologue: whole sq (64KB) + B tiles 0,1,2 (own 32-row halves)
        if (elect_one()) {
            MBARRIER_EXPECT_TX(smem_base + SMEM_SQFULL, 65536);
            bulk_g2s(smem_base + SMEM_SQ, (const char*)g_sq, 65536,
                     smem_base + SMEM_SQFULL);
#pragma unroll
            for (int pt = 0; pt < 3; ++pt) {
                uint32_t fb = smem_base + SMEM_FULL0 + pt * 8;
                MBARRIER_EXPECT_TX(fb, 32768);
                bulk_g2s(smem_base + SMEM_B + pt * 32768,
                         xb + (size_t)(2 * pt + rank) * 32768, 32768, fb);
            }
        }
    }
    __syncthreads();
    CLUSTER_SYNC();   // both CTAs' A in TMEM + mbarriers visible before any cg2 MMA

    if (is_prod) {
        for (int u = 0; u < NTILE; ++u) {
            const int ds = u & 3;
            // own B half landed
            MBARRIER_WAIT_PARITY(smem_base + SMEM_FULL0 + ds * 8, (u >> 2) & 1);
            // D slot WAR: own epilogue done with tile u-4
            if (u >= 4)
                MBARRIER_WAIT_PARITY(smem_base + SMEM_DFREE0 + ds * 8, ((u - 4) >> 2) & 1);

            if (rank == 1) {
                TCGEN05_FENCE_AFTER();
                if (elect_one())
                    MBARRIER_ARRIVE_LEADER(smem_base + SMEM_READY0 + ds * 8);
            } else {
                MBARRIER_WAIT_PARITY_CL(smem_base + SMEM_READY0 + ds * 8, (u >> 2) & 1);
                TCGEN05_FENCE_AFTER();
                if (elect_one()) {
                    uint64_t bdesc = make_desc(smem_base + SMEM_B + ds * 32768);
                    uint32_t dtm = tmem_base + TMEM_D + ds * 64;
#pragma unroll
                    for (int c = 0; c < 32; ++c) {
                        uint64_t boff = (uint64_t)((c >> 2) * 256 + (c & 3) * 2);
                        mma_f16_ts_cg2(dtm, tmem_base + TMEM_A + c * 8,
                                       bdesc + boff, MMA_IDESC, c > 0);
                    }
                    TCGEN05_COMMIT_MC_CG2(smem_base + SMEM_DONE0 + ds * 8);
                }
            }

            // recycle: B(u+3) -> slot (u+3)&3 == (u-1)&3, last read by MMA(u-1)
            if (u + 3 < NTILE) {
                if (u >= 1)
                    MBARRIER_WAIT_PARITY(smem_base + SMEM_DONE0 + ((u - 1) & 3) * 8,
                                         ((u - 1) >> 2) & 1);
                if (elect_one()) {
                    int s2 = (u + 3) & 3;
                    uint32_t fb = smem_base + SMEM_FULL0 + s2 * 8;
                    MBARRIER_EXPECT_TX(fb, 32768);
                    bulk_g2s(smem_base + SMEM_B + s2 * 32768,
                             xb + (size_t)(2 * (u + 3) + rank) * 32768, 32768, fb);
                }
            }
        }
    } else {
        // ---- epilogue warps: per-thread (one row) top-3 over all tiles ----
        MBARRIER_WAIT_PARITY(smem_base + SMEM_SQFULL, 0);   // whole sq resident
        const float* sqall = (const float*)(smem + SMEM_SQ);
        float v0 = FLT_MAX, v1 = FLT_MAX, v2 = FLT_MAX;
        int   i0 = 0, i1 = 0, i2 = 0;
        for (int u = 0; u < NTILE; ++u) {
            const int ds = u & 3;
            MBARRIER_WAIT_PARITY(smem_base + SMEM_DONE0 + ds * 8, (u >> 2) & 1);
            TCGEN05_FENCE_AFTER();
            const float* sqt = sqall + u * 64;
            const int colBase = u * 64;
            const uint32_t dtm = tmem_base + TMEM_D + ds * 64;
            uint32_t dr[64];
            TCGEN05_LD_X32(dr, dtm);
            TCGEN05_LD_X32(dr + 32, dtm + 32);
            TCGEN05_WAIT_LD();
#pragma unroll
            for (int g = 0; g < 4; ++g) {
                float key[16];
#pragma unroll
                for (int c = 0; c < 16; ++c)
                    key[c] = fmaf(-2.f, __uint_as_float(dr[g * 16 + c]), sqt[g * 16 + c]);
                float t8[8];
#pragma unroll
                for (int c = 0; c < 8; ++c) t8[c] = fminf(key[c], key[c + 8]);
                float t4a = fminf(t8[0], t8[4]), t4b = fminf(t8[1], t8[5]);
                float t4c = fminf(t8[2], t8[6]), t4d = fminf(t8[3], t8[7]);
                float mn = fminf(fminf(t4a, t4b), fminf(t4c, t4d));
                if (mn < v2) {   // rare: exact ordered insert, ascending cols
#pragma unroll
                    for (int c = 0; c < 16; ++c) {
                        float k = key[c];
                        int col = colBase + g * 16 + c;
                        if (k < v2) {
                            if (k < v1) {
                                v2 = v1; i2 = i1;
                                if (k < v0) { v1 = v0; i1 = i0; v0 = k; i0 = col; }
                                else        { v1 = k; i1 = col; }
                            } else { v2 = k; i2 = col; }
                        }
                    }
                }
            }
            TCGEN05_FENCE_BEFORE();
            if (lane == 0) MBARRIER_ARRIVE(smem_base + SMEM_DFREE0 + ds * 8);
        }
        g_neg[rowBase + row] = i2;
    }

    __syncthreads();
    CLUSTER_SYNC();   // peer MMA done reading my SMEM/TMEM before teardown
    if (is_prod) TCGEN05_DEALLOC_CG2(tmem_base, 512);
    CLUSTER_SYNC();

#else  // ---------------- SIMT fallback (non-'a' pass) ----------------
    float* As = (float*)(smem);
    float* Bs = (float*)(smem + 4096);
    float* mv = (float*)(smem + 12288);
    int*   mi = (int*)(smem + 36864);
    const int tx = tid & 15, ty = tid >> 4;
    const bool act = (tid < 128);

    for (int half = 0; half < 2; ++half) {
        const int rh = rowBase + half * 64;
        float tv[8][3]; int tii[8][3];
#pragma unroll
        for (int i = 0; i < 8; ++i)
#pragma unroll
            for (int q = 0; q < 3; ++q) { tv[i][q] = FLT_MAX; tii[i][q] = 0x7fffffff; }

        for (int jt = 0; jt < NROW / 128; ++jt) {
            const int colBase = jt * 128;
            float c[8][8];
#pragma unroll
            for (int i = 0; i < 8; ++i)
#pragma unroll
                for (int j = 0; j < 8; ++j) c[i][j] = 0.f;

            for (int kt = 0; kt < DIM; kt += 16) {
                __syncthreads();
                if (act) {
#pragma unroll
                    for (int l = 0; l < 4; ++l) {
                        int f = tid + l * 128;
                        int r = f >> 3, uu = f & 7;
                        uint32_t w = g_xb16[(size_t)(rh + r) * 256 + kt / 2 + uu];
                        __nv_bfloat162 b2 = *(__nv_bfloat162*)&w;
                        float2 f2 = __bfloat1622float2(b2);
                        As[(2 * uu + 0) * 64 + r] = f2.x;
                        As[(2 * uu + 1) * 64 + r] = f2.y;
                    }
#pragma unroll
                    for (int l = 0; l < 8; ++l) {
                        int f = tid + l * 128;
                        int r = f >> 3, uu = f & 7;
                        uint32_t w = g_xb16[(size_t)(colBase + r) * 256 + kt / 2 + uu];
                        __nv_bfloat162 b2 = *(__nv_bfloat162*)&w;
                        float2 f2 = __bfloat1622float2(b2);
                        Bs[(2 * uu + 0) * 128 + r] = f2.x;
                        Bs[(2 * uu + 1) * 128 + r] = f2.y;
                    }
                }
                __syncthreads();
                if (act) {
#pragma unroll
                    for (int kk = 0; kk < 16; ++kk) {
                        float a[8], b[8];
#pragma unroll
                        for (int i = 0; i < 8; ++i) a[i] = As[kk * 64 + ty * 8 + i];
#pragma unroll
                        for (int j = 0; j < 8; ++j) b[j] = Bs[kk * 128 + tx * 8 + j];
#pragma unroll
                        for (int i = 0; i < 8; ++i)
#pragma unroll
                            for (int j = 0; j < 8; ++j) c[i][j] += a[i] * b[j];
                    }
                }
            }
            if (act) {
#pragma unroll
                for (int j = 0; j < 8; ++j) {
                    int col = colBase + tx * 8 + j;
                    float sqc = g_sq[col];
#pragma unroll
                    for (int i = 0; i < 8; ++i) {
                        float d2 = fmaf(-2.f, c[i][j], sqc);
                        bool b2c = (d2 < tv[i][2]) || (d2 == tv[i][2] && col < tii[i][2]);
                        if (b2c) {
                            bool b1c = (d2 < tv[i][1]) || (d2 == tv[i][1] && col < tii[i][1]);
                            bool b0c = (d2 < tv[i][0]) || (d2 == tv[i][0] && col < tii[i][0]);
                            if (b0c) {
                                tv[i][2] = tv[i][1]; tii[i][2] = tii[i][1];
                                tv[i][1] = tv[i][0]; tii[i][1] = tii[i][0];
                                tv[i][0] = d2;       tii[i][0] = col;
                            } else if (b1c) {
                                tv[i][2] = tv[i][1]; tii[i][2] = tii[i][1];
                                tv[i][1] = d2;       tii[i][1] = col;
                            } else { tv[i][2] = d2; tii[i][2] = col; }
                        }
                    }
                }
            }
        }

        __syncthreads();
        if (act) {
#pragma unroll
            for (int i = 0; i < 8; ++i)
#pragma unroll
                for (int q = 0; q < 3; ++q) {
                    mv[(ty * 8 + i) * 48 + tx * 3 + q] = tv[i][q];
                    mi[(ty * 8 + i) * 48 + tx * 3 + q] = tii[i][q];
                }
        }
        __syncthreads();
        if (tid < 64) {
            float w0 = FLT_MAX, w1 = FLT_MAX, w2 = FLT_MAX;
            int   j0 = 0x7fffffff, j1 = 0x7fffffff, j2 = 0x7fffffff;
            for (int cnd = 0; cnd < 48; ++cnd) {
                float d = mv[tid * 48 + cnd];
                int   ix = mi[tid * 48 + cnd];
                bool b2c = (d < w2) || (d == w2 && ix < j2);
                if (b2c) {
                    bool b1c = (d < w1) || (d == w1 && ix < j1);
                    bool b0c = (d < w0) || (d == w0 && ix < j0);
                    if (b0c)      { w2 = w1; j2 = j1; w1 = w0; j1 = j0; w0 = d; j0 = ix; }
                    else if (b1c) { w2 = w1; j2 = j1; w1 = d; j1 = ix; }
                    else          { w2 = d;  j2 = ix; }
                }
            }
            g_neg[rh + tid] = j2;
        }
        __syncthreads();
    }
#endif
}

// ============================================================
// Kernel 2: per-row triplet loss (one warp per row, fp32 exact)
// ============================================================
__global__ __launch_bounds__(256) void rowloss_kernel(const float* __restrict__ X,
                                                      const float* __restrict__ P) {
    int warp = threadIdx.x >> 5;
    int lane = threadIdx.x & 31;
    int row = blockIdx.x * 8 + warp;
    const float4* xr = (const float4*)(X + (size_t)row * DIM);
    const float4* pr = (const float4*)(P + (size_t)row * DIM);
    const float4* nr = (const float4*)(X + (size_t)g_neg[row] * DIM);
    float sap = 0.f, san = 0.f;
#pragma unroll
    for (int i = 0; i < 4; ++i) {
        float4 x = xr[lane + 32 * i];
        float4 p = pr[lane + 32 * i];
        float4 v = nr[lane + 32 * i];
        float d;
        d = x.x - p.x + EPSV; sap += d * d;
        d = x.y - p.y + EPSV; sap += d * d;
        d = x.z - p.z + EPSV; sap += d * d;
        d = x.w - p.w + EPSV; sap += d * d;
        d = x.x - v.x + EPSV; san += d * d;
        d = x.y - v.y + EPSV; san += d * d;
        d = x.z - v.z + EPSV; san += d * d;
        d = x.w - v.w + EPSV; san += d * d;
    }
#pragma unroll
    for (int o = 16; o > 0; o >>= 1) {
        sap += __shfl_down_sync(0xffffffffu, sap, o);
        san += __shfl_down_sync(0xffffffffu, san, o);
    }
    if (lane == 0)
        g_rowloss[row] = fmaxf(sqrtf(sap) - sqrtf(san) + MARGIN, 0.f);
}

// ============================================================
// Kernel 3: mean reduction -> d_out[0]
// ============================================================
__global__ __launch_bounds__(512) void reduce_kernel(float* __restrict__ out) {
    int t = threadIdx.x;
    float s = 0.f;
    for (int i = t; i < NROW; i += 512) s += g_rowloss[i];
#pragma unroll
    for (int o = 16; o > 0; o >>= 1) s += __shfl_down_sync(0xffffffffu, s, o);
    __shared__ float ws[16];
    if ((t & 31) == 0) ws[t >> 5] = s;
    __syncthreads();
    if (t == 0) {
        float tot = 0.f;
#pragma unroll
        for (int w = 0; w < 16; ++w) tot += ws[w];
        out[0] = tot / (float)NROW;
    }
}

extern "C" void kernel_launch(void* const* d_in, const int* in_sizes, int n_in,
                              void* d_out, int out_size) {
    const float* X = (const float*)d_in[0];   // inputs  [16384, 512] f32
    const float* P = (const float*)d_in[1];   // positive[16384, 512] f32
    float* out = (float*)d_out;

    cudaFuncSetAttribute(mma_topk_kernel,
                         cudaFuncAttributeMaxDynamicSharedMemorySize, SMEM_TOTAL);

    cvtsq_kernel<<<NROW, 128>>>(X);
    mma_topk_kernel<<<128, THREADS, SMEM_TOTAL>>>();
    rowloss_kernel<<<NROW / 8, 256>>>(X, P);
    reduce_kernel<<<1, 512>>>(out);
}

// round 15
// speedup vs baseline: 1.5367x; 1.0125x over previous
#include <cuda_runtime.h>
#include <cuda_bf16.h>
#include <math.h>
#include <float.h>
#include <stdint.h>

#define NROW 16384
#define DIM  512
#define MARGIN 2.0f
#define EPSV 1e-6f

#if defined(__CUDA_ARCH_FEAT_SM103_ALL) || (defined(__CUDA_ARCH_SPECIFIC__) && (__CUDA_ARCH_SPECIFIC__ == 1030))
#define HAS_TCGEN05 1
#else
#define HAS_TCGEN05 0
#endif

// ---- device scratch ----
__device__ __align__(16) float g_sq[NROW];
__device__ int   g_neg[NROW];
__device__ float g_rowloss[NROW];
__device__ int   g_blkdone;               // rowloss completion counter (self-resetting)
// bf16 PRE-SWIZZLED as 512 tiles of 32 rows x 512 K = 32KB each (SW128 image):
// tile t: 8 slabs of 4KB (64 K-elems each); bo = r*128 + (k&63)*2,
// stored at bo^((bo>>3)&0x70). 16B granules stay contiguous under SW128.
__device__ __align__(256) uint32_t g_xb[NROW * DIM / 2];

// SMEM layout (A in TMEM; whole sq resident; 4-deep B ring)
#define SMEM_TPTR   0
#define SMEM_FULL0  8            // 4 mbarriers (own B ring complete_tx)
#define SMEM_DONE0  40           // 4 mbarriers (MMA commit, multicast to both)
#define SMEM_DFREE0 72           // 4 mbarriers (own epilogue done with D slot)
#define SMEM_READY0 104          // 4 mbarriers (leader: follower tile-ready)
#define SMEM_SQFULL 136          // 1 mbarrier  (whole-sq load complete)
#define SMEM_SQ     1024         // 16384 floats = 65536 B -> ends 66560
#define SMEM_B      66560        // 4 x 32768 -> ends 197632
#define SMEM_TOTAL  197632

#define TMEM_A 0                 // 256 cols: own 128 rows x 512 bf16
#define TMEM_D 256               // 4 x 64 cols f32

#define NTILE 256
#define THREADS 160              // w0 = producer(+MMA on leader), w1-4 = epilogue

#if HAS_TCGEN05
__device__ __forceinline__ uint32_t elect_one() {
    uint32_t p;
    asm volatile("{\n\t.reg .pred p;\n\telect.sync _|p, 0xFFFFFFFF;\n\tselp.b32 %0, 1, 0, p;\n\t}" : "=r"(p));
    return p;
}
#define TCGEN05_ALLOC_CG2(dst, n) \
    asm volatile("tcgen05.alloc.cta_group::2.sync.aligned.shared::cta.b32 [%0], %1;" :: "r"(dst), "r"(n) : "memory")
#define TCGEN05_DEALLOC_CG2(t, n) \
    asm volatile("tcgen05.dealloc.cta_group::2.sync.aligned.b32 %0, %1;" :: "r"(t), "r"(n))
#define TCGEN05_RELINQ_CG2() \
    asm volatile("tcgen05.relinquish_alloc_permit.cta_group::2.sync.aligned;")
#define TCGEN05_WAIT_ST() asm volatile("tcgen05.wait::st.sync.aligned;" ::: "memory")
#define TCGEN05_WAIT_LD() asm volatile("tcgen05.wait::ld.sync.aligned;" ::: "memory")
#define TCGEN05_FENCE_BEFORE() asm volatile("tcgen05.fence::before_thread_sync;" ::: "memory")
#define TCGEN05_FENCE_AFTER()  asm volatile("tcgen05.fence::after_thread_sync;" ::: "memory")
#define FENCE_PROXY_ASYNC() asm volatile("fence.proxy.async;" ::: "memory")
#define MBARRIER_INIT(m, c) \
    asm volatile("mbarrier.init.shared.b64 [%0], %1;" :: "r"(m), "r"(c) : "memory")
#define MBARRIER_ARRIVE(m) \
    asm volatile("mbarrier.arrive.release.cta.shared.b64 _, [%0];" :: "r"(m) : "memory")
#define MBARRIER_EXPECT_TX(m, b) \
    asm volatile("mbarrier.arrive.expect_tx.shared.b64 _, [%0], %1;" :: "r"(m), "r"(b) : "memory")
#define MBARRIER_ARRIVE_LEADER(local_addr) \
    asm volatile("{\n\t.reg .b32 rA;\n\t.reg .b32 z;\n\tmov.b32 z, 0;\n\t" \
        "mapa.shared::cluster.u32 rA, %0, z;\n\t" \
        "mbarrier.arrive.release.cluster.shared::cluster.b64 _, [rA];\n\t}" \
        :: "r"((uint32_t)(local_addr)) : "memory")
#define TCGEN05_COMMIT_MC_CG2(m) \
    asm volatile("tcgen05.commit.cta_group::2.mbarrier::arrive::one.shared::cluster.multicast::cluster.b64 [%0], %1;" \
        :: "r"(m), "h"((uint16_t)3) : "memory")
#define CLUSTER_SYNC() do { \
    asm volatile("barrier.cluster.arrive.aligned;" ::: "memory"); \
    asm volatile("barrier.cluster.wait.aligned;" ::: "memory"); \
} while (0)

#define MBARRIER_WAIT_PARITY(mbar_smem_addr, phase_parity) do { \
    uint32_t _mbar = (uint32_t)(mbar_smem_addr); \
    uint32_t _parity = (uint32_t)(phase_parity); \
    uint32_t _done; \
    asm volatile("{\n\t.reg .pred p;\n\t" \
        "mbarrier.try_wait.parity.acquire.cta.shared::cta.b64 p, [%1], %2;\n\t" \
        "selp.b32 %0, 1, 0, p;\n\t}" : "=r"(_done) : "r"(_mbar), "r"(_parity) : "memory"); \
    if (!_done) { \
        asm volatile("{\n\t.reg .pred P1;\n\t" \
            "WAIT_LOOP_%=:\n\t" \
            "mbarrier.try_wait.parity.acquire.cta.shared::cta.b64 P1, [%0], %1, 0x989680;\n\t" \
            "@P1 bra.uni WAIT_DONE_%=;\n\t" \
            "bra.uni WAIT_LOOP_%=;\n\t" \
            "WAIT_DONE_%=:\n\t}" :: "r"(_mbar), "r"(_parity) : "memory"); \
    } \
} while (0)

#define MBARRIER_WAIT_PARITY_CL(mbar_smem_addr, phase_parity) do { \
    uint32_t _mbar = (uint32_t)(mbar_smem_addr); \
    uint32_t _parity = (uint32_t)(phase_parity); \
    uint32_t _done; \
    asm volatile("{\n\t.reg .pred p;\n\t" \
        "mbarrier.try_wait.parity.acquire.cluster.shared::cta.b64 p, [%1], %2;\n\t" \
        "selp.b32 %0, 1, 0, p;\n\t}" : "=r"(_done) : "r"(_mbar), "r"(_parity) : "memory"); \
    if (!_done) { \
        asm volatile("{\n\t.reg .pred P1;\n\t" \
            "WAIT_LOOP_%=:\n\t" \
            "mbarrier.try_wait.parity.acquire.cluster.shared::cta.b64 P1, [%0], %1, 0x989680;\n\t" \
            "@P1 bra.uni WAIT_DONE_%=;\n\t" \
            "bra.uni WAIT_LOOP_%=;\n\t" \
            "WAIT_DONE_%=:\n\t}" :: "r"(_mbar), "r"(_parity) : "memory"); \
    } \
} while (0)

#define TCGEN05_ST_X32(tmem_addr, r) \
    asm volatile("tcgen05.st.sync.aligned.32x32b.x32.b32 [%0], " \
        "{%1, %2, %3, %4, %5, %6, %7, %8, %9, %10, %11, %12, %13, %14, %15, %16, " \
        "%17, %18, %19, %20, %21, %22, %23, %24, %25, %26, %27, %28, %29, %30, %31, %32};" \
        :: "r"(tmem_addr), \
           "r"((r)[0]),"r"((r)[1]),"r"((r)[2]),"r"((r)[3]),"r"((r)[4]),"r"((r)[5]),"r"((r)[6]),"r"((r)[7]), \
           "r"((r)[8]),"r"((r)[9]),"r"((r)[10]),"r"((r)[11]),"r"((r)[12]),"r"((r)[13]),"r"((r)[14]),"r"((r)[15]), \
           "r"((r)[16]),"r"((r)[17]),"r"((r)[18]),"r"((r)[19]),"r"((r)[20]),"r"((r)[21]),"r"((r)[22]),"r"((r)[23]), \
           "r"((r)[24]),"r"((r)[25]),"r"((r)[26]),"r"((r)[27]),"r"((r)[28]),"r"((r)[29]),"r"((r)[30]),"r"((r)[31]) \
        : "memory")

#define TCGEN05_LD_X32(r, tmem_addr) \
    asm volatile("tcgen05.ld.sync.aligned.32x32b.x32.b32 " \
        "{%0, %1, %2, %3, %4, %5, %6, %7, %8, %9, %10, %11, %12, %13, %14, %15, " \
        "%16, %17, %18, %19, %20, %21, %22, %23, %24, %25, %26, %27, %28, %29, %30, %31}, [%32];" \
        : "=r"((r)[0]),"=r"((r)[1]),"=r"((r)[2]),"=r"((r)[3]),"=r"((r)[4]),"=r"((r)[5]),"=r"((r)[6]),"=r"((r)[7]), \
          "=r"((r)[8]),"=r"((r)[9]),"=r"((r)[10]),"=r"((r)[11]),"=r"((r)[12]),"=r"((r)[13]),"=r"((r)[14]),"=r"((r)[15]), \
          "=r"((r)[16]),"=r"((r)[17]),"=r"((r)[18]),"=r"((r)[19]),"=r"((r)[20]),"=r"((r)[21]),"=r"((r)[22]),"=r"((r)[23]), \
          "=r"((r)[24]),"=r"((r)[25]),"=r"((r)[26]),"=r"((r)[27]),"=r"((r)[28]),"=r"((r)[29]),"=r"((r)[30]),"=r"((r)[31]) \
        : "r"(tmem_addr))

__device__ __forceinline__ void bulk_g2s(uint32_t dst, const void* src, uint32_t bytes, uint32_t mbar) {
    asm volatile("cp.async.bulk.shared::cta.global.mbarrier::complete_tx::bytes [%0], [%1], %2, [%3];"
                 :: "r"(dst), "l"(src), "r"(bytes), "r"(mbar) : "memory");
}

// cg2 TS-mode bf16 MMA: A in (each CTA's own) TMEM, B via SMEM descriptor
__device__ __forceinline__ void mma_f16_ts_cg2(uint32_t d_tmem, uint32_t a_tmem,
                                               uint64_t b_desc, uint32_t idesc, bool acc) {
    uint32_t en = acc ? 1u : 0u;
    asm volatile("{\n\t.reg .pred p;\n\tsetp.ne.u32 p, %5, 0;\n\t"
        "tcgen05.mma.cta_group::2.kind::f16 [%0], [%1], %2, %3, "
        "{%4, %4, %4, %4, %4, %4, %4, %4}, p;\n\t}"
        :: "r"(d_tmem), "r"(a_tmem), "l"(b_desc), "r"(idesc), "r"(0u), "r"(en)
        : "memory");
}

__device__ __forceinline__ uint64_t make_desc(uint32_t addr) {
    return (uint64_t(2) << 61) | (uint64_t(1) << 46) | (uint64_t(64) << 32)
         | (uint64_t(1) << 16) | ((addr >> 4) & 0x3FFF);
}

// idesc: F32 accum, bf16 A/B, M=256 (16<<24), N=64 (8<<17)
#define MMA_IDESC ((16u << 24) | (8u << 17) | (1u << 10) | (1u << 7) | (1u << 4))
#endif  // HAS_TCGEN05

__device__ __forceinline__ uint32_t smem_u32(const void* p) {
    uint32_t a;
    asm("{ .reg .u64 t; cvta.to.shared.u64 t, %1; cvt.u32.u64 %0, t; }" : "=r"(a) : "l"(p));
    return a;
}

// ============================================================
// Kernel 0: fp32 -> pre-swizzled 32-row bf16 tiles + exact row norms
// ============================================================
__global__ __launch_bounds__(128) void cvtsq_kernel(const float* __restrict__ X) {
    int row = blockIdx.x;
    int t = threadIdx.x;
    float4 v = *(const float4*)(X + (size_t)row * DIM + t * 4);
    uint32_t lo, hi;
    asm("cvt.rn.bf16x2.f32 %0, %1, %2;" : "=r"(lo) : "f"(v.y), "f"(v.x));
    asm("cvt.rn.bf16x2.f32 %0, %1, %2;" : "=r"(hi) : "f"(v.w), "f"(v.z));
    int tile = row >> 5, r = row & 31;
    int k = t * 4;
    uint32_t bo = (uint32_t)(r * 128 + (k & 63) * 2);
    uint32_t sw = bo ^ ((bo >> 3) & 0x70);
    *(uint2*)((char*)g_xb + (size_t)tile * 32768 + (size_t)(k >> 6) * 4096 + sw)
        = make_uint2(lo, hi);
    float s = v.x * v.x + v.y * v.y + v.z * v.z + v.w * v.w;
#pragma unroll
    for (int o = 16; o > 0; o >>= 1) s += __shfl_down_sync(0xffffffffu, s, o);
    __shared__ float ws[4];
    if ((t & 31) == 0) ws[t >> 5] = s;
    __syncthreads();
    if (t == 0) g_sq[row] = ws[0] + ws[1] + ws[2] + ws[3];
}

// ============================================================
// Kernel 1: cg2 TS-mode bf16 GEMM, 4-deep TMEM D ring, 4-deep B ring,
// whole sq resident in SMEM. 64 clusters x 2 CTAs x 160 threads.
// Each CTA: 128 A rows in OWN TMEM; per 64-col tile u, rank r bulk-
// loads B rows [u*64 + r*32, +32) into slot u&3 (prefetch depth 3).
// Leader issues 32 cg2 TS MMAs -> D slot u&3; commit multicast.
// Epilogue: wait done -> LDTM -> EARLY dfree release -> min-screen top-3.
// ============================================================
__global__ __launch_bounds__(THREADS, 1) __cluster_dims__(2, 1, 1)
void mma_topk_kernel() {
    extern __shared__ char smem[];
    const uint32_t smem_base = smem_u32(smem);
    const int tid = threadIdx.x;
    const int rowBase = blockIdx.x * 128;
    const char* xb = (const char*)g_xb;

#if HAS_TCGEN05
    const int wid = tid >> 5;
    const int lane = tid & 31;
    const bool is_prod = (wid == 0);
    const int rank = blockIdx.x & 1;
    const int smsp = wid & 3;
    const int row = smsp * 32 + lane;

    if (is_prod) {
        TCGEN05_ALLOC_CG2(smem_base + SMEM_TPTR, 512);
        TCGEN05_RELINQ_CG2();
    }
    if (tid == 0) {
#pragma unroll
        for (int s = 0; s < 4; ++s) {
            MBARRIER_INIT(smem_base + SMEM_FULL0 + s * 8, 1);
            MBARRIER_INIT(smem_base + SMEM_DONE0 + s * 8, 1);
            MBARRIER_INIT(smem_base + SMEM_DFREE0 + s * 8, 4);
            MBARRIER_INIT(smem_base + SMEM_READY0 + s * 8, 1);
        }
        MBARRIER_INIT(smem_base + SMEM_SQFULL, 1);
    }
    __syncthreads();
    uint32_t tmem_base;
    asm volatile("ld.shared.b32 %0, [%1];" : "=r"(tmem_base) : "r"(smem_base + SMEM_TPTR));

    // ---- A fill: epilogue warps store own 128 rows x 512 bf16 to own TMEM,
    //      de-swizzling 16B granules from the pre-swizzled g_xb image ----
    if (!is_prod) {
        const int R = rowBase + row;
        const int tt = R >> 5, r = R & 31;
        const char* tbase = xb + (size_t)tt * 32768;
        uint32_t wo = (uint32_t)smsp << 21;
#pragma unroll
        for (int c8 = 0; c8 < 8; ++c8) {
            uint32_t rg[32];
#pragma unroll
            for (int u = 0; u < 8; ++u) {
                int g = c8 * 8 + u;                 // 16B granule index (k = g*8)
                uint32_t bo = (uint32_t)(r * 128 + (g & 7) * 16);
                uint32_t sw = bo ^ ((bo >> 3) & 0x70);
                uint4 v = *(const uint4*)(tbase + (size_t)(g >> 3) * 4096 + sw);
                rg[u * 4 + 0] = v.x; rg[u * 4 + 1] = v.y;
                rg[u * 4 + 2] = v.z; rg[u * 4 + 3] = v.w;
            }
            TCGEN05_ST_X32(tmem_base + TMEM_A + c8 * 32 + wo, rg);
        }
        TCGEN05_WAIT_ST();
        TCGEN05_FENCE_BEFORE();
    } else {
        // prologue: whole sq (64KB) + B tiles 0,1,2 (own 32-row halves)
        if (elect_one()) {
            MBARRIER_EXPECT_TX(smem_base + SMEM_SQFULL, 65536);
            bulk_g2s(smem_base + SMEM_SQ, (const char*)g_sq, 65536,
                     smem_base + SMEM_SQFULL);
#pragma unroll
            for (int pt = 0; pt < 3; ++pt) {
                uint32_t fb = smem_base + SMEM_FULL0 + pt * 8;
                MBARRIER_EXPECT_TX(fb, 32768);
                bulk_g2s(smem_base + SMEM_B + pt * 32768,
                         xb + (size_t)(2 * pt + rank) * 32768, 32768, fb);
            }
        }
    }
    __syncthreads();
    CLUSTER_SYNC();   // both CTAs' A in TMEM + mbarriers visible before any cg2 MMA

    if (is_prod) {
        for (int u = 0; u < NTILE; ++u) {
            const int ds = u & 3;
            MBARRIER_WAIT_PARITY(smem_base + SMEM_FULL0 + ds * 8, (u >> 2) & 1);
            if (u >= 4)
                MBARRIER_WAIT_PARITY(smem_base + SMEM_DFREE0 + ds * 8, ((u - 4) >> 2) & 1);

            if (rank == 1) {
                TCGEN05_FENCE_AFTER();
                if (elect_one())
                    MBARRIER_ARRIVE_LEADER(smem_base + SMEM_READY0 + ds * 8);
            } else {
                MBARRIER_WAIT_PARITY_CL(smem_base + SMEM_READY0 + ds * 8, (u >> 2) & 1);
                TCGEN05_FENCE_AFTER();
                if (elect_one()) {
                    uint64_t bdesc = make_desc(smem_base + SMEM_B + ds * 32768);
                    uint32_t dtm = tmem_base + TMEM_D + ds * 64;
#pragma unroll
                    for (int c = 0; c < 32; ++c) {
                        uint64_t boff = (uint64_t)((c >> 2) * 256 + (c & 3) * 2);
                        mma_f16_ts_cg2(dtm, tmem_base + TMEM_A + c * 8,
                                       bdesc + boff, MMA_IDESC, c > 0);
                    }
                    TCGEN05_COMMIT_MC_CG2(smem_base + SMEM_DONE0 + ds * 8);
                }
            }

            // recycle: B(u+3) -> slot (u+3)&3 == (u-1)&3, last read by MMA(u-1)
            if (u + 3 < NTILE) {
                if (u >= 1)
                    MBARRIER_WAIT_PARITY(smem_base + SMEM_DONE0 + ((u - 1) & 3) * 8,
                                         ((u - 1) >> 2) & 1);
                if (elect_one()) {
                    int s2 = (u + 3) & 3;
                    uint32_t fb = smem_base + SMEM_FULL0 + s2 * 8;
                    MBARRIER_EXPECT_TX(fb, 32768);
                    bulk_g2s(smem_base + SMEM_B + s2 * 32768,
                             xb + (size_t)(2 * (u + 3) + rank) * 32768, 32768, fb);
                }
            }
        }
    } else {
        // ---- epilogue warps: per-thread (one row) top-3 over all tiles ----
        MBARRIER_WAIT_PARITY(smem_base + SMEM_SQFULL, 0);
        const float* sqall = (const float*)(smem + SMEM_SQ);
        float v0 = FLT_MAX, v1 = FLT_MAX, v2 = FLT_MAX;
        int   i0 = 0, i1 = 0, i2 = 0;
        for (int u = 0; u < NTILE; ++u) {
            const int ds = u & 3;
            MBARRIER_WAIT_PARITY(smem_base + SMEM_DONE0 + ds * 8, (u >> 2) & 1);
            TCGEN05_FENCE_AFTER();
            const float* sqt = sqall + u * 64;
            const int colBase = u * 64;
            const uint32_t dtm = tmem_base + TMEM_D + ds * 64;
            uint32_t dr[64];
            TCGEN05_LD_X32(dr, dtm);
            TCGEN05_LD_X32(dr + 32, dtm + 32);
            TCGEN05_WAIT_LD();
            // EARLY release: D data fully in registers, sq is resident
            TCGEN05_FENCE_BEFORE();
            if (lane == 0) MBARRIER_ARRIVE(smem_base + SMEM_DFREE0 + ds * 8);
#pragma unroll
            for (int g = 0; g < 4; ++g) {
                float key[16];
#pragma unroll
                for (int c = 0; c < 16; ++c)
                    key[c] = fmaf(-2.f, __uint_as_float(dr[g * 16 + c]), sqt[g * 16 + c]);
                float t8[8];
#pragma unroll
                for (int c = 0; c < 8; ++c) t8[c] = fminf(key[c], key[c + 8]);
                float t4a = fminf(t8[0], t8[4]), t4b = fminf(t8[1], t8[5]);
                float t4c = fminf(t8[2], t8[6]), t4d = fminf(t8[3], t8[7]);
                float mn = fminf(fminf(t4a, t4b), fminf(t4c, t4d));
                if (mn < v2) {   // rare: exact ordered insert, ascending cols
#pragma unroll
                    for (int c = 0; c < 16; ++c) {
                        float k = key[c];
                        int col = colBase + g * 16 + c;
                        if (k < v2) {
                            if (k < v1) {
                                v2 = v1; i2 = i1;
                                if (k < v0) { v1 = v0; i1 = i0; v0 = k; i0 = col; }
                                else        { v1 = k; i1 = col; }
                            } else { v2 = k; i2 = col; }
                        }
                    }
                }
            }
        }
        g_neg[rowBase + row] = i2;
    }

    __syncthreads();
    CLUSTER_SYNC();   // peer MMA done reading my SMEM/TMEM before teardown
    if (is_prod) TCGEN05_DEALLOC_CG2(tmem_base, 512);
    CLUSTER_SYNC();

#else  // ---------------- SIMT fallback (non-'a' pass) ----------------
    // Reads the pre-swizzled 32-row-tile g_xb layout (per-4B de-swizzle).
    float* As = (float*)(smem);
    float* Bs = (float*)(smem + 4096);
    float* mv = (float*)(smem + 12288);
    int*   mi = (int*)(smem + 36864);
    const int tx = tid & 15, ty = tid >> 4;
    const bool act = (tid < 128);

    for (int half = 0; half < 2; ++half) {
        const int rh = rowBase + half * 64;
        float tv[8][3]; int tii[8][3];
#pragma unroll
        for (int i = 0; i < 8; ++i)
#pragma unroll
            for (int q = 0; q < 3; ++q) { tv[i][q] = FLT_MAX; tii[i][q] = 0x7fffffff; }

        for (int jt = 0; jt < NROW / 128; ++jt) {
            const int colBase = jt * 128;
            float c[8][8];
#pragma unroll
            for (int i = 0; i < 8; ++i)
#pragma unroll
                for (int j = 0; j < 8; ++j) c[i][j] = 0.f;

            for (int kt = 0; kt < DIM; kt += 16) {
                __syncthreads();
                if (act) {
#pragma unroll
                    for (int l = 0; l < 4; ++l) {
                        int f = tid + l * 128;
                        int r = f >> 3, uu = f & 7;
                        int R = rh + r, kk = kt + 2 * uu;
                        uint32_t bo = (uint32_t)((R & 31) * 128 + (kk & 63) * 2);
                        uint32_t sw = bo ^ ((bo >> 3) & 0x70);
                        uint32_t w = *(const uint32_t*)(xb + (size_t)(R >> 5) * 32768
                                                        + (size_t)(kk >> 6) * 4096 + sw);
                        __nv_bfloat162 b2 = *(__nv_bfloat162*)&w;
                        float2 f2 = __bfloat1622float2(b2);
                        As[(2 * uu + 0) * 64 + r] = f2.x;
                        As[(2 * uu + 1) * 64 + r] = f2.y;
                    }
#pragma unroll
                    for (int l = 0; l < 8; ++l) {
                        int f = tid + l * 128;
                        int r = f >> 3, uu = f & 7;
                        int R = colBase + r, kk = kt + 2 * uu;
                        uint32_t bo = (uint32_t)((R & 31) * 128 + (kk & 63) * 2);
                        uint32_t sw = bo ^ ((bo >> 3) & 0x70);
                        uint32_t w = *(const uint32_t*)(xb + (size_t)(R >> 5) * 32768
                                                        + (size_t)(kk >> 6) * 4096 + sw);
                        __nv_bfloat162 b2 = *(__nv_bfloat162*)&w;
                        float2 f2 = __bfloat1622float2(b2);
                        Bs[(2 * uu + 0) * 128 + r] = f2.x;
                        Bs[(2 * uu + 1) * 128 + r] = f2.y;
                    }
                }
                __syncthreads();
                if (act) {
#pragma unroll
                    for (int kk = 0; kk < 16; ++kk) {
                        float a[8], b[8];
#pragma unroll
                        for (int i = 0; i < 8; ++i) a[i] = As[kk * 64 + ty * 8 + i];
#pragma unroll
                        for (int j = 0; j < 8; ++j) b[j] = Bs[kk * 128 + tx * 8 + j];
#pragma unroll
                        for (int i = 0; i < 8; ++i)
#pragma unroll
                            for (int j = 0; j < 8; ++j) c[i][j] += a[i] * b[j];
                    }
                }
            }
            if (act) {
#pragma unroll
                for (int j = 0; j < 8; ++j) {
                    int col = colBase + tx * 8 + j;
                    float sqc = g_sq[col];
#pragma unroll
                    for (int i = 0; i < 8; ++i) {
                        float d2 = fmaf(-2.f, c[i][j], sqc);
                        bool b2c = (d2 < tv[i][2]) || (d2 == tv[i][2] && col < tii[i][2]);
                        if (b2c) {
                            bool b1c = (d2 < tv[i][1]) || (d2 == tv[i][1] && col < tii[i][1]);
                            bool b0c = (d2 < tv[i][0]) || (d2 == tv[i][0] && col < tii[i][0]);
                            if (b0c) {
                                tv[i][2] = tv[i][1]; tii[i][2] = tii[i][1];
                                tv[i][1] = tv[i][0]; tii[i][1] = tii[i][0];
                                tv[i][0] = d2;       tii[i][0] = col;
                            } else if (b1c) {
                                tv[i][2] = tv[i][1]; tii[i][2] = tii[i][1];
                                tv[i][1] = d2;       tii[i][1] = col;
                            } else { tv[i][2] = d2; tii[i][2] = col; }
                        }
                    }
                }
            }
        }

        __syncthreads();
        if (act) {
#pragma unroll
            for (int i = 0; i < 8; ++i)
#pragma unroll
                for (int q = 0; q < 3; ++q) {
                    mv[(ty * 8 + i) * 48 + tx * 3 + q] = tv[i][q];
                    mi[(ty * 8 + i) * 48 + tx * 3 + q] = tii[i][q];
                }
        }
        __syncthreads();
        if (tid < 64) {
            float w0 = FLT_MAX, w1 = FLT_MAX, w2 = FLT_MAX;
            int   j0 = 0x7fffffff, j1 = 0x7fffffff, j2 = 0x7fffffff;
            for (int cnd = 0; cnd < 48; ++cnd) {
                float d = mv[tid * 48 + cnd];
                int   ix = mi[tid * 48 + cnd];
                bool b2c = (d < w2) || (d == w2 && ix < j2);
                if (b2c) {
                    bool b1c = (d < w1) || (d == w1 && ix < j1);
                    bool b0c = (d < w0) || (d == w0 && ix < j0);
                    if (b0c)      { w2 = w1; j2 = j1; w1 = w0; j1 = j0; w0 = d; j0 = ix; }
                    else if (b1c) { w2 = w1; j2 = j1; w1 = d; j1 = ix; }
                    else          { w2 = d;  j2 = ix; }
                }
            }
            g_neg[rh + tid] = j2;
        }
        __syncthreads();
    }
#endif
}

// ============================================================
// Kernel 2: per-row triplet loss (one warp per row) + fused
// deterministic mean reduction in the last-arriving block.
// ============================================================
__global__ __launch_bounds__(256) void rowloss_kernel(const float* __restrict__ X,
                                                      const float* __restrict__ P,
                                                      float* __restrict__ out) {
    int warp = threadIdx.x >> 5;
    int lane = threadIdx.x & 31;
    int row = blockIdx.x * 8 + warp;
    const float4* xr = (const float4*)(X + (size_t)row * DIM);
    const float4* pr = (const float4*)(P + (size_t)row * DIM);
    const float4* nr = (const float4*)(X + (size_t)g_neg[row] * DIM);
    float sap = 0.f, san = 0.f;
#pragma unroll
    for (int i = 0; i < 4; ++i) {
        float4 x = xr[lane + 32 * i];
        float4 p = pr[lane + 32 * i];
        float4 v = nr[lane + 32 * i];
        float d;
        d = x.x - p.x + EPSV; sap += d * d;
        d = x.y - p.y + EPSV; sap += d * d;
        d = x.z - p.z + EPSV; sap += d * d;
        d = x.w - p.w + EPSV; sap += d * d;
        d = x.x - v.x + EPSV; san += d * d;
        d = x.y - v.y + EPSV; san += d * d;
        d = x.z - v.z + EPSV; san += d * d;
        d = x.w - v.w + EPSV; san += d * d;
    }
#pragma unroll
    for (int o = 16; o > 0; o >>= 1) {
        sap += __shfl_down_sync(0xffffffffu, sap, o);
        san += __shfl_down_sync(0xffffffffu, san, o);
    }
    if (lane == 0)
        g_rowloss[row] = fmaxf(sqrtf(sap) - sqrtf(san) + MARGIN, 0.f);

    // ---- fused mean reduction: last block does a fixed-order tree sum ----
    __shared__ bool s_last;
    __threadfence();
    __syncthreads();
    if (threadIdx.x == 0) {
        int done = atomicAdd(&g_blkdone, 1);
        s_last = (done == gridDim.x - 1);
    }
    __syncthreads();
    if (s_last) {
        int t = threadIdx.x;
        float s = 0.f;
        for (int i = t; i < NROW; i += 256) s += g_rowloss[i];
#pragma unroll
        for (int o = 16; o > 0; o >>= 1) s += __shfl_down_sync(0xffffffffu, s, o);
        __shared__ float ws[8];
        if ((t & 31) == 0) ws[t >> 5] = s;
        __syncthreads();
        if (t == 0) {
            float tot = 0.f;
#pragma unroll
            for (int w = 0; w < 8; ++w) tot += ws[w];
            out[0] = tot / (float)NROW;
            g_blkdone = 0;      // reset for next graph replay
        }
    }
}

extern "C" void kernel_launch(void* const* d_in, const int* in_sizes, int n_in,
                              void* d_out, int out_size) {
    const float* X = (const float*)d_in[0];   // inputs  [16384, 512] f32
    const float* P = (const float*)d_in[1];   // positive[16384, 512] f32
    float* out = (float*)d_out;

    cudaFuncSetAttribute(mma_topk_kernel,
                         cudaFuncAttributeMaxDynamicSharedMemorySize, SMEM_TOTAL);

    cvtsq_kernel<<<NROW, 128>>>(X);
    mma_topk_kernel<<<128, THREADS, SMEM_TOTAL>>>();
    rowloss_kernel<<<NROW / 8, 256>>>(X, P, out);
}